// round 4
// baseline (speedup 1.0000x reference)
#include <cuda_runtime.h>
#include <cuda_bf16.h>
#include <math.h>
#include <stdint.h>

#define BB 16
#define EE 2048
#define FF 8192
#define QQ 20
#define DD 256
#define WDD 300
#define NRELROWS 601
#define L4D 1024
#define NWORD 50000

#define VERY_NEG -1e11f
#define VERY_SMALL 1e-10f

// ---------------- scratch (device globals; no runtime alloc) ----------------
__device__ float g_lr[NRELROWS * DD];
__device__ float g_fs[3 * NRELROWS * DD];
__device__ float g_lstmb[L4D];
__device__ float g_whhT[DD * L4D];
__device__ float g_gx[BB * QQ * L4D];
__device__ float g_qh[BB * QQ * DD];
__device__ float g_qnode[BB * DD];
__device__ float g_s0[BB * QQ * NRELROWS];
__device__ float g_Wr[BB * NRELROWS];
__device__ float g_maxb[BB];
__device__ float g_Wt[BB * FF];
__device__ float g_e2fs[BB * EE];
__device__ float g_leA[BB * EE * DD];
__device__ float g_leB[BB * EE * DD];
__device__ float g_head[BB * EE * DD];
__device__ float g_eself[BB * EE * DD];   // becomes f2e_emb in-place
__device__ float g_Asc[BB * EE * DD];
__device__ float g_pr[BB * EE];
__device__ float g_prnew[BB * EE];
__device__ float g_cnt[BB * EE];
__device__ float g_q2ev[BB * DD];
__device__ float g_biasBE[BB * DD];
__device__ float g_sred[2 * BB * DD];
__device__ float g_prsum[BB];

// ------------- tensor-core GEMM: bf16x3 split, m16n8k16, fp32 acc -----------
// C[M,N] = act( [C +] alpha * A@W^T + bias )
// A: M x K (row stride lda), optionally row-gathered via gidx. W: N x K (row ldw).
// BIASMODE: 0 none, 1 bias[n], 2 bias[(m>>11)*N + n]
#define TBM 128
#define TBN 128
#define TBK 32
#define LDSK 36   // bf16 units per smem row (72B: 8B-aligned, conflict-free)

#define MMA_BF16(c, a, b)                                                  \
  asm volatile(                                                            \
      "mma.sync.aligned.m16n8k16.row.col.f32.bf16.bf16.f32 "               \
      "{%0,%1,%2,%3},{%4,%5,%6,%7},{%8,%9},{%0,%1,%2,%3};"                 \
      : "+f"((c)[0]), "+f"((c)[1]), "+f"((c)[2]), "+f"((c)[3])             \
      : "r"((a)[0]), "r"((a)[1]), "r"((a)[2]), "r"((a)[3]),                \
        "r"((b)[0]), "r"((b)[1]));

__device__ __forceinline__ void bf16split(float v, __nv_bfloat16& h,
                                          __nv_bfloat16& l) {
  h = __float2bfloat16(v);
  l = __float2bfloat16(v - __bfloat162float(h));
}

template <bool GATHER, bool ACCUM, bool RELU, int BIASMODE>
__global__ void __launch_bounds__(256) gemm_k(
    float* __restrict__ C, const float* __restrict__ A, int lda,
    const int* __restrict__ gidx, const float* __restrict__ W, int ldw,
    const float* __restrict__ bias, int M, int N, int K, float alpha) {
  __shared__ __nv_bfloat16 Ah[TBM][LDSK], Al[TBM][LDSK];
  __shared__ __nv_bfloat16 Bh[TBN][LDSK], Bl[TBN][LDSK];
  const int bm = blockIdx.y * TBM, bn = blockIdx.x * TBN;
  const int tid = threadIdx.x;
  const int warp = tid >> 5, lane = tid & 31;
  const int g = lane >> 2, tig = lane & 3;
  const int wm = (warp >> 2) * 64, wn = (warp & 3) * 32;

  float acc[4][4][4];
#pragma unroll
  for (int i = 0; i < 4; i++)
#pragma unroll
    for (int j = 0; j < 4; j++)
#pragma unroll
      for (int c = 0; c < 4; c++) acc[i][j][c] = 0.f;

  for (int kk0 = 0; kk0 < K; kk0 += TBK) {
    // load + split: 4096 floats each for A and B, 256 threads -> float4 x4
#pragma unroll
    for (int i = 0; i < 4; i++) {
      int idx = tid + i * 256;
      int row = idx >> 3, kq = idx & 7;
      int k = kk0 + kq * 4;
      float4 va = make_float4(0.f, 0.f, 0.f, 0.f);
      int m = bm + row;
      if (m < M) {
        long r = GATHER ? (long)gidx[m] : (long)m;
        const float* p = A + r * (long)lda + k;
        if (k + 3 < K) va = *(const float4*)p;
        else {
          if (k < K) va.x = p[0];
          if (k + 1 < K) va.y = p[1];
          if (k + 2 < K) va.z = p[2];
        }
      }
      bf16split(va.x, Ah[row][kq * 4 + 0], Al[row][kq * 4 + 0]);
      bf16split(va.y, Ah[row][kq * 4 + 1], Al[row][kq * 4 + 1]);
      bf16split(va.z, Ah[row][kq * 4 + 2], Al[row][kq * 4 + 2]);
      bf16split(va.w, Ah[row][kq * 4 + 3], Al[row][kq * 4 + 3]);
      float4 vb = make_float4(0.f, 0.f, 0.f, 0.f);
      int n = bn + row;
      if (n < N) {
        const float* p = W + (long)n * ldw + k;
        if (k + 3 < K) vb = *(const float4*)p;
        else {
          if (k < K) vb.x = p[0];
          if (k + 1 < K) vb.y = p[1];
          if (k + 2 < K) vb.z = p[2];
        }
      }
      bf16split(vb.x, Bh[row][kq * 4 + 0], Bl[row][kq * 4 + 0]);
      bf16split(vb.y, Bh[row][kq * 4 + 1], Bl[row][kq * 4 + 1]);
      bf16split(vb.z, Bh[row][kq * 4 + 2], Bl[row][kq * 4 + 2]);
      bf16split(vb.w, Bh[row][kq * 4 + 3], Bl[row][kq * 4 + 3]);
    }
    __syncthreads();
#pragma unroll
    for (int ks = 0; ks < TBK; ks += 16) {
      uint32_t bh[4][2], bl[4][2];
#pragma unroll
      for (int nt = 0; nt < 4; nt++) {
        int n0 = wn + nt * 8 + g;
        bh[nt][0] = *(const uint32_t*)&Bh[n0][ks + tig * 2];
        bh[nt][1] = *(const uint32_t*)&Bh[n0][ks + 8 + tig * 2];
        bl[nt][0] = *(const uint32_t*)&Bl[n0][ks + tig * 2];
        bl[nt][1] = *(const uint32_t*)&Bl[n0][ks + 8 + tig * 2];
      }
#pragma unroll
      for (int mt = 0; mt < 4; mt++) {
        int m0 = wm + mt * 16;
        uint32_t ah[4], al[4];
        ah[0] = *(const uint32_t*)&Ah[m0 + g][ks + tig * 2];
        ah[1] = *(const uint32_t*)&Ah[m0 + g + 8][ks + tig * 2];
        ah[2] = *(const uint32_t*)&Ah[m0 + g][ks + 8 + tig * 2];
        ah[3] = *(const uint32_t*)&Ah[m0 + g + 8][ks + 8 + tig * 2];
        al[0] = *(const uint32_t*)&Al[m0 + g][ks + tig * 2];
        al[1] = *(const uint32_t*)&Al[m0 + g + 8][ks + tig * 2];
        al[2] = *(const uint32_t*)&Al[m0 + g][ks + 8 + tig * 2];
        al[3] = *(const uint32_t*)&Al[m0 + g + 8][ks + 8 + tig * 2];
#pragma unroll
        for (int nt = 0; nt < 4; nt++) {
          MMA_BF16(acc[mt][nt], ah, bl[nt]);
          MMA_BF16(acc[mt][nt], al, bh[nt]);
          MMA_BF16(acc[mt][nt], ah, bh[nt]);
        }
      }
    }
    __syncthreads();
  }

  // epilogue
#pragma unroll
  for (int mt = 0; mt < 4; mt++) {
#pragma unroll
    for (int nt = 0; nt < 4; nt++) {
#pragma unroll
      for (int half = 0; half < 2; half++) {
        int m = bm + wm + mt * 16 + g + half * 8;
        if (m >= M) continue;
#pragma unroll
        for (int cc = 0; cc < 2; cc++) {
          int n = bn + wn + nt * 8 + tig * 2 + cc;
          if (n >= N) continue;
          float v = alpha * acc[mt][nt][half * 2 + cc];
          if (BIASMODE == 1) v += bias[n];
          if (BIASMODE == 2) v += bias[(m >> 11) * N + n];
          long off = (long)m * N + n;
          if (ACCUM) v += C[off];
          if (RELU) v = fmaxf(v, 0.f);
          C[off] = v;
        }
      }
    }
  }
}

// ---------------- small kernels ----------------
__global__ void zero_k(float* p, int n) {
  int i = blockIdx.x * 256 + threadIdx.x;
  if (i < n) p[i] = 0.f;
}
__global__ void copy_k(float* d, const float* s, int n) {
  int i = blockIdx.x * 256 + threadIdx.x;
  if (i < n) d[i] = s[i];
}
__global__ void vadd_k(float* o, const float* a, const float* b, int n) {
  int i = blockIdx.x * 256 + threadIdx.x;
  if (i < n) o[i] = a[i] + b[i];
}
__global__ void transp_k(float* o, const float* in) {  // (1024,256)->(256,1024)
  int i = blockIdx.x * 256 + threadIdx.x;
  if (i >= 1024 * 256) return;
  int g = i >> 8, k = i & 255;
  o[k * 1024 + g] = in[i];
}
__global__ void qcopy_k(float* qnode, const float* qh) {
  int b = blockIdx.x, d = threadIdx.x;
  qnode[b * DD + d] = qh[(b * QQ + QQ - 1) * DD + d];
}

__global__ void __launch_bounds__(1024) lstm_k(const float* __restrict__ gx,
                                               const float* __restrict__ whhT,
                                               float* __restrict__ qh) {
  int b = blockIdx.x, g = threadIdx.x;
  __shared__ float hs[DD], cs[DD], zs[L4D];
  if (g < DD) { hs[g] = 0.f; cs[g] = 0.f; }
  __syncthreads();
  for (int t = 0; t < QQ; t++) {
    float acc = gx[(b * QQ + t) * L4D + g];
#pragma unroll 8
    for (int k = 0; k < DD; k++) acc += hs[k] * whhT[k * L4D + g];
    zs[g] = acc;
    __syncthreads();
    if (g < DD) {
      float zi = zs[g], zf = zs[DD + g], zg = zs[2 * DD + g], zo = zs[3 * DD + g];
      float cn = (1.f / (1.f + expf(-zf))) * cs[g] +
                 (1.f / (1.f + expf(-zi))) * tanhf(zg);
      float hn = (1.f / (1.f + expf(-zo))) * tanhf(cn);
      cs[g] = cn;
      hs[g] = hn;
      qh[(b * QQ + t) * DD + g] = hn;
    }
    __syncthreads();
  }
}

__global__ void wr_k(const float* __restrict__ s0, const int* __restrict__ qt,
                     float* __restrict__ Wr) {
  int idx = blockIdx.x * 256 + threadIdx.x;
  if (idx >= BB * NRELROWS) return;
  int b = idx / NRELROWS, r = idx - b * NRELROWS;
  float raw[QQ], lg[QQ];
  float mx = -1e30f;
  for (int q = 0; q < QQ; q++) {
    float v = s0[(b * QQ + q) * NRELROWS + r];
    raw[q] = v;
    lg[q] = v + ((qt[b * QQ + q] == NWORD) ? VERY_NEG : 0.f);
    mx = fmaxf(mx, lg[q]);
  }
  float se = 0.f;
  for (int q = 0; q < QQ; q++) { lg[q] = expf(lg[q] - mx); se += lg[q]; }
  float w = 0.f;
  for (int q = 0; q < QQ; q++) w += (lg[q] / se) * raw[q];
  Wr[idx] = w;
}

__global__ void rowmax_k(const float* Wr, const int* rel, float* maxb) {
  int b = blockIdx.x;
  __shared__ float red[256];
  float mx = -1e30f;
  for (int f = threadIdx.x; f < FF; f += 256)
    mx = fmaxf(mx, Wr[b * NRELROWS + rel[b * FF + f]]);
  red[threadIdx.x] = mx;
  __syncthreads();
  for (int s = 128; s > 0; s >>= 1) {
    if (threadIdx.x < s) red[threadIdx.x] = fmaxf(red[threadIdx.x], red[threadIdx.x + s]);
    __syncthreads();
  }
  if (!threadIdx.x) maxb[b] = red[0];
}

__global__ void wtilde_k(const float* Wr, const int* rel, const int* e2f,
                         const float* maxb, float* Wt, float* e2fs) {
  int i = blockIdx.x * 256 + threadIdx.x;
  if (i >= BB * FF) return;
  int b = i >> 13;
  float wt = expf(Wr[b * NRELROWS + rel[i]] - maxb[b]);
  Wt[i] = wt;
  atomicAdd(&e2fs[b * EE + e2f[i]], wt);
}

__global__ void clamp_k(float* p, int n) {
  int i = blockIdx.x * 256 + threadIdx.x;
  if (i < n) p[i] = fmaxf(p[i], VERY_SMALL);
}

__global__ void cnt_k(float* cnt, const int* f2e) {
  int i = blockIdx.x * 256 + threadIdx.x;
  if (i >= BB * FF) return;
  atomicAdd(&cnt[(i >> 13) * EE + f2e[i]], 1.0f);
}

__global__ void fact_k(const float* __restrict__ fsl, const float* __restrict__ head,
                       const float* __restrict__ Wt, const float* __restrict__ pr,
                       const float* __restrict__ e2fs, const int* __restrict__ rel,
                       const int* __restrict__ e2f, const int* __restrict__ f2e,
                       float* __restrict__ Asc, float* __restrict__ prnew) {
  int bf = blockIdx.x;  // 0 .. B*F-1
  int b = bf >> 13;
  __shared__ float s_norm;
  __shared__ int s_esrc, s_edst, s_rel;
  if (threadIdx.x == 0) {
    int es = e2f[bf], ed = f2e[bf], r = rel[bf];
    float nrm = Wt[bf] * pr[b * EE + es] / e2fs[b * EE + es];
    s_norm = nrm; s_esrc = es; s_edst = ed; s_rel = r;
    atomicAdd(&prnew[b * EE + ed], nrm);
  }
  __syncthreads();
  int d = threadIdx.x;
  float v = fsl[s_rel * DD + d] + head[(long)(b * EE + s_esrc) * DD + d];
  v = fmaxf(v, 0.f) * s_norm;
  atomicAdd(&Asc[(long)(b * EE + s_edst) * DD + d], v);
}

__global__ void f2epre_k(float* eself, const float* cnt, const float* tb) {
  int i = blockIdx.x * 256 + threadIdx.x;
  if (i >= BB * EE * DD) return;
  eself[i] += cnt[i >> 8] * tb[i & 255];
}

__global__ void prupd_k(float* pr, const float* prnew, int n) {
  int i = blockIdx.x * 256 + threadIdx.x;
  if (i < n) pr[i] = 0.8f * prnew[i] + 0.2f * pr[i];
}

__global__ void prsum_k(const float* pr, float* prsum) {
  int b = blockIdx.x;
  __shared__ float red[256];
  float s = 0.f;
  for (int e = threadIdx.x; e < EE; e += 256) s += pr[b * EE + e];
  red[threadIdx.x] = s;
  __syncthreads();
  for (int st = 128; st > 0; st >>= 1) {
    if (threadIdx.x < st) red[threadIdx.x] += red[threadIdx.x + st];
    __syncthreads();
  }
  if (!threadIdx.x) prsum[b] = red[0];
}

__global__ void wsum_k(const float* __restrict__ pr, const float* __restrict__ le,
                       const float* __restrict__ f2e, float* __restrict__ sle,
                       float* __restrict__ sf2e) {
  int blk = blockIdx.x;
  int b = blk >> 3, ch = blk & 7;
  int d = threadIdx.x;
  float a = 0.f, c = 0.f;
  int e0 = ch * 256;
  for (int e = e0; e < e0 + 256; e++) {
    float w = pr[b * EE + e];
    a += w * le[(long)(b * EE + e) * DD + d];
    c += w * f2e[(long)(b * EE + e) * DD + d];
  }
  atomicAdd(&sle[b * DD + d], a);
  atomicAdd(&sf2e[b * DD + d], c);
}

// y[b,n] = bias[n] + sum_k x[b,k] * W[n*ldw + k]
__global__ void smallmv_k(const float* __restrict__ x, const float* __restrict__ W,
                          int ldw, const float* __restrict__ bias,
                          float* __restrict__ y, int K) {
  int b = blockIdx.x, n = threadIdx.x;
  const float* w = W + (long)n * ldw;
  const float* xb = x + b * K;
  float acc = bias ? bias[n] : 0.f;
  for (int k = 0; k < K; k++) acc += xb[k] * w[k];
  y[b * DD + n] = acc;
}

__global__ void qupd_k(const float* sle, const float* sf2e, const float* q2ev,
                       const float* prsum, const float* __restrict__ W,
                       const float* bias, float* qnode) {
  int b = blockIdx.x, n = threadIdx.x;
  const float* w = W + (long)n * 768;
  float ps = prsum[b];
  float acc = ps * bias[n];
  for (int k = 0; k < DD; k++) acc += sle[b * DD + k] * w[k];
  for (int k = 0; k < DD; k++) acc += ps * q2ev[b * DD + k] * w[DD + k];
  for (int k = 0; k < DD; k++) acc += 3.f * sf2e[b * DD + k] * w[2 * DD + k];
  qnode[b * DD + n] = acc;
}

__global__ void score_k(const float* __restrict__ le, const float* __restrict__ sw,
                        const float* __restrict__ sb, float* __restrict__ out) {
  int row = blockIdx.x * 8 + (threadIdx.x >> 5);
  int lane = threadIdx.x & 31;
  float acc = 0.f;
#pragma unroll
  for (int j = 0; j < 8; j++) {
    int k = lane + j * 32;
    acc += le[(long)row * DD + k] * sw[k];
  }
#pragma unroll
  for (int o = 16; o > 0; o >>= 1) acc += __shfl_down_sync(0xffffffffu, acc, o);
  if (!lane) out[row] = acc + sb[0];
}

// ---------------- host ----------------
extern "C" void kernel_launch(void* const* d_in, const int* in_sizes, int n_in,
                              void* d_out, int out_size) {
  const int* local_entity = (const int*)d_in[0];
  const float* q2e_adj = (const float*)d_in[1];
  const int* kb_fact_rel = (const int*)d_in[2];
  const int* query_text = (const int*)d_in[3];
  const int* e2f_ent = (const int*)d_in[5];
  const int* f2e_ent = (const int*)d_in[6];
  const float* word_emb = (const float*)d_in[7];
  const float* entity_emb = (const float*)d_in[8];
  const float* relation_emb = (const float*)d_in[9];
  const float* ent_w = (const float*)d_in[10];
  const float* ent_b = (const float*)d_in[11];
  const float* rel_w = (const float*)d_in[12];
  const float* rel_b = (const float*)d_in[13];
  const float* w_ih = (const float*)d_in[14];
  const float* w_hh = (const float*)d_in[15];
  const float* b_ih = (const float*)d_in[16];
  const float* b_hh = (const float*)d_in[17];
  const float* q2e_w = (const float*)d_in[18];
  const float* q2e_b = (const float*)d_in[19];
  const float* e2q_w = (const float*)d_in[20];
  const float* e2q_b = (const float*)d_in[21];
  const float* e2e_w = (const float*)d_in[22];
  const float* e2e_b = (const float*)d_in[23];
  const float* kb_head_w = (const float*)d_in[24];
  const float* kb_head_b = (const float*)d_in[25];
  const float* kb_tail_w = (const float*)d_in[26];
  const float* kb_tail_b = (const float*)d_in[27];
  const float* kb_self_w = (const float*)d_in[28];
  const float* kb_self_b = (const float*)d_in[29];
  const float* score_w = (const float*)d_in[30];
  const float* score_b = (const float*)d_in[31];
  float* out = (float*)d_out;
  (void)in_sizes; (void)n_in; (void)out_size;

  float *lr, *fs, *lstmb, *whhT, *gx, *qh, *qnode, *s0, *Wr, *maxb, *Wt, *e2fs;
  float *leA, *leB, *head, *eself, *Asc, *pr, *prnew, *cnt, *q2ev, *biasBE;
  float *sred, *prsum;
  cudaGetSymbolAddress((void**)&lr, g_lr);
  cudaGetSymbolAddress((void**)&fs, g_fs);
  cudaGetSymbolAddress((void**)&lstmb, g_lstmb);
  cudaGetSymbolAddress((void**)&whhT, g_whhT);
  cudaGetSymbolAddress((void**)&gx, g_gx);
  cudaGetSymbolAddress((void**)&qh, g_qh);
  cudaGetSymbolAddress((void**)&qnode, g_qnode);
  cudaGetSymbolAddress((void**)&s0, g_s0);
  cudaGetSymbolAddress((void**)&Wr, g_Wr);
  cudaGetSymbolAddress((void**)&maxb, g_maxb);
  cudaGetSymbolAddress((void**)&Wt, g_Wt);
  cudaGetSymbolAddress((void**)&e2fs, g_e2fs);
  cudaGetSymbolAddress((void**)&leA, g_leA);
  cudaGetSymbolAddress((void**)&leB, g_leB);
  cudaGetSymbolAddress((void**)&head, g_head);
  cudaGetSymbolAddress((void**)&eself, g_eself);
  cudaGetSymbolAddress((void**)&Asc, g_Asc);
  cudaGetSymbolAddress((void**)&pr, g_pr);
  cudaGetSymbolAddress((void**)&prnew, g_prnew);
  cudaGetSymbolAddress((void**)&cnt, g_cnt);
  cudaGetSymbolAddress((void**)&q2ev, g_q2ev);
  cudaGetSymbolAddress((void**)&biasBE, g_biasBE);
  cudaGetSymbolAddress((void**)&sred, g_sred);
  cudaGetSymbolAddress((void**)&prsum, g_prsum);

  const int ME = BB * EE;            // 32768
  const int MED = BB * EE * DD;      // 8388608
  dim3 gBig(2, ME / TBM);            // N=256 GEMMs on 32768 rows
  dim3 gRel(2, (NRELROWS + TBM - 1) / TBM);

  // --- prologue: relation tables, LSTM ---
  vadd_k<<<4, 256>>>(lstmb, b_ih, b_hh, L4D);
  transp_k<<<1024, 256>>>(whhT, w_hh);
  gemm_k<false, false, false, 1><<<gRel, 256>>>(
      lr, relation_emb, 600, nullptr, rel_w, 600, rel_b, NRELROWS, 256, 600, 1.f);
  for (int l = 0; l < 3; l++)
    gemm_k<false, false, false, 1><<<gRel, 256>>>(
        fs + l * NRELROWS * DD, lr, 256, nullptr, kb_self_w + l * 65536, 256,
        kb_self_b + l * 256, NRELROWS, 256, 256, 1.f);
  gemm_k<true, false, false, 1><<<dim3(8, 3), 256>>>(
      gx, word_emb, WDD, query_text, w_ih, WDD, lstmb, BB * QQ, L4D, WDD, 1.f);
  lstm_k<<<BB, 1024>>>(gx, whhT, qh);
  qcopy_k<<<BB, 256>>>(qnode, qh);

  // --- attention -> Wr -> W_tilde -> e2f_softmax ---
  gemm_k<false, false, false, 0><<<dim3(5, 3), 256>>>(
      s0, qh, 256, nullptr, lr, 256, nullptr, BB * QQ, NRELROWS, 256, 1.f / 16.f);
  wr_k<<<(BB * NRELROWS + 255) / 256, 256>>>(s0, query_text, Wr);
  rowmax_k<<<BB, 256>>>(Wr, kb_fact_rel, maxb);
  zero_k<<<(ME + 255) / 256, 256>>>(e2fs, ME);
  wtilde_k<<<(BB * FF) / 256, 256>>>(Wr, kb_fact_rel, e2f_ent, maxb, Wt, e2fs);
  clamp_k<<<(ME + 255) / 256, 256>>>(e2fs, ME);

  // --- entity embeddings, pagerank init, fact counts ---
  gemm_k<true, false, false, 1><<<gBig, 256>>>(
      leA, entity_emb, WDD, local_entity, ent_w, WDD, ent_b, ME, 256, WDD, 1.f);
  copy_k<<<(ME + 255) / 256, 256>>>(pr, q2e_adj, ME);
  zero_k<<<(ME + 255) / 256, 256>>>(cnt, ME);
  cnt_k<<<(BB * FF) / 256, 256>>>(cnt, f2e_ent);

  float* leCur = leA;
  float* leNxt = leB;
  for (int l = 0; l < 3; l++) {
    const float* Wh = kb_head_w + l * 65536;
    const float* Ws = kb_self_w + l * 65536;
    const float* Wtl = kb_tail_w + l * 65536;
    const float* We2e = e2e_w + l * 256 * 768;
    const float* We2q = e2q_w + l * 256 * 768;

    smallmv_k<<<BB, 256>>>(qnode, q2e_w + l * 65536, 256, q2e_b + l * 256, q2ev, 256);
    gemm_k<false, false, false, 1><<<gBig, 256>>>(
        head, leCur, 256, nullptr, Wh, 256, kb_head_b + l * 256, ME, 256, 256, 1.f);
    gemm_k<false, false, false, 1><<<gBig, 256>>>(
        eself, leCur, 256, nullptr, Ws, 256, kb_self_b + l * 256, ME, 256, 256, 1.f);
    zero_k<<<(MED + 255) / 256, 256>>>(Asc, MED);
    zero_k<<<(ME + 255) / 256, 256>>>(prnew, ME);
    fact_k<<<BB * FF, 256>>>(fs + l * NRELROWS * DD, head, Wt, pr, e2fs,
                             kb_fact_rel, e2f_ent, f2e_ent, Asc, prnew);
    f2epre_k<<<(MED + 255) / 256, 256>>>(eself, cnt, kb_tail_b + l * 256);
    gemm_k<false, true, true, 0><<<gBig, 256>>>(
        eself, Asc, 256, nullptr, Wtl, 256, nullptr, ME, 256, 256, 1.f);
    prupd_k<<<(ME + 255) / 256, 256>>>(pr, prnew, ME);
    zero_k<<<(2 * BB * DD + 255) / 256, 256>>>(sred, 2 * BB * DD);
    prsum_k<<<BB, 256>>>(pr, prsum);
    wsum_k<<<BB * 8, 256>>>(pr, leCur, eself, sred, sred + BB * DD);
    qupd_k<<<BB, 256>>>(sred, sred + BB * DD, q2ev, prsum, We2q,
                        e2q_b + l * 256, qnode);
    smallmv_k<<<BB, 256>>>(q2ev, We2e + 256, 768, e2e_b + l * 256, biasBE, 256);
    gemm_k<false, false, false, 2><<<gBig, 256>>>(
        leNxt, leCur, 256, nullptr, We2e, 768, biasBE, ME, 256, 256, 1.f);
    gemm_k<false, true, true, 0><<<gBig, 256>>>(
        leNxt, eself, 256, nullptr, We2e + 512, 768, nullptr, ME, 256, 256, 3.f);
    float* t = leCur; leCur = leNxt; leNxt = t;
  }

  score_k<<<ME / 8, 256>>>(leCur, score_w, score_b, out);
}

// round 5
// speedup vs baseline: 1.2298x; 1.2298x over previous
#include <cuda_runtime.h>
#include <math.h>
#include <stdint.h>

#define BB 16
#define EE 2048
#define FF 8192
#define QQ 20
#define DD 256
#define WDD 300
#define NRELROWS 601
#define L4D 1024
#define NWORD 50000

#define VERY_NEG -1e11f
#define VERY_SMALL 1e-10f

// ---------------- scratch (device globals; no runtime alloc) ----------------
__device__ float g_lr[NRELROWS * DD];
__device__ float g_fs[3 * NRELROWS * DD];
__device__ float g_lstmb[L4D];
__device__ float g_whhT[DD * L4D];
__device__ float g_gx[BB * QQ * L4D];
__device__ float g_qh[BB * QQ * DD];
__device__ float g_qnode[BB * DD];
__device__ float g_s0[BB * QQ * NRELROWS];
__device__ float g_Wr[BB * NRELROWS];
__device__ float g_maxb[BB];
__device__ float g_Wt[BB * FF];
__device__ float g_e2fs[BB * EE];
__device__ float g_leA[BB * EE * DD];
__device__ float g_leB[BB * EE * DD];
__device__ float g_head[BB * EE * DD];
__device__ float g_eself[BB * EE * DD];   // becomes f2e_emb in-place
__device__ float g_Asc[BB * EE * DD];
__device__ float g_pr[BB * EE];
__device__ float g_prnew[BB * EE];
__device__ float g_cnt[BB * EE];
__device__ float g_q2ev[BB * DD];
__device__ float g_biasBE[BB * DD];
__device__ float g_sred[2 * BB * DD];
__device__ float g_prsum[BB];

// ---------------- tensor-core GEMM core (3xTF32 for fp32 accuracy) ----------
#define TBM 128
#define TBN 128
#define TBK 32
#define TLD (TBK + 4)   // padded smem row stride (floats)

__device__ __forceinline__ void tf32split(float f, uint32_t& hi, uint32_t& lo) {
  asm("cvt.rna.tf32.f32 %0, %1;" : "=r"(hi) : "f"(f));
  float r = f - __uint_as_float(hi);
  asm("cvt.rna.tf32.f32 %0, %1;" : "=r"(lo) : "f"(r));
}

#define MMA_TF32(c, a, b)                                                  \
  asm volatile(                                                            \
      "mma.sync.aligned.m16n8k8.row.col.f32.tf32.tf32.f32 "                \
      "{%0,%1,%2,%3},{%4,%5,%6,%7},{%8,%9},{%0,%1,%2,%3};"                 \
      : "+f"((c)[0]), "+f"((c)[1]), "+f"((c)[2]), "+f"((c)[3])             \
      : "r"((a)[0]), "r"((a)[1]), "r"((a)[2]), "r"((a)[3]),                \
        "r"((b)[0]), "r"((b)[1]));

// inner compute over one smem tile: acc += As-tile @ Bs-tile^T
__device__ __forceinline__ void mma_tile(float acc[4][4][4],
                                         const float (*As)[TLD],
                                         const float (*Bs)[TLD], int wm,
                                         int wn, int g, int tig) {
#pragma unroll
  for (int ks = 0; ks < TBK; ks += 8) {
    uint32_t ahi[4][4], alo[4][4], bhi[4][2], blo[4][2];
#pragma unroll
    for (int mt = 0; mt < 4; mt++) {
      int m0 = wm + mt * 16;
      tf32split(As[m0 + g][ks + tig], ahi[mt][0], alo[mt][0]);
      tf32split(As[m0 + g + 8][ks + tig], ahi[mt][1], alo[mt][1]);
      tf32split(As[m0 + g][ks + tig + 4], ahi[mt][2], alo[mt][2]);
      tf32split(As[m0 + g + 8][ks + tig + 4], ahi[mt][3], alo[mt][3]);
    }
#pragma unroll
    for (int nt = 0; nt < 4; nt++) {
      int n0 = wn + nt * 8 + g;
      tf32split(Bs[n0][ks + tig], bhi[nt][0], blo[nt][0]);
      tf32split(Bs[n0][ks + tig + 4], bhi[nt][1], blo[nt][1]);
    }
#pragma unroll
    for (int mt = 0; mt < 4; mt++)
#pragma unroll
      for (int nt = 0; nt < 4; nt++) {
        MMA_TF32(acc[mt][nt], ahi[mt], blo[nt]);
        MMA_TF32(acc[mt][nt], alo[mt], bhi[nt]);
        MMA_TF32(acc[mt][nt], ahi[mt], bhi[nt]);
      }
  }
}

// ---------------- generic GEMM: C = act([C +] alpha*A@W^T + bias) ------------
// BIASMODE: 0 none, 1 bias[n], 2 bias[(m>>11)*N + n]
template <bool GATHER, bool ACCUM, bool RELU, int BIASMODE>
__global__ void __launch_bounds__(256) gemm_k(
    float* __restrict__ C, const float* __restrict__ A, int lda,
    const int* __restrict__ gidx, const float* __restrict__ W, int ldw,
    const float* __restrict__ bias, int M, int N, int K, float alpha) {
  __shared__ float As[TBM][TLD];
  __shared__ float Bs[TBN][TLD];
  const int bm = blockIdx.y * TBM, bn = blockIdx.x * TBN;
  const int tid = threadIdx.x;
  const int warp = tid >> 5, lane = tid & 31;
  const int g = lane >> 2, tig = lane & 3;
  const int wm = (warp >> 2) * 64, wn = (warp & 3) * 32;

  float acc[4][4][4];
#pragma unroll
  for (int i = 0; i < 4; i++)
#pragma unroll
    for (int j = 0; j < 4; j++)
#pragma unroll
      for (int c = 0; c < 4; c++) acc[i][j][c] = 0.f;

  for (int kk0 = 0; kk0 < K; kk0 += TBK) {
#pragma unroll
    for (int i = 0; i < 4; i++) {
      int idx = tid + i * 256;
      int row = idx >> 3, kq = idx & 7;
      int k = kk0 + kq * 4;
      float4 va = make_float4(0.f, 0.f, 0.f, 0.f);
      int m = bm + row;
      if (m < M) {
        long r = GATHER ? (long)gidx[m] : (long)m;
        const float* p = A + r * (long)lda + k;
        if (k + 3 < K) va = *(const float4*)p;
        else {
          if (k < K) va.x = p[0];
          if (k + 1 < K) va.y = p[1];
          if (k + 2 < K) va.z = p[2];
        }
      }
      *(float4*)&As[row][kq * 4] = va;
      float4 vb = make_float4(0.f, 0.f, 0.f, 0.f);
      int n = bn + row;
      if (n < N) {
        const float* p = W + (long)n * ldw + k;
        if (k + 3 < K) vb = *(const float4*)p;
        else {
          if (k < K) vb.x = p[0];
          if (k + 1 < K) vb.y = p[1];
          if (k + 2 < K) vb.z = p[2];
        }
      }
      *(float4*)&Bs[row][kq * 4] = vb;
    }
    __syncthreads();
    mma_tile(acc, As, Bs, wm, wn, g, tig);
    __syncthreads();
  }

#pragma unroll
  for (int mt = 0; mt < 4; mt++) {
#pragma unroll
    for (int nt = 0; nt < 4; nt++) {
#pragma unroll
      for (int half = 0; half < 2; half++) {
        int m = bm + wm + mt * 16 + g + half * 8;
        if (m >= M) continue;
#pragma unroll
        for (int cc = 0; cc < 2; cc++) {
          int n = bn + wn + nt * 8 + tig * 2 + cc;
          if (n >= N) continue;
          float v = alpha * acc[mt][nt][half * 2 + cc];
          if (BIASMODE == 1) v += bias[n];
          if (BIASMODE == 2) v += bias[(m >> 11) * N + n];
          long off = (long)m * N + n;
          if (ACCUM) v += C[off];
          if (RELU) v = fmaxf(v, 0.f);
          C[off] = v;
        }
      }
    }
  }
}

// ------------- dual-output GEMM: head = A@W1^T+b1 ; self = A@W2^T+b2 --------
// N logical = 512 (cols 0..255 -> C1/W1/b1, 256..511 -> C2/W2/b2), ldw = 256
__global__ void __launch_bounds__(256) gemm_dualout_k(
    float* __restrict__ C1, float* __restrict__ C2,
    const float* __restrict__ A, const float* __restrict__ W1,
    const float* __restrict__ W2, const float* __restrict__ b1,
    const float* __restrict__ b2, int M) {
  __shared__ float As[TBM][TLD];
  __shared__ float Bs[TBN][TLD];
  const int bm = blockIdx.y * TBM, bn = blockIdx.x * TBN;
  const int tid = threadIdx.x;
  const int warp = tid >> 5, lane = tid & 31;
  const int g = lane >> 2, tig = lane & 3;
  const int wm = (warp >> 2) * 64, wn = (warp & 3) * 32;

  float acc[4][4][4];
#pragma unroll
  for (int i = 0; i < 4; i++)
#pragma unroll
    for (int j = 0; j < 4; j++)
#pragma unroll
      for (int c = 0; c < 4; c++) acc[i][j][c] = 0.f;

  for (int kk0 = 0; kk0 < DD; kk0 += TBK) {
#pragma unroll
    for (int i = 0; i < 4; i++) {
      int idx = tid + i * 256;
      int row = idx >> 3, kq = idx & 7;
      int k = kk0 + kq * 4;
      *(float4*)&As[row][kq * 4] =
          *(const float4*)(A + (long)(bm + row) * DD + k);
      int n = bn + row;
      const float* Wp = (n < 256) ? (W1 + (long)n * DD) : (W2 + (long)(n - 256) * DD);
      *(float4*)&Bs[row][kq * 4] = *(const float4*)(Wp + k);
    }
    __syncthreads();
    mma_tile(acc, As, Bs, wm, wn, g, tig);
    __syncthreads();
  }

#pragma unroll
  for (int mt = 0; mt < 4; mt++)
#pragma unroll
    for (int nt = 0; nt < 4; nt++)
#pragma unroll
      for (int half = 0; half < 2; half++) {
        int m = bm + wm + mt * 16 + g + half * 8;
#pragma unroll
        for (int cc = 0; cc < 2; cc++) {
          int n = bn + wn + nt * 8 + tig * 2 + cc;
          float v = acc[mt][nt][half * 2 + cc];
          if (n < 256) C1[(long)m * DD + n] = v + b1[n];
          else C2[(long)m * DD + (n - 256)] = v + b2[n - 256];
        }
      }
}

// -------- dual-input GEMM: C = relu(A1@W1^T + sc2*A2@W2^T + biasBE) ---------
// K logical = 512; chunks <256 from A1/W1, >=256 from A2(*sc2)/W2. ldw = 768.
__global__ void __launch_bounds__(256) gemm_dualin_k(
    float* __restrict__ C, const float* __restrict__ A1,
    const float* __restrict__ A2, const float* __restrict__ W1,
    const float* __restrict__ W2, const float* __restrict__ biasBE,
    float sc2, int M) {
  __shared__ float As[TBM][TLD];
  __shared__ float Bs[TBN][TLD];
  const int bm = blockIdx.y * TBM, bn = blockIdx.x * TBN;
  const int tid = threadIdx.x;
  const int warp = tid >> 5, lane = tid & 31;
  const int g = lane >> 2, tig = lane & 3;
  const int wm = (warp >> 2) * 64, wn = (warp & 3) * 32;

  float acc[4][4][4];
#pragma unroll
  for (int i = 0; i < 4; i++)
#pragma unroll
    for (int j = 0; j < 4; j++)
#pragma unroll
      for (int c = 0; c < 4; c++) acc[i][j][c] = 0.f;

  for (int kk0 = 0; kk0 < 2 * DD; kk0 += TBK) {
    const bool second = (kk0 >= DD);
    const float* Asrc = second ? A2 : A1;
    const float* Wsrc = second ? W2 : W1;
    const int kb = second ? (kk0 - DD) : kk0;
    const float sc = second ? sc2 : 1.f;
#pragma unroll
    for (int i = 0; i < 4; i++) {
      int idx = tid + i * 256;
      int row = idx >> 3, kq = idx & 7;
      int k = kb + kq * 4;
      float4 va = *(const float4*)(Asrc + (long)(bm + row) * DD + k);
      va.x *= sc; va.y *= sc; va.z *= sc; va.w *= sc;
      *(float4*)&As[row][kq * 4] = va;
      *(float4*)&Bs[row][kq * 4] =
          *(const float4*)(Wsrc + (long)(bn + row) * 768 + k);
    }
    __syncthreads();
    mma_tile(acc, As, Bs, wm, wn, g, tig);
    __syncthreads();
  }

#pragma unroll
  for (int mt = 0; mt < 4; mt++)
#pragma unroll
    for (int nt = 0; nt < 4; nt++)
#pragma unroll
      for (int half = 0; half < 2; half++) {
        int m = bm + wm + mt * 16 + g + half * 8;
#pragma unroll
        for (int cc = 0; cc < 2; cc++) {
          int n = bn + wn + nt * 8 + tig * 2 + cc;
          float v = acc[mt][nt][half * 2 + cc] + biasBE[(m >> 11) * DD + n];
          C[(long)m * DD + n] = fmaxf(v, 0.f);
        }
      }
}

// ---------------- small kernels ----------------
__global__ void zero_k(float* p, int n) {
  int i = blockIdx.x * 256 + threadIdx.x;
  if (i < n) p[i] = 0.f;
}
__global__ void copy_k(float* d, const float* s, int n) {
  int i = blockIdx.x * 256 + threadIdx.x;
  if (i < n) d[i] = s[i];
}
__global__ void vadd_k(float* o, const float* a, const float* b, int n) {
  int i = blockIdx.x * 256 + threadIdx.x;
  if (i < n) o[i] = a[i] + b[i];
}
__global__ void transp_k(float* o, const float* in) {  // (1024,256)->(256,1024)
  int i = blockIdx.x * 256 + threadIdx.x;
  if (i >= 1024 * 256) return;
  int g = i >> 8, k = i & 255;
  o[k * 1024 + g] = in[i];
}
__global__ void qcopy_k(float* qnode, const float* qh) {
  int b = blockIdx.x, d = threadIdx.x;
  qnode[b * DD + d] = qh[(b * QQ + QQ - 1) * DD + d];
}

__global__ void __launch_bounds__(1024) lstm_k(const float* __restrict__ gx,
                                               const float* __restrict__ whhT,
                                               float* __restrict__ qh) {
  int b = blockIdx.x, g = threadIdx.x;
  __shared__ float hs[DD], cs[DD], zs[L4D];
  if (g < DD) { hs[g] = 0.f; cs[g] = 0.f; }
  __syncthreads();
  for (int t = 0; t < QQ; t++) {
    float acc = gx[(b * QQ + t) * L4D + g];
#pragma unroll 8
    for (int k = 0; k < DD; k++) acc += hs[k] * whhT[k * L4D + g];
    zs[g] = acc;
    __syncthreads();
    if (g < DD) {
      float zi = zs[g], zf = zs[DD + g], zg = zs[2 * DD + g], zo = zs[3 * DD + g];
      float cn = (1.f / (1.f + expf(-zf))) * cs[g] +
                 (1.f / (1.f + expf(-zi))) * tanhf(zg);
      float hn = (1.f / (1.f + expf(-zo))) * tanhf(cn);
      cs[g] = cn;
      hs[g] = hn;
      qh[(b * QQ + t) * DD + g] = hn;
    }
    __syncthreads();
  }
}

__global__ void wr_k(const float* __restrict__ s0, const int* __restrict__ qt,
                     float* __restrict__ Wr) {
  int idx = blockIdx.x * 256 + threadIdx.x;
  if (idx >= BB * NRELROWS) return;
  int b = idx / NRELROWS, r = idx - b * NRELROWS;
  float raw[QQ], lg[QQ];
  float mx = -1e30f;
  for (int q = 0; q < QQ; q++) {
    float v = s0[(b * QQ + q) * NRELROWS + r];
    raw[q] = v;
    lg[q] = v + ((qt[b * QQ + q] == NWORD) ? VERY_NEG : 0.f);
    mx = fmaxf(mx, lg[q]);
  }
  float se = 0.f;
  for (int q = 0; q < QQ; q++) { lg[q] = expf(lg[q] - mx); se += lg[q]; }
  float w = 0.f;
  for (int q = 0; q < QQ; q++) w += (lg[q] / se) * raw[q];
  Wr[idx] = w;
}

__global__ void rowmax_k(const float* Wr, const int* rel, float* maxb) {
  int b = blockIdx.x;
  __shared__ float red[256];
  float mx = -1e30f;
  for (int f = threadIdx.x; f < FF; f += 256)
    mx = fmaxf(mx, Wr[b * NRELROWS + rel[b * FF + f]]);
  red[threadIdx.x] = mx;
  __syncthreads();
  for (int s = 128; s > 0; s >>= 1) {
    if (threadIdx.x < s) red[threadIdx.x] = fmaxf(red[threadIdx.x], red[threadIdx.x + s]);
    __syncthreads();
  }
  if (!threadIdx.x) maxb[b] = red[0];
}

__global__ void wtilde_k(const float* Wr, const int* rel, const int* e2f,
                         const float* maxb, float* Wt, float* e2fs) {
  int i = blockIdx.x * 256 + threadIdx.x;
  if (i >= BB * FF) return;
  int b = i >> 13;
  float wt = expf(Wr[b * NRELROWS + rel[i]] - maxb[b]);
  Wt[i] = wt;
  atomicAdd(&e2fs[b * EE + e2f[i]], wt);
}

__global__ void clamp_k(float* p, int n) {
  int i = blockIdx.x * 256 + threadIdx.x;
  if (i < n) p[i] = fmaxf(p[i], VERY_SMALL);
}

__global__ void cnt_k(float* cnt, const int* f2e) {
  int i = blockIdx.x * 256 + threadIdx.x;
  if (i >= BB * FF) return;
  atomicAdd(&cnt[(i >> 13) * EE + f2e[i]], 1.0f);
}

__global__ void fact_k(const float* __restrict__ fsl, const float* __restrict__ head,
                       const float* __restrict__ Wt, const float* __restrict__ pr,
                       const float* __restrict__ e2fs, const int* __restrict__ rel,
                       const int* __restrict__ e2f, const int* __restrict__ f2e,
                       float* __restrict__ Asc, float* __restrict__ prnew) {
  int bf = blockIdx.x;  // 0 .. B*F-1
  int b = bf >> 13;
  __shared__ float s_norm;
  __shared__ int s_esrc, s_edst, s_rel;
  if (threadIdx.x == 0) {
    int es = e2f[bf], ed = f2e[bf], r = rel[bf];
    float nrm = Wt[bf] * pr[b * EE + es] / e2fs[b * EE + es];
    s_norm = nrm; s_esrc = es; s_edst = ed; s_rel = r;
    atomicAdd(&prnew[b * EE + ed], nrm);
  }
  __syncthreads();
  int d = threadIdx.x;
  float v = fsl[s_rel * DD + d] + head[(long)(b * EE + s_esrc) * DD + d];
  v = fmaxf(v, 0.f) * s_norm;
  atomicAdd(&Asc[(long)(b * EE + s_edst) * DD + d], v);
}

__global__ void f2epre_k(float* eself, const float* cnt, const float* tb) {
  int i = blockIdx.x * 256 + threadIdx.x;
  if (i >= BB * EE * DD) return;
  eself[i] += cnt[i >> 8] * tb[i & 255];
}

__global__ void prupd_k(float* pr, const float* prnew, int n) {
  int i = blockIdx.x * 256 + threadIdx.x;
  if (i < n) pr[i] = 0.8f * prnew[i] + 0.2f * pr[i];
}

__global__ void prsum_k(const float* pr, float* prsum) {
  int b = blockIdx.x;
  __shared__ float red[256];
  float s = 0.f;
  for (int e = threadIdx.x; e < EE; e += 256) s += pr[b * EE + e];
  red[threadIdx.x] = s;
  __syncthreads();
  for (int st = 128; st > 0; st >>= 1) {
    if (threadIdx.x < st) red[threadIdx.x] += red[threadIdx.x + st];
    __syncthreads();
  }
  if (!threadIdx.x) prsum[b] = red[0];
}

__global__ void wsum_k(const float* __restrict__ pr, const float* __restrict__ le,
                       const float* __restrict__ f2e, float* __restrict__ sle,
                       float* __restrict__ sf2e) {
  int blk = blockIdx.x;
  int b = blk >> 3, ch = blk & 7;
  int d = threadIdx.x;
  float a = 0.f, c = 0.f;
  int e0 = ch * 256;
  for (int e = e0; e < e0 + 256; e++) {
    float w = pr[b * EE + e];
    a += w * le[(long)(b * EE + e) * DD + d];
    c += w * f2e[(long)(b * EE + e) * DD + d];
  }
  atomicAdd(&sle[b * DD + d], a);
  atomicAdd(&sf2e[b * DD + d], c);
}

// y[b,n] = bias[n] + sum_k x[b,k] * W[n*ldw + k]
__global__ void smallmv_k(const float* __restrict__ x, const float* __restrict__ W,
                          int ldw, const float* __restrict__ bias,
                          float* __restrict__ y, int K) {
  int b = blockIdx.x, n = threadIdx.x;
  const float* w = W + (long)n * ldw;
  const float* xb = x + b * K;
  float acc = bias ? bias[n] : 0.f;
  for (int k = 0; k < K; k++) acc += xb[k] * w[k];
  y[b * DD + n] = acc;
}

__global__ void qupd_k(const float* sle, const float* sf2e, const float* q2ev,
                       const float* prsum, const float* __restrict__ W,
                       const float* bias, float* qnode) {
  int b = blockIdx.x, n = threadIdx.x;
  const float* w = W + (long)n * 768;
  float ps = prsum[b];
  float acc = ps * bias[n];
  for (int k = 0; k < DD; k++) acc += sle[b * DD + k] * w[k];
  for (int k = 0; k < DD; k++) acc += ps * q2ev[b * DD + k] * w[DD + k];
  for (int k = 0; k < DD; k++) acc += 3.f * sf2e[b * DD + k] * w[2 * DD + k];
  qnode[b * DD + n] = acc;
}

__global__ void score_k(const float* __restrict__ le, const float* __restrict__ sw,
                        const float* __restrict__ sb, float* __restrict__ out) {
  int row = blockIdx.x * 8 + (threadIdx.x >> 5);
  int lane = threadIdx.x & 31;
  float acc = 0.f;
#pragma unroll
  for (int j = 0; j < 8; j++) {
    int k = lane + j * 32;
    acc += le[(long)row * DD + k] * sw[k];
  }
#pragma unroll
  for (int o = 16; o > 0; o >>= 1) acc += __shfl_down_sync(0xffffffffu, acc, o);
  if (!lane) out[row] = acc + sb[0];
}

// ---------------- host ----------------
extern "C" void kernel_launch(void* const* d_in, const int* in_sizes, int n_in,
                              void* d_out, int out_size) {
  const int* local_entity = (const int*)d_in[0];
  const float* q2e_adj = (const float*)d_in[1];
  const int* kb_fact_rel = (const int*)d_in[2];
  const int* query_text = (const int*)d_in[3];
  const int* e2f_ent = (const int*)d_in[5];
  const int* f2e_ent = (const int*)d_in[6];
  const float* word_emb = (const float*)d_in[7];
  const float* entity_emb = (const float*)d_in[8];
  const float* relation_emb = (const float*)d_in[9];
  const float* ent_w = (const float*)d_in[10];
  const float* ent_b = (const float*)d_in[11];
  const float* rel_w = (const float*)d_in[12];
  const float* rel_b = (const float*)d_in[13];
  const float* w_ih = (const float*)d_in[14];
  const float* w_hh = (const float*)d_in[15];
  const float* b_ih = (const float*)d_in[16];
  const float* b_hh = (const float*)d_in[17];
  const float* q2e_w = (const float*)d_in[18];
  const float* q2e_b = (const float*)d_in[19];
  const float* e2q_w = (const float*)d_in[20];
  const float* e2q_b = (const float*)d_in[21];
  const float* e2e_w = (const float*)d_in[22];
  const float* e2e_b = (const float*)d_in[23];
  const float* kb_head_w = (const float*)d_in[24];
  const float* kb_head_b = (const float*)d_in[25];
  const float* kb_tail_w = (const float*)d_in[26];
  const float* kb_tail_b = (const float*)d_in[27];
  const float* kb_self_w = (const float*)d_in[28];
  const float* kb_self_b = (const float*)d_in[29];
  const float* score_w = (const float*)d_in[30];
  const float* score_b = (const float*)d_in[31];
  float* out = (float*)d_out;
  (void)in_sizes; (void)n_in; (void)out_size;

  float *lr, *fs, *lstmb, *whhT, *gx, *qh, *qnode, *s0, *Wr, *maxb, *Wt, *e2fs;
  float *leA, *leB, *head, *eself, *Asc, *pr, *prnew, *cnt, *q2ev, *biasBE;
  float *sred, *prsum;
  cudaGetSymbolAddress((void**)&lr, g_lr);
  cudaGetSymbolAddress((void**)&fs, g_fs);
  cudaGetSymbolAddress((void**)&lstmb, g_lstmb);
  cudaGetSymbolAddress((void**)&whhT, g_whhT);
  cudaGetSymbolAddress((void**)&gx, g_gx);
  cudaGetSymbolAddress((void**)&qh, g_qh);
  cudaGetSymbolAddress((void**)&qnode, g_qnode);
  cudaGetSymbolAddress((void**)&s0, g_s0);
  cudaGetSymbolAddress((void**)&Wr, g_Wr);
  cudaGetSymbolAddress((void**)&maxb, g_maxb);
  cudaGetSymbolAddress((void**)&Wt, g_Wt);
  cudaGetSymbolAddress((void**)&e2fs, g_e2fs);
  cudaGetSymbolAddress((void**)&leA, g_leA);
  cudaGetSymbolAddress((void**)&leB, g_leB);
  cudaGetSymbolAddress((void**)&head, g_head);
  cudaGetSymbolAddress((void**)&eself, g_eself);
  cudaGetSymbolAddress((void**)&Asc, g_Asc);
  cudaGetSymbolAddress((void**)&pr, g_pr);
  cudaGetSymbolAddress((void**)&prnew, g_prnew);
  cudaGetSymbolAddress((void**)&cnt, g_cnt);
  cudaGetSymbolAddress((void**)&q2ev, g_q2ev);
  cudaGetSymbolAddress((void**)&biasBE, g_biasBE);
  cudaGetSymbolAddress((void**)&sred, g_sred);
  cudaGetSymbolAddress((void**)&prsum, g_prsum);

  const int ME = BB * EE;            // 32768
  const int MED = BB * EE * DD;      // 8388608
  dim3 gBig(2, ME / TBM);            // N=256 GEMMs on 32768 rows
  dim3 gBig512(4, ME / TBM);         // N=512 dual-output GEMM
  dim3 gRel(2, (NRELROWS + TBM - 1) / TBM);

  // --- prologue (ordered so launch #6 = the BIG leA GEMM gets profiled) ---
  vadd_k<<<4, 256>>>(lstmb, b_ih, b_hh, L4D);                      // 1
  transp_k<<<1024, 256>>>(whhT, w_hh);                             // 2
  gemm_k<false, false, false, 1><<<gRel, 256>>>(                   // 3
      lr, relation_emb, 600, nullptr, rel_w, 600, rel_b, NRELROWS, 256, 600, 1.f);
  gemm_k<false, false, false, 1><<<gRel, 256>>>(                   // 4
      fs, lr, 256, nullptr, kb_self_w, 256, kb_self_b, NRELROWS, 256, 256, 1.f);
  gemm_k<false, false, false, 1><<<gRel, 256>>>(                   // 5
      fs + NRELROWS * DD, lr, 256, nullptr, kb_self_w + 65536, 256,
      kb_self_b + 256, NRELROWS, 256, 256, 1.f);
  gemm_k<true, false, false, 1><<<gBig, 256>>>(                    // 6 <- profiled
      leA, entity_emb, WDD, local_entity, ent_w, WDD, ent_b, ME, 256, WDD, 1.f);
  gemm_k<false, false, false, 1><<<gRel, 256>>>(
      fs + 2 * NRELROWS * DD, lr, 256, nullptr, kb_self_w + 2 * 65536, 256,
      kb_self_b + 2 * 256, NRELROWS, 256, 256, 1.f);
  gemm_k<true, false, false, 1><<<dim3(8, 3), 256>>>(
      gx, word_emb, WDD, query_text, w_ih, WDD, lstmb, BB * QQ, L4D, WDD, 1.f);
  lstm_k<<<BB, 1024>>>(gx, whhT, qh);
  qcopy_k<<<BB, 256>>>(qnode, qh);

  // --- attention -> Wr -> W_tilde -> e2f_softmax ---
  gemm_k<false, false, false, 0><<<dim3(5, 3), 256>>>(
      s0, qh, 256, nullptr, lr, 256, nullptr, BB * QQ, NRELROWS, 256, 1.f / 16.f);
  wr_k<<<(BB * NRELROWS + 255) / 256, 256>>>(s0, query_text, Wr);
  rowmax_k<<<BB, 256>>>(Wr, kb_fact_rel, maxb);
  zero_k<<<(ME + 255) / 256, 256>>>(e2fs, ME);
  wtilde_k<<<(BB * FF) / 256, 256>>>(Wr, kb_fact_rel, e2f_ent, maxb, Wt, e2fs);
  clamp_k<<<(ME + 255) / 256, 256>>>(e2fs, ME);

  // --- pagerank init, fact counts ---
  copy_k<<<(ME + 255) / 256, 256>>>(pr, q2e_adj, ME);
  zero_k<<<(ME + 255) / 256, 256>>>(cnt, ME);
  cnt_k<<<(BB * FF) / 256, 256>>>(cnt, f2e_ent);

  float* leCur = leA;
  float* leNxt = leB;
  for (int l = 0; l < 3; l++) {
    const float* Wh = kb_head_w + l * 65536;
    const float* Ws = kb_self_w + l * 65536;
    const float* Wtl = kb_tail_w + l * 65536;
    const float* We2e = e2e_w + l * 256 * 768;
    const float* We2q = e2q_w + l * 256 * 768;

    smallmv_k<<<BB, 256>>>(qnode, q2e_w + l * 65536, 256, q2e_b + l * 256, q2ev, 256);
    gemm_dualout_k<<<gBig512, 256>>>(head, eself, leCur, Wh, Ws,
                                     kb_head_b + l * 256, kb_self_b + l * 256, ME);
    zero_k<<<(MED + 255) / 256, 256>>>(Asc, MED);
    zero_k<<<(ME + 255) / 256, 256>>>(prnew, ME);
    fact_k<<<BB * FF, 256>>>(fs + l * NRELROWS * DD, head, Wt, pr, e2fs,
                             kb_fact_rel, e2f_ent, f2e_ent, Asc, prnew);
    f2epre_k<<<(MED + 255) / 256, 256>>>(eself, cnt, kb_tail_b + l * 256);
    gemm_k<false, true, true, 0><<<gBig, 256>>>(
        eself, Asc, 256, nullptr, Wtl, 256, nullptr, ME, 256, 256, 1.f);
    prupd_k<<<(ME + 255) / 256, 256>>>(pr, prnew, ME);
    zero_k<<<(2 * BB * DD + 255) / 256, 256>>>(sred, 2 * BB * DD);
    prsum_k<<<BB, 256>>>(pr, prsum);
    wsum_k<<<BB * 8, 256>>>(pr, leCur, eself, sred, sred + BB * DD);
    qupd_k<<<BB, 256>>>(sred, sred + BB * DD, q2ev, prsum, We2q,
                        e2q_b + l * 256, qnode);
    smallmv_k<<<BB, 256>>>(q2ev, We2e + 256, 768, e2e_b + l * 256, biasBE, 256);
    gemm_dualin_k<<<gBig, 256>>>(leNxt, leCur, eself, We2e, We2e + 512, biasBE,
                                 3.f, ME);
    float* t = leCur; leCur = leNxt; leNxt = t;
  }

  score_k<<<ME / 8, 256>>>(leCur, score_w, score_b, out);
}

// round 7
// speedup vs baseline: 1.4245x; 1.1584x over previous
#include <cuda_runtime.h>
#include <math.h>
#include <stdint.h>

#define BB 16
#define EE 2048
#define FF 8192
#define QQ 20
#define DD 256
#define WDD 300
#define NRELROWS 601
#define L4D 1024
#define NWORD 50000

#define VERY_NEG -1e11f
#define VERY_SMALL 1e-10f

// ---------------- scratch (device globals; no runtime alloc) ----------------
__device__ float g_lr[NRELROWS * DD];
__device__ float g_fs[3 * NRELROWS * DD];
__device__ float g_lstmb[L4D];
__device__ float g_whhT[DD * L4D];
__device__ float g_gx[BB * QQ * L4D];
__device__ float g_qh[BB * QQ * DD];
__device__ float g_qnode[BB * DD];
__device__ float g_s0[BB * QQ * NRELROWS];
__device__ float g_Wr[BB * NRELROWS];
__device__ float g_maxb[BB];
__device__ float g_Wt[BB * FF];
__device__ float g_e2fs[BB * EE];
__device__ float g_leA[BB * EE * DD];
__device__ float g_leB[BB * EE * DD];
__device__ float g_head[BB * EE * DD];
__device__ float g_eself[BB * EE * DD];   // becomes f2e_emb in-place
__device__ float g_Asc[BB * EE * DD];
__device__ float g_pr[BB * EE];
__device__ float g_prnew[BB * EE];
__device__ float g_cnt[BB * EE];
__device__ float g_q2ev[BB * DD];
__device__ float g_biasBE[BB * DD];
__device__ float g_sred[2 * BB * DD];
__device__ float g_prsum[BB];
// CSR for f2e scatter->gather
__device__ int g_cnti[BB * EE];
__device__ int g_rowptr[BB * (EE + 1)];
__device__ int g_fill[BB * EE];
__device__ int g_fidx[BB * FF];

// ---------------- tensor-core GEMM core (3xTF32 for fp32 accuracy) ----------
#define TBM 128
#define TBN 128
#define TBK 32
#define TLD (TBK + 4)   // padded smem row stride (floats)

__device__ __forceinline__ void tf32split(float f, uint32_t& hi, uint32_t& lo) {
  asm("cvt.rna.tf32.f32 %0, %1;" : "=r"(hi) : "f"(f));
  float r = f - __uint_as_float(hi);
  asm("cvt.rna.tf32.f32 %0, %1;" : "=r"(lo) : "f"(r));
}

#define MMA_TF32(c, a, b)                                                  \
  asm volatile(                                                            \
      "mma.sync.aligned.m16n8k8.row.col.f32.tf32.tf32.f32 "                \
      "{%0,%1,%2,%3},{%4,%5,%6,%7},{%8,%9},{%0,%1,%2,%3};"                 \
      : "+f"((c)[0]), "+f"((c)[1]), "+f"((c)[2]), "+f"((c)[3])             \
      : "r"((a)[0]), "r"((a)[1]), "r"((a)[2]), "r"((a)[3]),                \
        "r"((b)[0]), "r"((b)[1]));

__device__ __forceinline__ void mma_tile(float acc[4][4][4],
                                         const float (*As)[TLD],
                                         const float (*Bs)[TLD], int wm,
                                         int wn, int g, int tig) {
#pragma unroll
  for (int ks = 0; ks < TBK; ks += 8) {
    uint32_t ahi[4][4], alo[4][4], bhi[4][2], blo[4][2];
#pragma unroll
    for (int mt = 0; mt < 4; mt++) {
      int m0 = wm + mt * 16;
      tf32split(As[m0 + g][ks + tig], ahi[mt][0], alo[mt][0]);
      tf32split(As[m0 + g + 8][ks + tig], ahi[mt][1], alo[mt][1]);
      tf32split(As[m0 + g][ks + tig + 4], ahi[mt][2], alo[mt][2]);
      tf32split(As[m0 + g + 8][ks + tig + 4], ahi[mt][3], alo[mt][3]);
    }
#pragma unroll
    for (int nt = 0; nt < 4; nt++) {
      int n0 = wn + nt * 8 + g;
      tf32split(Bs[n0][ks + tig], bhi[nt][0], blo[nt][0]);
      tf32split(Bs[n0][ks + tig + 4], bhi[nt][1], blo[nt][1]);
    }
#pragma unroll
    for (int mt = 0; mt < 4; mt++)
#pragma unroll
      for (int nt = 0; nt < 4; nt++) {
        MMA_TF32(acc[mt][nt], ahi[mt], blo[nt]);
        MMA_TF32(acc[mt][nt], alo[mt], bhi[nt]);
        MMA_TF32(acc[mt][nt], ahi[mt], bhi[nt]);
      }
  }
}

// ---------------- generic GEMM: C = act([C +] alpha*A@W^T + bias) ------------
// BIASMODE: 0 none, 1 bias[n], 2 bias[(m>>11)*N + n]
template <bool GATHER, bool ACCUM, bool RELU, int BIASMODE>
__global__ void __launch_bounds__(256) gemm_k(
    float* __restrict__ C, const float* __restrict__ A, int lda,
    const int* __restrict__ gidx, const float* __restrict__ W, int ldw,
    const float* __restrict__ bias, int M, int N, int K, float alpha) {
  __shared__ float As[TBM][TLD];
  __shared__ float Bs[TBN][TLD];
  const int bm = blockIdx.y * TBM, bn = blockIdx.x * TBN;
  const int tid = threadIdx.x;
  const int warp = tid >> 5, lane = tid & 31;
  const int g = lane >> 2, tig = lane & 3;
  const int wm = (warp >> 2) * 64, wn = (warp & 3) * 32;

  float acc[4][4][4];
#pragma unroll
  for (int i = 0; i < 4; i++)
#pragma unroll
    for (int j = 0; j < 4; j++)
#pragma unroll
      for (int c = 0; c < 4; c++) acc[i][j][c] = 0.f;

  for (int kk0 = 0; kk0 < K; kk0 += TBK) {
#pragma unroll
    for (int i = 0; i < 4; i++) {
      int idx = tid + i * 256;
      int row = idx >> 3, kq = idx & 7;
      int k = kk0 + kq * 4;
      float4 va = make_float4(0.f, 0.f, 0.f, 0.f);
      int m = bm + row;
      if (m < M) {
        long r = GATHER ? (long)gidx[m] : (long)m;
        const float* p = A + r * (long)lda + k;
        if (k + 3 < K) va = *(const float4*)p;
        else {
          if (k < K) va.x = p[0];
          if (k + 1 < K) va.y = p[1];
          if (k + 2 < K) va.z = p[2];
        }
      }
      *(float4*)&As[row][kq * 4] = va;
      float4 vb = make_float4(0.f, 0.f, 0.f, 0.f);
      int n = bn + row;
      if (n < N) {
        const float* p = W + (long)n * ldw + k;
        if (k + 3 < K) vb = *(const float4*)p;
        else {
          if (k < K) vb.x = p[0];
          if (k + 1 < K) vb.y = p[1];
          if (k + 2 < K) vb.z = p[2];
        }
      }
      *(float4*)&Bs[row][kq * 4] = vb;
    }
    __syncthreads();
    mma_tile(acc, As, Bs, wm, wn, g, tig);
    __syncthreads();
  }

#pragma unroll
  for (int mt = 0; mt < 4; mt++) {
#pragma unroll
    for (int nt = 0; nt < 4; nt++) {
#pragma unroll
      for (int half = 0; half < 2; half++) {
        int m = bm + wm + mt * 16 + g + half * 8;
        if (m >= M) continue;
#pragma unroll
        for (int cc = 0; cc < 2; cc++) {
          int n = bn + wn + nt * 8 + tig * 2 + cc;
          if (n >= N) continue;
          float v = alpha * acc[mt][nt][half * 2 + cc];
          if (BIASMODE == 1) v += bias[n];
          if (BIASMODE == 2) v += bias[(m >> 11) * N + n];
          long off = (long)m * N + n;
          if (ACCUM) v += C[off];
          if (RELU) v = fmaxf(v, 0.f);
          C[off] = v;
        }
      }
    }
  }
}

// ------------- dual-output GEMM: head = A@W1^T+b1 ; self = A@W2^T+b2 --------
__global__ void __launch_bounds__(256) gemm_dualout_k(
    float* __restrict__ C1, float* __restrict__ C2,
    const float* __restrict__ A, const float* __restrict__ W1,
    const float* __restrict__ W2, const float* __restrict__ b1,
    const float* __restrict__ b2, int M) {
  __shared__ float As[TBM][TLD];
  __shared__ float Bs[TBN][TLD];
  const int bm = blockIdx.y * TBM, bn = blockIdx.x * TBN;
  const int tid = threadIdx.x;
  const int warp = tid >> 5, lane = tid & 31;
  const int g = lane >> 2, tig = lane & 3;
  const int wm = (warp >> 2) * 64, wn = (warp & 3) * 32;

  float acc[4][4][4];
#pragma unroll
  for (int i = 0; i < 4; i++)
#pragma unroll
    for (int j = 0; j < 4; j++)
#pragma unroll
      for (int c = 0; c < 4; c++) acc[i][j][c] = 0.f;

  for (int kk0 = 0; kk0 < DD; kk0 += TBK) {
#pragma unroll
    for (int i = 0; i < 4; i++) {
      int idx = tid + i * 256;
      int row = idx >> 3, kq = idx & 7;
      int k = kk0 + kq * 4;
      *(float4*)&As[row][kq * 4] =
          *(const float4*)(A + (long)(bm + row) * DD + k);
      int n = bn + row;
      const float* Wp = (n < 256) ? (W1 + (long)n * DD) : (W2 + (long)(n - 256) * DD);
      *(float4*)&Bs[row][kq * 4] = *(const float4*)(Wp + k);
    }
    __syncthreads();
    mma_tile(acc, As, Bs, wm, wn, g, tig);
    __syncthreads();
  }

#pragma unroll
  for (int mt = 0; mt < 4; mt++)
#pragma unroll
    for (int nt = 0; nt < 4; nt++)
#pragma unroll
      for (int half = 0; half < 2; half++) {
        int m = bm + wm + mt * 16 + g + half * 8;
#pragma unroll
        for (int cc = 0; cc < 2; cc++) {
          int n = bn + wn + nt * 8 + tig * 2 + cc;
          float v = acc[mt][nt][half * 2 + cc];
          if (n < 256) C1[(long)m * DD + n] = v + b1[n];
          else C2[(long)m * DD + (n - 256)] = v + b2[n - 256];
        }
      }
}

// -------- dual-input GEMM: C = relu(A1@W1^T + sc2*A2@W2^T + biasBE) ---------
__global__ void __launch_bounds__(256) gemm_dualin_k(
    float* __restrict__ C, const float* __restrict__ A1,
    const float* __restrict__ A2, const float* __restrict__ W1,
    const float* __restrict__ W2, const float* __restrict__ biasBE,
    float sc2, int M) {
  __shared__ float As[TBM][TLD];
  __shared__ float Bs[TBN][TLD];
  const int bm = blockIdx.y * TBM, bn = blockIdx.x * TBN;
  const int tid = threadIdx.x;
  const int warp = tid >> 5, lane = tid & 31;
  const int g = lane >> 2, tig = lane & 3;
  const int wm = (warp >> 2) * 64, wn = (warp & 3) * 32;

  float acc[4][4][4];
#pragma unroll
  for (int i = 0; i < 4; i++)
#pragma unroll
    for (int j = 0; j < 4; j++)
#pragma unroll
      for (int c = 0; c < 4; c++) acc[i][j][c] = 0.f;

  for (int kk0 = 0; kk0 < 2 * DD; kk0 += TBK) {
    const bool second = (kk0 >= DD);
    const float* Asrc = second ? A2 : A1;
    const float* Wsrc = second ? W2 : W1;
    const int kb = second ? (kk0 - DD) : kk0;
    const float sc = second ? sc2 : 1.f;
#pragma unroll
    for (int i = 0; i < 4; i++) {
      int idx = tid + i * 256;
      int row = idx >> 3, kq = idx & 7;
      int k = kb + kq * 4;
      float4 va = *(const float4*)(Asrc + (long)(bm + row) * DD + k);
      va.x *= sc; va.y *= sc; va.z *= sc; va.w *= sc;
      *(float4*)&As[row][kq * 4] = va;
      *(float4*)&Bs[row][kq * 4] =
          *(const float4*)(Wsrc + (long)(bn + row) * 768 + k);
    }
    __syncthreads();
    mma_tile(acc, As, Bs, wm, wn, g, tig);
    __syncthreads();
  }

#pragma unroll
  for (int mt = 0; mt < 4; mt++)
#pragma unroll
    for (int nt = 0; nt < 4; nt++)
#pragma unroll
      for (int half = 0; half < 2; half++) {
        int m = bm + wm + mt * 16 + g + half * 8;
#pragma unroll
        for (int cc = 0; cc < 2; cc++) {
          int n = bn + wn + nt * 8 + tig * 2 + cc;
          float v = acc[mt][nt][half * 2 + cc] + biasBE[(m >> 11) * DD + n];
          C[(long)m * DD + n] = fmaxf(v, 0.f);
        }
      }
}

// ---------------- small kernels ----------------
__global__ void zero_k(float* p, int n) {
  int i = blockIdx.x * 256 + threadIdx.x;
  if (i < n) p[i] = 0.f;
}
__global__ void zeroi_k(int* p, int n) {
  int i = blockIdx.x * 256 + threadIdx.x;
  if (i < n) p[i] = 0;
}
__global__ void copy_k(float* d, const float* s, int n) {
  int i = blockIdx.x * 256 + threadIdx.x;
  if (i < n) d[i] = s[i];
}
__global__ void vadd_k(float* o, const float* a, const float* b, int n) {
  int i = blockIdx.x * 256 + threadIdx.x;
  if (i < n) o[i] = a[i] + b[i];
}
__global__ void transp_k(float* o, const float* in) {  // (1024,256)->(256,1024)
  int i = blockIdx.x * 256 + threadIdx.x;
  if (i >= 1024 * 256) return;
  int g = i >> 8, k = i & 255;
  o[k * 1024 + g] = in[i];
}
__global__ void qcopy_k(float* qnode, const float* qh) {
  int b = blockIdx.x, d = threadIdx.x;
  qnode[b * DD + d] = qh[(b * QQ + QQ - 1) * DD + d];
}

__global__ void __launch_bounds__(1024) lstm_k(const float* __restrict__ gx,
                                               const float* __restrict__ whhT,
                                               float* __restrict__ qh) {
  int b = blockIdx.x, g = threadIdx.x;
  __shared__ float hs[DD], cs[DD], zs[L4D];
  if (g < DD) { hs[g] = 0.f; cs[g] = 0.f; }
  __syncthreads();
  for (int t = 0; t < QQ; t++) {
    float acc = gx[(b * QQ + t) * L4D + g];
#pragma unroll 8
    for (int k = 0; k < DD; k++) acc += hs[k] * whhT[k * L4D + g];
    zs[g] = acc;
    __syncthreads();
    if (g < DD) {
      float zi = zs[g], zf = zs[DD + g], zg = zs[2 * DD + g], zo = zs[3 * DD + g];
      float cn = (1.f / (1.f + expf(-zf))) * cs[g] +
                 (1.f / (1.f + expf(-zi))) * tanhf(zg);
      float hn = (1.f / (1.f + expf(-zo))) * tanhf(cn);
      cs[g] = cn;
      hs[g] = hn;
      qh[(b * QQ + t) * DD + g] = hn;
    }
    __syncthreads();
  }
}

__global__ void wr_k(const float* __restrict__ s0, const int* __restrict__ qt,
                     float* __restrict__ Wr) {
  int idx = blockIdx.x * 256 + threadIdx.x;
  if (idx >= BB * NRELROWS) return;
  int b = idx / NRELROWS, r = idx - b * NRELROWS;
  float raw[QQ], lg[QQ];
  float mx = -1e30f;
  for (int q = 0; q < QQ; q++) {
    float v = s0[(b * QQ + q) * NRELROWS + r];
    raw[q] = v;
    lg[q] = v + ((qt[b * QQ + q] == NWORD) ? VERY_NEG : 0.f);
    mx = fmaxf(mx, lg[q]);
  }
  float se = 0.f;
  for (int q = 0; q < QQ; q++) { lg[q] = expf(lg[q] - mx); se += lg[q]; }
  float w = 0.f;
  for (int q = 0; q < QQ; q++) w += (lg[q] / se) * raw[q];
  Wr[idx] = w;
}

__global__ void rowmax_k(const float* Wr, const int* rel, float* maxb) {
  int b = blockIdx.x;
  __shared__ float red[256];
  float mx = -1e30f;
  for (int f = threadIdx.x; f < FF; f += 256)
    mx = fmaxf(mx, Wr[b * NRELROWS + rel[b * FF + f]]);
  red[threadIdx.x] = mx;
  __syncthreads();
  for (int s = 128; s > 0; s >>= 1) {
    if (threadIdx.x < s) red[threadIdx.x] = fmaxf(red[threadIdx.x], red[threadIdx.x + s]);
    __syncthreads();
  }
  if (!threadIdx.x) maxb[b] = red[0];
}

__global__ void wtilde_k(const float* Wr, const int* rel, const int* e2f,
                         const float* maxb, float* Wt, float* e2fs) {
  int i = blockIdx.x * 256 + threadIdx.x;
  if (i >= BB * FF) return;
  int b = i >> 13;
  float wt = expf(Wr[b * NRELROWS + rel[i]] - maxb[b]);
  Wt[i] = wt;
  atomicAdd(&e2fs[b * EE + e2f[i]], wt);
}

__global__ void clamp_k(float* p, int n) {
  int i = blockIdx.x * 256 + threadIdx.x;
  if (i < n) p[i] = fmaxf(p[i], VERY_SMALL);
}

// ---- CSR build (once; f2e_ent is layer-invariant) ----
__global__ void cnti_k(int* cnt, const int* f2e) {
  int i = blockIdx.x * 256 + threadIdx.x;
  if (i >= BB * FF) return;
  atomicAdd(&cnt[(i >> 13) * EE + f2e[i]], 1);
}

__global__ void scan_k(const int* __restrict__ cnt, int* __restrict__ rowptr,
                       float* __restrict__ cntf) {
  int b = blockIdx.x, t = threadIdx.x;
  __shared__ int part[256];
  __shared__ int partx[257];
  int loc[8];
  int s = 0;
  int base = b * EE + t * 8;
  for (int j = 0; j < 8; j++) { loc[j] = cnt[base + j]; s += loc[j]; }
  part[t] = s;
  __syncthreads();
  if (t == 0) {
    int a = 0;
    for (int i = 0; i < 256; i++) { partx[i] = a; a += part[i]; }
    partx[256] = a;
  }
  __syncthreads();
  int off = partx[t];
  for (int j = 0; j < 8; j++) {
    rowptr[b * (EE + 1) + t * 8 + j] = off;
    cntf[base + j] = (float)loc[j];
    off += loc[j];
  }
  if (t == 255) rowptr[b * (EE + 1) + EE] = off;
}

__global__ void fill_k(const int* __restrict__ f2e, const int* __restrict__ rowptr,
                       int* __restrict__ fill, int* __restrict__ fidx) {
  int i = blockIdx.x * 256 + threadIdx.x;
  if (i >= BB * FF) return;
  int b = i >> 13, f = i & (FF - 1);
  int e = f2e[i];
  int pos = rowptr[b * (EE + 1) + e] + atomicAdd(&fill[b * EE + e], 1);
  fidx[b * FF + pos] = f;
}

// ---- per-layer fact gather: Asc[b,e,:] = sum_f relu(fsl[rel]+head[esrc])*nrm;
//      prnew[b,e] = sum_f nrm.  No atomics, no pre-zero. ----
__global__ void __launch_bounds__(256) gather_k(
    const float* __restrict__ fsl, const float* __restrict__ head,
    const float* __restrict__ Wt, const float* __restrict__ pr,
    const float* __restrict__ e2fs, const int* __restrict__ rel,
    const int* __restrict__ e2f, const int* __restrict__ rowptr,
    const int* __restrict__ fidx, float* __restrict__ Asc,
    float* __restrict__ prnew) {
  int sub = threadIdx.x >> 6;        // 4 rows per block
  int lane = threadIdx.x & 63;       // 64 threads x float4 = 256 dims
  int be = blockIdx.x * 4 + sub;
  int b = be >> 11, e = be & (EE - 1);
  int beg = rowptr[b * (EE + 1) + e], end = rowptr[b * (EE + 1) + e + 1];
  float4 acc = make_float4(0.f, 0.f, 0.f, 0.f);
  float nsum = 0.f;
  for (int p = beg; p < end; p++) {
    int f = fidx[b * FF + p];
    int bf = (b << 13) + f;
    int esrc = e2f[bf];
    int r = rel[bf];
    float nrm = Wt[bf] * pr[b * EE + esrc] / e2fs[b * EE + esrc];
    nsum += nrm;
    float4 h = ((const float4*)(head + (long)(b * EE + esrc) * DD))[lane];
    float4 fv = ((const float4*)(fsl + (long)r * DD))[lane];
    acc.x += fmaxf(h.x + fv.x, 0.f) * nrm;
    acc.y += fmaxf(h.y + fv.y, 0.f) * nrm;
    acc.z += fmaxf(h.z + fv.z, 0.f) * nrm;
    acc.w += fmaxf(h.w + fv.w, 0.f) * nrm;
  }
  ((float4*)(Asc + (long)be * DD))[lane] = acc;
  if (lane == 0) prnew[be] = nsum;
}

__global__ void f2epre_k(float* eself, const float* cnt, const float* tb) {
  int i = blockIdx.x * 256 + threadIdx.x;
  if (i >= BB * EE * DD) return;
  eself[i] += cnt[i >> 8] * tb[i & 255];
}

__global__ void prupd_k(float* pr, const float* prnew, int n) {
  int i = blockIdx.x * 256 + threadIdx.x;
  if (i < n) pr[i] = 0.8f * prnew[i] + 0.2f * pr[i];
}

__global__ void prsum_k(const float* pr, float* prsum) {
  int b = blockIdx.x;
  __shared__ float red[256];
  float s = 0.f;
  for (int e = threadIdx.x; e < EE; e += 256) s += pr[b * EE + e];
  red[threadIdx.x] = s;
  __syncthreads();
  for (int st = 128; st > 0; st >>= 1) {
    if (threadIdx.x < st) red[threadIdx.x] += red[threadIdx.x + st];
    __syncthreads();
  }
  if (!threadIdx.x) prsum[b] = red[0];
}

__global__ void wsum_k(const float* __restrict__ pr, const float* __restrict__ le,
                       const float* __restrict__ f2e, float* __restrict__ sle,
                       float* __restrict__ sf2e) {
  int blk = blockIdx.x;
  int b = blk >> 5, ch = blk & 31;   // 32 chunks of 64 entities
  int d = threadIdx.x;
  float a = 0.f, c = 0.f;
  int e0 = ch * 64;
  for (int e = e0; e < e0 + 64; e++) {
    float w = pr[b * EE + e];
    a += w * le[(long)(b * EE + e) * DD + d];
    c += w * f2e[(long)(b * EE + e) * DD + d];
  }
  atomicAdd(&sle[b * DD + d], a);
  atomicAdd(&sf2e[b * DD + d], c);
}

// y[b,n] = bias[n] + sum_k x[b,k] * W[n*ldw + k]
__global__ void smallmv_k(const float* __restrict__ x, const float* __restrict__ W,
                          int ldw, const float* __restrict__ bias,
                          float* __restrict__ y, int K) {
  int b = blockIdx.x, n = threadIdx.x;
  const float* w = W + (long)n * ldw;
  const float* xb = x + b * K;
  float acc = bias ? bias[n] : 0.f;
  for (int k = 0; k < K; k++) acc += xb[k] * w[k];
  y[b * DD + n] = acc;
}

__global__ void qupd_k(const float* sle, const float* sf2e, const float* q2ev,
                       const float* prsum, const float* __restrict__ W,
                       const float* bias, float* qnode) {
  int b = blockIdx.x, n = threadIdx.x;
  const float* w = W + (long)n * 768;
  float ps = prsum[b];
  float acc = ps * bias[n];
  for (int k = 0; k < DD; k++) acc += sle[b * DD + k] * w[k];
  for (int k = 0; k < DD; k++) acc += ps * q2ev[b * DD + k] * w[DD + k];
  for (int k = 0; k < DD; k++) acc += 3.f * sf2e[b * DD + k] * w[2 * DD + k];
  qnode[b * DD + n] = acc;
}

__global__ void score_k(const float* __restrict__ le, const float* __restrict__ sw,
                        const float* __restrict__ sb, float* __restrict__ out) {
  int row = blockIdx.x * 8 + (threadIdx.x >> 5);
  int lane = threadIdx.x & 31;
  float acc = 0.f;
#pragma unroll
  for (int j = 0; j < 8; j++) {
    int k = lane + j * 32;
    acc += le[(long)row * DD + k] * sw[k];
  }
#pragma unroll
  for (int o = 16; o > 0; o >>= 1) acc += __shfl_down_sync(0xffffffffu, acc, o);
  if (!lane) out[row] = acc + sb[0];
}

// ---------------- host ----------------
extern "C" void kernel_launch(void* const* d_in, const int* in_sizes, int n_in,
                              void* d_out, int out_size) {
  const int* local_entity = (const int*)d_in[0];
  const float* q2e_adj = (const float*)d_in[1];
  const int* kb_fact_rel = (const int*)d_in[2];
  const int* query_text = (const int*)d_in[3];
  const int* e2f_ent = (const int*)d_in[5];
  const int* f2e_ent = (const int*)d_in[6];
  const float* word_emb = (const float*)d_in[7];
  const float* entity_emb = (const float*)d_in[8];
  const float* relation_emb = (const float*)d_in[9];
  const float* ent_w = (const float*)d_in[10];
  const float* ent_b = (const float*)d_in[11];
  const float* rel_w = (const float*)d_in[12];
  const float* rel_b = (const float*)d_in[13];
  const float* w_ih = (const float*)d_in[14];
  const float* w_hh = (const float*)d_in[15];
  const float* b_ih = (const float*)d_in[16];
  const float* b_hh = (const float*)d_in[17];
  const float* q2e_w = (const float*)d_in[18];
  const float* q2e_b = (const float*)d_in[19];
  const float* e2q_w = (const float*)d_in[20];
  const float* e2q_b = (const float*)d_in[21];
  const float* e2e_w = (const float*)d_in[22];
  const float* e2e_b = (const float*)d_in[23];
  const float* kb_head_w = (const float*)d_in[24];
  const float* kb_head_b = (const float*)d_in[25];
  const float* kb_tail_w = (const float*)d_in[26];
  const float* kb_tail_b = (const float*)d_in[27];
  const float* kb_self_w = (const float*)d_in[28];
  const float* kb_self_b = (const float*)d_in[29];
  const float* score_w = (const float*)d_in[30];
  const float* score_b = (const float*)d_in[31];
  float* out = (float*)d_out;
  (void)in_sizes; (void)n_in; (void)out_size;

  float *lr, *fs, *lstmb, *whhT, *gx, *qh, *qnode, *s0, *Wr, *maxb, *Wt, *e2fs;
  float *leA, *leB, *head, *eself, *Asc, *pr, *prnew, *cnt, *q2ev, *biasBE;
  float *sred, *prsum;
  int *cnti, *rowptr, *fill, *fidx;
  cudaGetSymbolAddress((void**)&lr, g_lr);
  cudaGetSymbolAddress((void**)&fs, g_fs);
  cudaGetSymbolAddress((void**)&lstmb, g_lstmb);
  cudaGetSymbolAddress((void**)&whhT, g_whhT);
  cudaGetSymbolAddress((void**)&gx, g_gx);
  cudaGetSymbolAddress((void**)&qh, g_qh);
  cudaGetSymbolAddress((void**)&qnode, g_qnode);
  cudaGetSymbolAddress((void**)&s0, g_s0);
  cudaGetSymbolAddress((void**)&Wr, g_Wr);
  cudaGetSymbolAddress((void**)&maxb, g_maxb);
  cudaGetSymbolAddress((void**)&Wt, g_Wt);
  cudaGetSymbolAddress((void**)&e2fs, g_e2fs);
  cudaGetSymbolAddress((void**)&leA, g_leA);
  cudaGetSymbolAddress((void**)&leB, g_leB);
  cudaGetSymbolAddress((void**)&head, g_head);
  cudaGetSymbolAddress((void**)&eself, g_eself);
  cudaGetSymbolAddress((void**)&Asc, g_Asc);
  cudaGetSymbolAddress((void**)&pr, g_pr);
  cudaGetSymbolAddress((void**)&prnew, g_prnew);
  cudaGetSymbolAddress((void**)&cnt, g_cnt);
  cudaGetSymbolAddress((void**)&q2ev, g_q2ev);
  cudaGetSymbolAddress((void**)&biasBE, g_biasBE);
  cudaGetSymbolAddress((void**)&sred, g_sred);
  cudaGetSymbolAddress((void**)&prsum, g_prsum);
  cudaGetSymbolAddress((void**)&cnti, g_cnti);
  cudaGetSymbolAddress((void**)&rowptr, g_rowptr);
  cudaGetSymbolAddress((void**)&fill, g_fill);
  cudaGetSymbolAddress((void**)&fidx, g_fidx);

  const int ME = BB * EE;            // 32768
  const int MED = BB * EE * DD;      // 8388608
  dim3 gBig(2, ME / TBM);
  dim3 gBig512(4, ME / TBM);
  dim3 gRel(2, (NRELROWS + TBM - 1) / TBM);

  // --- prologue; 5th launch (ncu-profiled) = the BIG entity GEMM ---
  vadd_k<<<4, 256>>>(lstmb, b_ih, b_hh, L4D);                       // 1
  transp_k<<<1024, 256>>>(whhT, w_hh);                              // 2
  gemm_k<false, false, false, 1><<<gRel, 256>>>(                    // 3
      lr, relation_emb, 600, nullptr, rel_w, 600, rel_b, NRELROWS, 256, 600, 1.f);
  zeroi_k<<<(ME + 255) / 256, 256>>>(cnti, ME);                     // 4
  gemm_k<true, false, false, 1><<<gBig, 256>>>(                     // 5 <- profiled
      leA, entity_emb, WDD, local_entity, ent_w, WDD, ent_b, ME, 256, WDD, 1.f);
  for (int l = 0; l < 3; l++)
    gemm_k<false, false, false, 1><<<gRel, 256>>>(
        fs + l * NRELROWS * DD, lr, 256, nullptr, kb_self_w + l * 65536, 256,
        kb_self_b + l * 256, NRELROWS, 256, 256, 1.f);
  gemm_k<true, false, false, 1><<<dim3(8, 3), 256>>>(
      gx, word_emb, WDD, query_text, w_ih, WDD, lstmb, BB * QQ, L4D, WDD, 1.f);
  lstm_k<<<BB, 1024>>>(gx, whhT, qh);
  qcopy_k<<<BB, 256>>>(qnode, qh);

  // --- CSR build for f2e gather ---
  zeroi_k<<<(ME + 255) / 256, 256>>>(fill, ME);
  cnti_k<<<(BB * FF) / 256, 256>>>(cnti, f2e_ent);
  scan_k<<<BB, 256>>>(cnti, rowptr, cnt);
  fill_k<<<(BB * FF) / 256, 256>>>(f2e_ent, rowptr, fill, fidx);

  // --- attention -> Wr -> W_tilde -> e2f_softmax ---
  gemm_k<false, false, false, 0><<<dim3(5, 3), 256>>>(
      s0, qh, 256, nullptr, lr, 256, nullptr, BB * QQ, NRELROWS, 256, 1.f / 16.f);
  wr_k<<<(BB * NRELROWS + 255) / 256, 256>>>(s0, query_text, Wr);
  rowmax_k<<<BB, 256>>>(Wr, kb_fact_rel, maxb);
  zero_k<<<(ME + 255) / 256, 256>>>(e2fs, ME);
  wtilde_k<<<(BB * FF) / 256, 256>>>(Wr, kb_fact_rel, e2f_ent, maxb, Wt, e2fs);
  clamp_k<<<(ME + 255) / 256, 256>>>(e2fs, ME);

  // --- pagerank init ---
  copy_k<<<(ME + 255) / 256, 256>>>(pr, q2e_adj, ME);

  float* leCur = leA;
  float* leNxt = leB;
  for (int l = 0; l < 3; l++) {
    const float* Wh = kb_head_w + l * 65536;
    const float* Ws = kb_self_w + l * 65536;
    const float* Wtl = kb_tail_w + l * 65536;
    const float* We2e = e2e_w + l * 256 * 768;
    const float* We2q = e2q_w + l * 256 * 768;

    smallmv_k<<<BB, 256>>>(qnode, q2e_w + l * 65536, 256, q2e_b + l * 256, q2ev, 256);
    gemm_dualout_k<<<gBig512, 256>>>(head, eself, leCur, Wh, Ws,
                                     kb_head_b + l * 256, kb_self_b + l * 256, ME);
    gather_k<<<ME / 4, 256>>>(fs + l * NRELROWS * DD, head, Wt, pr, e2fs,
                              kb_fact_rel, e2f_ent, rowptr, fidx, Asc, prnew);
    f2epre_k<<<(MED + 255) / 256, 256>>>(eself, cnt, kb_tail_b + l * 256);
    gemm_k<false, true, true, 0><<<gBig, 256>>>(
        eself, Asc, 256, nullptr, Wtl, 256, nullptr, ME, 256, 256, 1.f);
    prupd_k<<<(ME + 255) / 256, 256>>>(pr, prnew, ME);
    zero_k<<<(2 * BB * DD + 255) / 256, 256>>>(sred, 2 * BB * DD);
    prsum_k<<<BB, 256>>>(pr, prsum);
    wsum_k<<<BB * 32, 256>>>(pr, leCur, eself, sred, sred + BB * DD);
    qupd_k<<<BB, 256>>>(sred, sred + BB * DD, q2ev, prsum, We2q,
                        e2q_b + l * 256, qnode);
    smallmv_k<<<BB, 256>>>(q2ev, We2e + 256, 768, e2e_b + l * 256, biasBE, 256);
    gemm_dualin_k<<<gBig, 256>>>(leNxt, leCur, eself, We2e, We2e + 512, biasBE,
                                 3.f, ME);
    float* t = leCur; leCur = leNxt; leNxt = t;
  }

  score_k<<<ME / 8, 256>>>(leCur, score_w, score_b, out);
}

// round 8
// speedup vs baseline: 1.4745x; 1.0351x over previous
#include <cuda_runtime.h>
#include <math.h>
#include <stdint.h>

#define BB 16
#define EE 2048
#define FF 8192
#define QQ 20
#define DD 256
#define WDD 300
#define NRELROWS 601
#define L4D 1024
#define NWORD 50000

#define VERY_NEG -1e11f
#define VERY_SMALL 1e-10f

// ---------------- scratch (device globals; no runtime alloc) ----------------
__device__ float g_lr[NRELROWS * DD];
__device__ float g_fs[3 * NRELROWS * DD];
__device__ float g_lstmb[L4D];
__device__ float g_whhT[DD * L4D];
__device__ float g_gx[BB * QQ * L4D];
__device__ float g_qh[BB * QQ * DD];
__device__ float g_qnode[BB * DD];
__device__ float g_s0[BB * QQ * NRELROWS];
__device__ float g_Wr[BB * NRELROWS];
__device__ float g_maxb[BB];
__device__ float g_Wt[BB * FF];
__device__ float g_e2fs[BB * EE];
__device__ float g_leA[BB * EE * DD];
__device__ float g_leB[BB * EE * DD];
__device__ float g_head[BB * EE * DD];
__device__ float g_eself[BB * EE * DD];
__device__ float g_Asc[BB * EE * DD];
__device__ float g_pr[BB * EE];
__device__ float g_prnew[BB * EE];
__device__ float g_cnt[BB * EE];
__device__ float g_q2ev[BB * DD];
__device__ float g_biasBE[BB * DD];
__device__ float g_sred[2 * BB * DD];
__device__ float g_prsum[BB];
// CSR for f2e scatter->gather
__device__ int g_cnti[BB * EE];
__device__ int g_rowptr[BB * (EE + 1)];
__device__ int g_fill[BB * EE];
__device__ int g_fidx[BB * FF];

// ------- tensor-core GEMM core (3xTF32, hi/lo pre-split into smem) ----------
#define TBM 128
#define TBN 128
#define TBK 32
#define LD2 36   // float2 units per row; 36 mod 16 == 4 -> conflict-free
#define SMB (2 * TBM * LD2 * (int)sizeof(float2))   // 73728 B

__device__ __forceinline__ void tf32split(float f, uint32_t& hi, uint32_t& lo) {
  asm("cvt.rna.tf32.f32 %0, %1;" : "=r"(hi) : "f"(f));
  float r = f - __uint_as_float(hi);
  asm("cvt.rna.tf32.f32 %0, %1;" : "=r"(lo) : "f"(r));
}

__device__ __forceinline__ float2 sp2(float v) {
  uint32_t h, l;
  tf32split(v, h, l);
  return make_float2(__uint_as_float(h), __uint_as_float(l));
}

// split a float4 into two float4s of (hi,lo,hi,lo) and store at 16B-aligned dst
__device__ __forceinline__ void store_split4(float2* dst, float4 v) {
  float2 s0 = sp2(v.x), s1 = sp2(v.y), s2 = sp2(v.z), s3 = sp2(v.w);
  *(float4*)dst = make_float4(s0.x, s0.y, s1.x, s1.y);
  *(float4*)(dst + 2) = make_float4(s2.x, s2.y, s3.x, s3.y);
}

#define MMA_TF32(c, a, b)                                                  \
  asm volatile(                                                            \
      "mma.sync.aligned.m16n8k8.row.col.f32.tf32.tf32.f32 "                \
      "{%0,%1,%2,%3},{%4,%5,%6,%7},{%8,%9},{%0,%1,%2,%3};"                 \
      : "+f"((c)[0]), "+f"((c)[1]), "+f"((c)[2]), "+f"((c)[3])             \
      : "r"((a)[0]), "r"((a)[1]), "r"((a)[2]), "r"((a)[3]),                \
        "r"((b)[0]), "r"((b)[1]));

__device__ __forceinline__ void mma_tile2(float acc[4][4][4],
                                          const float2* __restrict__ As2,
                                          const float2* __restrict__ Bs2,
                                          int wm, int wn, int g, int tig) {
#pragma unroll
  for (int ks = 0; ks < TBK; ks += 8) {
    uint32_t ahi[4][4], alo[4][4], bhi[4][2], blo[4][2];
#pragma unroll
    for (int nt = 0; nt < 4; nt++) {
      int n0 = wn + nt * 8 + g;
      float2 b0 = Bs2[n0 * LD2 + ks + tig];
      float2 b1 = Bs2[n0 * LD2 + ks + tig + 4];
      bhi[nt][0] = __float_as_uint(b0.x); blo[nt][0] = __float_as_uint(b0.y);
      bhi[nt][1] = __float_as_uint(b1.x); blo[nt][1] = __float_as_uint(b1.y);
    }
#pragma unroll
    for (int mt = 0; mt < 4; mt++) {
      int m0 = wm + mt * 16;
      float2 a0 = As2[(m0 + g) * LD2 + ks + tig];
      float2 a1 = As2[(m0 + g + 8) * LD2 + ks + tig];
      float2 a2 = As2[(m0 + g) * LD2 + ks + tig + 4];
      float2 a3 = As2[(m0 + g + 8) * LD2 + ks + tig + 4];
      ahi[mt][0] = __float_as_uint(a0.x); alo[mt][0] = __float_as_uint(a0.y);
      ahi[mt][1] = __float_as_uint(a1.x); alo[mt][1] = __float_as_uint(a1.y);
      ahi[mt][2] = __float_as_uint(a2.x); alo[mt][2] = __float_as_uint(a2.y);
      ahi[mt][3] = __float_as_uint(a3.x); alo[mt][3] = __float_as_uint(a3.y);
    }
#pragma unroll
    for (int mt = 0; mt < 4; mt++)
#pragma unroll
      for (int nt = 0; nt < 4; nt++) {
        MMA_TF32(acc[mt][nt], ahi[mt], blo[nt]);
        MMA_TF32(acc[mt][nt], alo[mt], bhi[nt]);
        MMA_TF32(acc[mt][nt], ahi[mt], bhi[nt]);
      }
  }
}

// ---------------- generic GEMM: C = act([C +] alpha*A@W^T + bias) ------------
// BIASMODE: 0 none, 1 bias[n], 2 bias[(m>>11)*N+n], 3 rowscale[m]*bias[n]
template <bool GATHER, bool ACCUM, bool RELU, int BIASMODE>
__global__ void __launch_bounds__(256, 2) gemm_k(
    float* __restrict__ C, const float* __restrict__ A, int lda,
    const int* __restrict__ gidx, const float* __restrict__ W, int ldw,
    const float* __restrict__ bias, const float* __restrict__ rowscale,
    int M, int N, int K, float alpha) {
  extern __shared__ float2 dynsm[];
  float2* As2 = dynsm;
  float2* Bs2 = dynsm + TBM * LD2;
  const int bm = blockIdx.y * TBM, bn = blockIdx.x * TBN;
  const int tid = threadIdx.x;
  const int warp = tid >> 5, lane = tid & 31;
  const int g = lane >> 2, tig = lane & 3;
  const int wm = (warp >> 2) * 64, wn = (warp & 3) * 32;

  float acc[4][4][4];
#pragma unroll
  for (int i = 0; i < 4; i++)
#pragma unroll
    for (int j = 0; j < 4; j++)
#pragma unroll
      for (int c = 0; c < 4; c++) acc[i][j][c] = 0.f;

  for (int kk0 = 0; kk0 < K; kk0 += TBK) {
#pragma unroll
    for (int i = 0; i < 4; i++) {
      int idx = tid + i * 256;
      int row = idx >> 3, kq = idx & 7;
      int k = kk0 + kq * 4;
      float4 va = make_float4(0.f, 0.f, 0.f, 0.f);
      int m = bm + row;
      if (m < M) {
        long r = GATHER ? (long)gidx[m] : (long)m;
        const float* p = A + r * (long)lda + k;
        if (k + 3 < K) va = *(const float4*)p;
        else {
          if (k < K) va.x = p[0];
          if (k + 1 < K) va.y = p[1];
          if (k + 2 < K) va.z = p[2];
        }
      }
      store_split4(As2 + row * LD2 + kq * 4, va);
      float4 vb = make_float4(0.f, 0.f, 0.f, 0.f);
      int n = bn + row;
      if (n < N) {
        const float* p = W + (long)n * ldw + k;
        if (k + 3 < K) vb = *(const float4*)p;
        else {
          if (k < K) vb.x = p[0];
          if (k + 1 < K) vb.y = p[1];
          if (k + 2 < K) vb.z = p[2];
        }
      }
      store_split4(Bs2 + row * LD2 + kq * 4, vb);
    }
    __syncthreads();
    mma_tile2(acc, As2, Bs2, wm, wn, g, tig);
    __syncthreads();
  }

#pragma unroll
  for (int mt = 0; mt < 4; mt++) {
#pragma unroll
    for (int nt = 0; nt < 4; nt++) {
#pragma unroll
      for (int half = 0; half < 2; half++) {
        int m = bm + wm + mt * 16 + g + half * 8;
        if (m >= M) continue;
#pragma unroll
        for (int cc = 0; cc < 2; cc++) {
          int n = bn + wn + nt * 8 + tig * 2 + cc;
          if (n >= N) continue;
          float v = alpha * acc[mt][nt][half * 2 + cc];
          if (BIASMODE == 1) v += bias[n];
          if (BIASMODE == 2) v += bias[(m >> 11) * N + n];
          if (BIASMODE == 3) v += rowscale[m] * bias[n];
          long off = (long)m * N + n;
          if (ACCUM) v += C[off];
          if (RELU) v = fmaxf(v, 0.f);
          C[off] = v;
        }
      }
    }
  }
}

// ------------- dual-output GEMM: head = A@W1^T+b1 ; self = A@W2^T+b2 --------
__global__ void __launch_bounds__(256, 2) gemm_dualout_k(
    float* __restrict__ C1, float* __restrict__ C2,
    const float* __restrict__ A, const float* __restrict__ W1,
    const float* __restrict__ W2, const float* __restrict__ b1,
    const float* __restrict__ b2, int M) {
  extern __shared__ float2 dynsm[];
  float2* As2 = dynsm;
  float2* Bs2 = dynsm + TBM * LD2;
  const int bm = blockIdx.y * TBM, bn = blockIdx.x * TBN;
  const int tid = threadIdx.x;
  const int warp = tid >> 5, lane = tid & 31;
  const int g = lane >> 2, tig = lane & 3;
  const int wm = (warp >> 2) * 64, wn = (warp & 3) * 32;

  float acc[4][4][4];
#pragma unroll
  for (int i = 0; i < 4; i++)
#pragma unroll
    for (int j = 0; j < 4; j++)
#pragma unroll
      for (int c = 0; c < 4; c++) acc[i][j][c] = 0.f;

  for (int kk0 = 0; kk0 < DD; kk0 += TBK) {
#pragma unroll
    for (int i = 0; i < 4; i++) {
      int idx = tid + i * 256;
      int row = idx >> 3, kq = idx & 7;
      int k = kk0 + kq * 4;
      store_split4(As2 + row * LD2 + kq * 4,
                   *(const float4*)(A + (long)(bm + row) * DD + k));
      int n = bn + row;
      const float* Wp = (n < 256) ? (W1 + (long)n * DD) : (W2 + (long)(n - 256) * DD);
      store_split4(Bs2 + row * LD2 + kq * 4, *(const float4*)(Wp + k));
    }
    __syncthreads();
    mma_tile2(acc, As2, Bs2, wm, wn, g, tig);
    __syncthreads();
  }

#pragma unroll
  for (int mt = 0; mt < 4; mt++)
#pragma unroll
    for (int nt = 0; nt < 4; nt++)
#pragma unroll
      for (int half = 0; half < 2; half++) {
        int m = bm + wm + mt * 16 + g + half * 8;
#pragma unroll
        for (int cc = 0; cc < 2; cc++) {
          int n = bn + wn + nt * 8 + tig * 2 + cc;
          float v = acc[mt][nt][half * 2 + cc];
          if (n < 256) C1[(long)m * DD + n] = v + b1[n];
          else C2[(long)m * DD + (n - 256)] = v + b2[n - 256];
        }
      }
}

// -------- dual-input GEMM: C = relu(A1@W1^T + sc2*A2@W2^T + biasBE) ---------
__global__ void __launch_bounds__(256, 2) gemm_dualin_k(
    float* __restrict__ C, const float* __restrict__ A1,
    const float* __restrict__ A2, const float* __restrict__ W1,
    const float* __restrict__ W2, const float* __restrict__ biasBE,
    float sc2, int M) {
  extern __shared__ float2 dynsm[];
  float2* As2 = dynsm;
  float2* Bs2 = dynsm + TBM * LD2;
  const int bm = blockIdx.y * TBM, bn = blockIdx.x * TBN;
  const int tid = threadIdx.x;
  const int warp = tid >> 5, lane = tid & 31;
  const int g = lane >> 2, tig = lane & 3;
  const int wm = (warp >> 2) * 64, wn = (warp & 3) * 32;

  float acc[4][4][4];
#pragma unroll
  for (int i = 0; i < 4; i++)
#pragma unroll
    for (int j = 0; j < 4; j++)
#pragma unroll
      for (int c = 0; c < 4; c++) acc[i][j][c] = 0.f;

  for (int kk0 = 0; kk0 < 2 * DD; kk0 += TBK) {
    const bool second = (kk0 >= DD);
    const float* Asrc = second ? A2 : A1;
    const float* Wsrc = second ? W2 : W1;
    const int kb = second ? (kk0 - DD) : kk0;
    const float sc = second ? sc2 : 1.f;
#pragma unroll
    for (int i = 0; i < 4; i++) {
      int idx = tid + i * 256;
      int row = idx >> 3, kq = idx & 7;
      int k = kb + kq * 4;
      float4 va = *(const float4*)(Asrc + (long)(bm + row) * DD + k);
      va.x *= sc; va.y *= sc; va.z *= sc; va.w *= sc;
      store_split4(As2 + row * LD2 + kq * 4, va);
      store_split4(Bs2 + row * LD2 + kq * 4,
                   *(const float4*)(Wsrc + (long)(bn + row) * 768 + k));
    }
    __syncthreads();
    mma_tile2(acc, As2, Bs2, wm, wn, g, tig);
    __syncthreads();
  }

#pragma unroll
  for (int mt = 0; mt < 4; mt++)
#pragma unroll
    for (int nt = 0; nt < 4; nt++)
#pragma unroll
      for (int half = 0; half < 2; half++) {
        int m = bm + wm + mt * 16 + g + half * 8;
#pragma unroll
        for (int cc = 0; cc < 2; cc++) {
          int n = bn + wn + nt * 8 + tig * 2 + cc;
          float v = acc[mt][nt][half * 2 + cc] + biasBE[(m >> 11) * DD + n];
          C[(long)m * DD + n] = fmaxf(v, 0.f);
        }
      }
}

// ---------------- small kernels ----------------
__global__ void zero_k(float* p, int n) {
  int i = blockIdx.x * 256 + threadIdx.x;
  if (i < n) p[i] = 0.f;
}
__global__ void zeroi_k(int* p, int n) {
  int i = blockIdx.x * 256 + threadIdx.x;
  if (i < n) p[i] = 0;
}
__global__ void copy_k(float* d, const float* s, int n) {
  int i = blockIdx.x * 256 + threadIdx.x;
  if (i < n) d[i] = s[i];
}
__global__ void vadd_k(float* o, const float* a, const float* b, int n) {
  int i = blockIdx.x * 256 + threadIdx.x;
  if (i < n) o[i] = a[i] + b[i];
}
__global__ void transp_k(float* o, const float* in) {  // (1024,256)->(256,1024)
  int i = blockIdx.x * 256 + threadIdx.x;
  if (i >= 1024 * 256) return;
  int g = i >> 8, k = i & 255;
  o[k * 1024 + g] = in[i];
}
__global__ void qcopy_k(float* qnode, const float* qh) {
  int b = blockIdx.x, d = threadIdx.x;
  qnode[b * DD + d] = qh[(b * QQ + QQ - 1) * DD + d];
}

__global__ void __launch_bounds__(1024) lstm_k(const float* __restrict__ gx,
                                               const float* __restrict__ whhT,
                                               float* __restrict__ qh) {
  int b = blockIdx.x, g = threadIdx.x;
  __shared__ float hs[DD], cs[DD], zs[L4D];
  if (g < DD) { hs[g] = 0.f; cs[g] = 0.f; }
  __syncthreads();
  for (int t = 0; t < QQ; t++) {
    float acc = gx[(b * QQ + t) * L4D + g];
#pragma unroll 8
    for (int k = 0; k < DD; k++) acc += hs[k] * whhT[k * L4D + g];
    zs[g] = acc;
    __syncthreads();
    if (g < DD) {
      float zi = zs[g], zf = zs[DD + g], zg = zs[2 * DD + g], zo = zs[3 * DD + g];
      float cn = (1.f / (1.f + expf(-zf))) * cs[g] +
                 (1.f / (1.f + expf(-zi))) * tanhf(zg);
      float hn = (1.f / (1.f + expf(-zo))) * tanhf(cn);
      cs[g] = cn;
      hs[g] = hn;
      qh[(b * QQ + t) * DD + g] = hn;
    }
    __syncthreads();
  }
}

__global__ void wr_k(const float* __restrict__ s0, const int* __restrict__ qt,
                     float* __restrict__ Wr) {
  int idx = blockIdx.x * 256 + threadIdx.x;
  if (idx >= BB * NRELROWS) return;
  int b = idx / NRELROWS, r = idx - b * NRELROWS;
  float raw[QQ], lg[QQ];
  float mx = -1e30f;
  for (int q = 0; q < QQ; q++) {
    float v = s0[(b * QQ + q) * NRELROWS + r];
    raw[q] = v;
    lg[q] = v + ((qt[b * QQ + q] == NWORD) ? VERY_NEG : 0.f);
    mx = fmaxf(mx, lg[q]);
  }
  float se = 0.f;
  for (int q = 0; q < QQ; q++) { lg[q] = expf(lg[q] - mx); se += lg[q]; }
  float w = 0.f;
  for (int q = 0; q < QQ; q++) w += (lg[q] / se) * raw[q];
  Wr[idx] = w;
}

__global__ void rowmax_k(const float* Wr, const int* rel, float* maxb) {
  int b = blockIdx.x;
  __shared__ float red[256];
  float mx = -1e30f;
  for (int f = threadIdx.x; f < FF; f += 256)
    mx = fmaxf(mx, Wr[b * NRELROWS + rel[b * FF + f]]);
  red[threadIdx.x] = mx;
  __syncthreads();
  for (int s = 128; s > 0; s >>= 1) {
    if (threadIdx.x < s) red[threadIdx.x] = fmaxf(red[threadIdx.x], red[threadIdx.x + s]);
    __syncthreads();
  }
  if (!threadIdx.x) maxb[b] = red[0];
}

__global__ void wtilde_k(const float* Wr, const int* rel, const int* e2f,
                         const float* maxb, float* Wt, float* e2fs) {
  int i = blockIdx.x * 256 + threadIdx.x;
  if (i >= BB * FF) return;
  int b = i >> 13;
  float wt = expf(Wr[b * NRELROWS + rel[i]] - maxb[b]);
  Wt[i] = wt;
  atomicAdd(&e2fs[b * EE + e2f[i]], wt);
}

__global__ void clamp_k(float* p, int n) {
  int i = blockIdx.x * 256 + threadIdx.x;
  if (i < n) p[i] = fmaxf(p[i], VERY_SMALL);
}

// ---- CSR build (once; f2e_ent is layer-invariant) ----
__global__ void cnti_k(int* cnt, const int* f2e) {
  int i = blockIdx.x * 256 + threadIdx.x;
  if (i >= BB * FF) return;
  atomicAdd(&cnt[(i >> 13) * EE + f2e[i]], 1);
}

__global__ void scan_k(const int* __restrict__ cnt, int* __restrict__ rowptr,
                       float* __restrict__ cntf) {
  int b = blockIdx.x, t = threadIdx.x;
  __shared__ int part[256];
  __shared__ int partx[257];
  int loc[8];
  int s = 0;
  int base = b * EE + t * 8;
  for (int j = 0; j < 8; j++) { loc[j] = cnt[base + j]; s += loc[j]; }
  part[t] = s;
  __syncthreads();
  if (t == 0) {
    int a = 0;
    for (int i = 0; i < 256; i++) { partx[i] = a; a += part[i]; }
    partx[256] = a;
  }
  __syncthreads();
  int off = partx[t];
  for (int j = 0; j < 8; j++) {
    rowptr[b * (EE + 1) + t * 8 + j] = off;
    cntf[base + j] = (float)loc[j];
    off += loc[j];
  }
  if (t == 255) rowptr[b * (EE + 1) + EE] = off;
}

__global__ void fill_k(const int* __restrict__ f2e, const int* __restrict__ rowptr,
                       int* __restrict__ fill, int* __restrict__ fidx) {
  int i = blockIdx.x * 256 + threadIdx.x;
  if (i >= BB * FF) return;
  int b = i >> 13, f = i & (FF - 1);
  int e = f2e[i];
  int pos = rowptr[b * (EE + 1) + e] + atomicAdd(&fill[b * EE + e], 1);
  fidx[b * FF + pos] = f;
}

// ---- per-layer fact gather ----
__global__ void __launch_bounds__(256) gather_k(
    const float* __restrict__ fsl, const float* __restrict__ head,
    const float* __restrict__ Wt, const float* __restrict__ pr,
    const float* __restrict__ e2fs, const int* __restrict__ rel,
    const int* __restrict__ e2f, const int* __restrict__ rowptr,
    const int* __restrict__ fidx, float* __restrict__ Asc,
    float* __restrict__ prnew) {
  int sub = threadIdx.x >> 6;
  int lane = threadIdx.x & 63;
  int be = blockIdx.x * 4 + sub;
  int b = be >> 11, e = be & (EE - 1);
  int beg = rowptr[b * (EE + 1) + e], end = rowptr[b * (EE + 1) + e + 1];
  float4 acc = make_float4(0.f, 0.f, 0.f, 0.f);
  float nsum = 0.f;
  for (int p = beg; p < end; p++) {
    int f = fidx[b * FF + p];
    int bf = (b << 13) + f;
    int esrc = e2f[bf];
    int r = rel[bf];
    float nrm = Wt[bf] * pr[b * EE + esrc] / e2fs[b * EE + esrc];
    nsum += nrm;
    float4 h = ((const float4*)(head + (long)(b * EE + esrc) * DD))[lane];
    float4 fv = ((const float4*)(fsl + (long)r * DD))[lane];
    acc.x += fmaxf(h.x + fv.x, 0.f) * nrm;
    acc.y += fmaxf(h.y + fv.y, 0.f) * nrm;
    acc.z += fmaxf(h.z + fv.z, 0.f) * nrm;
    acc.w += fmaxf(h.w + fv.w, 0.f) * nrm;
  }
  ((float4*)(Asc + (long)be * DD))[lane] = acc;
  if (lane == 0) prnew[be] = nsum;
}

__global__ void prupd_k(float* pr, const float* prnew, int n) {
  int i = blockIdx.x * 256 + threadIdx.x;
  if (i < n) pr[i] = 0.8f * prnew[i] + 0.2f * pr[i];
}

__global__ void prsum_k(const float* pr, float* prsum) {
  int b = blockIdx.x;
  __shared__ float red[256];
  float s = 0.f;
  for (int e = threadIdx.x; e < EE; e += 256) s += pr[b * EE + e];
  red[threadIdx.x] = s;
  __syncthreads();
  for (int st = 128; st > 0; st >>= 1) {
    if (threadIdx.x < st) red[threadIdx.x] += red[threadIdx.x + st];
    __syncthreads();
  }
  if (!threadIdx.x) prsum[b] = red[0];
}

__global__ void wsum_k(const float* __restrict__ pr, const float* __restrict__ le,
                       const float* __restrict__ f2e, float* __restrict__ sle,
                       float* __restrict__ sf2e) {
  int blk = blockIdx.x;
  int b = blk >> 5, ch = blk & 31;
  int d = threadIdx.x;
  float a = 0.f, c = 0.f;
  int e0 = ch * 64;
  for (int e = e0; e < e0 + 64; e++) {
    float w = pr[b * EE + e];
    a += w * le[(long)(b * EE + e) * DD + d];
    c += w * f2e[(long)(b * EE + e) * DD + d];
  }
  atomicAdd(&sle[b * DD + d], a);
  atomicAdd(&sf2e[b * DD + d], c);
}

__global__ void smallmv_k(const float* __restrict__ x, const float* __restrict__ W,
                          int ldw, const float* __restrict__ bias,
                          float* __restrict__ y, int K) {
  int b = blockIdx.x, n = threadIdx.x;
  const float* w = W + (long)n * ldw;
  const float* xb = x + b * K;
  float acc = bias ? bias[n] : 0.f;
  for (int k = 0; k < K; k++) acc += xb[k] * w[k];
  y[b * DD + n] = acc;
}

__global__ void qupd_k(const float* sle, const float* sf2e, const float* q2ev,
                       const float* prsum, const float* __restrict__ W,
                       const float* bias, float* qnode) {
  int b = blockIdx.x, n = threadIdx.x;
  const float* w = W + (long)n * 768;
  float ps = prsum[b];
  float acc = ps * bias[n];
  for (int k = 0; k < DD; k++) acc += sle[b * DD + k] * w[k];
  for (int k = 0; k < DD; k++) acc += ps * q2ev[b * DD + k] * w[DD + k];
  for (int k = 0; k < DD; k++) acc += 3.f * sf2e[b * DD + k] * w[2 * DD + k];
  qnode[b * DD + n] = acc;
}

__global__ void score_k(const float* __restrict__ le, const float* __restrict__ sw,
                        const float* __restrict__ sb, float* __restrict__ out) {
  int row = blockIdx.x * 8 + (threadIdx.x >> 5);
  int lane = threadIdx.x & 31;
  float acc = 0.f;
#pragma unroll
  for (int j = 0; j < 8; j++) {
    int k = lane + j * 32;
    acc += le[(long)row * DD + k] * sw[k];
  }
#pragma unroll
  for (int o = 16; o > 0; o >>= 1) acc += __shfl_down_sync(0xffffffffu, acc, o);
  if (!lane) out[row] = acc + sb[0];
}

// ---------------- host ----------------
extern "C" void kernel_launch(void* const* d_in, const int* in_sizes, int n_in,
                              void* d_out, int out_size) {
  const int* local_entity = (const int*)d_in[0];
  const float* q2e_adj = (const float*)d_in[1];
  const int* kb_fact_rel = (const int*)d_in[2];
  const int* query_text = (const int*)d_in[3];
  const int* e2f_ent = (const int*)d_in[5];
  const int* f2e_ent = (const int*)d_in[6];
  const float* word_emb = (const float*)d_in[7];
  const float* entity_emb = (const float*)d_in[8];
  const float* relation_emb = (const float*)d_in[9];
  const float* ent_w = (const float*)d_in[10];
  const float* ent_b = (const float*)d_in[11];
  const float* rel_w = (const float*)d_in[12];
  const float* rel_b = (const float*)d_in[13];
  const float* w_ih = (const float*)d_in[14];
  const float* w_hh = (const float*)d_in[15];
  const float* b_ih = (const float*)d_in[16];
  const float* b_hh = (const float*)d_in[17];
  const float* q2e_w = (const float*)d_in[18];
  const float* q2e_b = (const float*)d_in[19];
  const float* e2q_w = (const float*)d_in[20];
  const float* e2q_b = (const float*)d_in[21];
  const float* e2e_w = (const float*)d_in[22];
  const float* e2e_b = (const float*)d_in[23];
  const float* kb_head_w = (const float*)d_in[24];
  const float* kb_head_b = (const float*)d_in[25];
  const float* kb_tail_w = (const float*)d_in[26];
  const float* kb_tail_b = (const float*)d_in[27];
  const float* kb_self_w = (const float*)d_in[28];
  const float* kb_self_b = (const float*)d_in[29];
  const float* score_w = (const float*)d_in[30];
  const float* score_b = (const float*)d_in[31];
  float* out = (float*)d_out;
  (void)in_sizes; (void)n_in; (void)out_size;

  // raise dynamic smem limits (idempotent; not a stream op)
  cudaFuncSetAttribute(gemm_k<false, false, false, 1>,
                       cudaFuncAttributeMaxDynamicSharedMemorySize, SMB);
  cudaFuncSetAttribute(gemm_k<true, false, false, 1>,
                       cudaFuncAttributeMaxDynamicSharedMemorySize, SMB);
  cudaFuncSetAttribute(gemm_k<false, false, false, 0>,
                       cudaFuncAttributeMaxDynamicSharedMemorySize, SMB);
  cudaFuncSetAttribute(gemm_k<false, true, true, 3>,
                       cudaFuncAttributeMaxDynamicSharedMemorySize, SMB);
  cudaFuncSetAttribute(gemm_dualout_k,
                       cudaFuncAttributeMaxDynamicSharedMemorySize, SMB);
  cudaFuncSetAttribute(gemm_dualin_k,
                       cudaFuncAttributeMaxDynamicSharedMemorySize, SMB);

  float *lr, *fs, *lstmb, *whhT, *gx, *qh, *qnode, *s0, *Wr, *maxb, *Wt, *e2fs;
  float *leA, *leB, *head, *eself, *Asc, *pr, *prnew, *cnt, *q2ev, *biasBE;
  float *sred, *prsum;
  int *cnti, *rowptr, *fill, *fidx;
  cudaGetSymbolAddress((void**)&lr, g_lr);
  cudaGetSymbolAddress((void**)&fs, g_fs);
  cudaGetSymbolAddress((void**)&lstmb, g_lstmb);
  cudaGetSymbolAddress((void**)&whhT, g_whhT);
  cudaGetSymbolAddress((void**)&gx, g_gx);
  cudaGetSymbolAddress((void**)&qh, g_qh);
  cudaGetSymbolAddress((void**)&qnode, g_qnode);
  cudaGetSymbolAddress((void**)&s0, g_s0);
  cudaGetSymbolAddress((void**)&Wr, g_Wr);
  cudaGetSymbolAddress((void**)&maxb, g_maxb);
  cudaGetSymbolAddress((void**)&Wt, g_Wt);
  cudaGetSymbolAddress((void**)&e2fs, g_e2fs);
  cudaGetSymbolAddress((void**)&leA, g_leA);
  cudaGetSymbolAddress((void**)&leB, g_leB);
  cudaGetSymbolAddress((void**)&head, g_head);
  cudaGetSymbolAddress((void**)&eself, g_eself);
  cudaGetSymbolAddress((void**)&Asc, g_Asc);
  cudaGetSymbolAddress((void**)&pr, g_pr);
  cudaGetSymbolAddress((void**)&prnew, g_prnew);
  cudaGetSymbolAddress((void**)&cnt, g_cnt);
  cudaGetSymbolAddress((void**)&q2ev, g_q2ev);
  cudaGetSymbolAddress((void**)&biasBE, g_biasBE);
  cudaGetSymbolAddress((void**)&sred, g_sred);
  cudaGetSymbolAddress((void**)&prsum, g_prsum);
  cudaGetSymbolAddress((void**)&cnti, g_cnti);
  cudaGetSymbolAddress((void**)&rowptr, g_rowptr);
  cudaGetSymbolAddress((void**)&fill, g_fill);
  cudaGetSymbolAddress((void**)&fidx, g_fidx);

  const int ME = BB * EE;            // 32768
  dim3 gBig(2, ME / TBM);
  dim3 gBig512(4, ME / TBM);
  dim3 gRel(2, (NRELROWS + TBM - 1) / TBM);

  // --- prologue; 4th launch (ncu-profiled) = the BIG entity GEMM ---
  vadd_k<<<4, 256>>>(lstmb, b_ih, b_hh, L4D);                       // 1
  transp_k<<<1024, 256>>>(whhT, w_hh);                              // 2
  gemm_k<false, false, false, 1><<<gRel, 256, SMB>>>(               // 3
      lr, relation_emb, 600, nullptr, rel_w, 600, rel_b, nullptr,
      NRELROWS, 256, 600, 1.f);
  gemm_k<true, false, false, 1><<<gBig, 256, SMB>>>(                // 4 <- profiled
      leA, entity_emb, WDD, local_entity, ent_w, WDD, ent_b, nullptr,
      ME, 256, WDD, 1.f);
  for (int l = 0; l < 3; l++)
    gemm_k<false, false, false, 1><<<gRel, 256, SMB>>>(
        fs + l * NRELROWS * DD, lr, 256, nullptr, kb_self_w + l * 65536, 256,
        kb_self_b + l * 256, nullptr, NRELROWS, 256, 256, 1.f);
  gemm_k<true, false, false, 1><<<dim3(8, 3), 256, SMB>>>(
      gx, word_emb, WDD, query_text, w_ih, WDD, lstmb, nullptr,
      BB * QQ, L4D, WDD, 1.f);
  lstm_k<<<BB, 1024>>>(gx, whhT, qh);
  qcopy_k<<<BB, 256>>>(qnode, qh);

  // --- CSR build for f2e gather ---
  zeroi_k<<<(ME + 255) / 256, 256>>>(cnti, ME);
  zeroi_k<<<(ME + 255) / 256, 256>>>(fill, ME);
  cnti_k<<<(BB * FF) / 256, 256>>>(cnti, f2e_ent);
  scan_k<<<BB, 256>>>(cnti, rowptr, cnt);
  fill_k<<<(BB * FF) / 256, 256>>>(f2e_ent, rowptr, fill, fidx);

  // --- attention -> Wr -> W_tilde -> e2f_softmax ---
  gemm_k<false, false, false, 0><<<dim3(5, 3), 256, SMB>>>(
      s0, qh, 256, nullptr, lr, 256, nullptr, nullptr,
      BB * QQ, NRELROWS, 256, 1.f / 16.f);
  wr_k<<<(BB * NRELROWS + 255) / 256, 256>>>(s0, query_text, Wr);
  rowmax_k<<<BB, 256>>>(Wr, kb_fact_rel, maxb);
  zero_k<<<(ME + 255) / 256, 256>>>(e2fs, ME);
  wtilde_k<<<(BB * FF) / 256, 256>>>(Wr, kb_fact_rel, e2f_ent, maxb, Wt, e2fs);
  clamp_k<<<(ME + 255) / 256, 256>>>(e2fs, ME);

  // --- pagerank init ---
  copy_k<<<(ME + 255) / 256, 256>>>(pr, q2e_adj, ME);

  float* leCur = leA;
  float* leNxt = leB;
  for (int l = 0; l < 3; l++) {
    const float* Wh = kb_head_w + l * 65536;
    const float* Ws = kb_self_w + l * 65536;
    const float* Wtl = kb_tail_w + l * 65536;
    const float* We2e = e2e_w + l * 256 * 768;
    const float* We2q = e2q_w + l * 256 * 768;

    smallmv_k<<<BB, 256>>>(qnode, q2e_w + l * 65536, 256, q2e_b + l * 256, q2ev, 256);
    gemm_dualout_k<<<gBig512, 256, SMB>>>(head, eself, leCur, Wh, Ws,
                                          kb_head_b + l * 256,
                                          kb_self_b + l * 256, ME);
    gather_k<<<ME / 4, 256>>>(fs + l * NRELROWS * DD, head, Wt, pr, e2fs,
                              kb_fact_rel, e2f_ent, rowptr, fidx, Asc, prnew);
    // tail GEMM with fused per-entity tail-bias (cnt[m] * kb_tail_b[n])
    gemm_k<false, true, true, 3><<<gBig, 256, SMB>>>(
        eself, Asc, 256, nullptr, Wtl, 256, kb_tail_b + l * 256, cnt,
        ME, 256, 256, 1.f);
    prupd_k<<<(ME + 255) / 256, 256>>>(pr, prnew, ME);
    zero_k<<<(2 * BB * DD + 255) / 256, 256>>>(sred, 2 * BB * DD);
    prsum_k<<<BB, 256>>>(pr, prsum);
    wsum_k<<<BB * 32, 256>>>(pr, leCur, eself, sred, sred + BB * DD);
    qupd_k<<<BB, 256>>>(sred, sred + BB * DD, q2ev, prsum, We2q,
                        e2q_b + l * 256, qnode);
    smallmv_k<<<BB, 256>>>(q2ev, We2e + 256, 768, e2e_b + l * 256, biasBE, 256);
    gemm_dualin_k<<<gBig, 256, SMB>>>(leNxt, leCur, eself, We2e, We2e + 512,
                                      biasBE, 3.f, ME);
    float* t = leCur; leCur = leNxt; leNxt = t;
  }

  score_k<<<ME / 8, 256>>>(leCur, score_w, score_b, out);
}

// round 9
// speedup vs baseline: 1.9651x; 1.3327x over previous
#include <cuda_runtime.h>
#include <cuda_bf16.h>
#include <math.h>
#include <stdint.h>

#define BB 16
#define EE 2048
#define FF 8192
#define QQ 20
#define DD 256
#define WDD 300
#define NRELROWS 601
#define L4D 1024
#define NWORD 50000

#define VERY_NEG -1e11f
#define VERY_SMALL 1e-10f

// ---------------- scratch (device globals; no runtime alloc) ----------------
__device__ float g_lr[NRELROWS * DD];
__device__ float g_fs[3 * NRELROWS * DD];
__device__ float g_lstmb[L4D];
__device__ float g_whhT[DD * L4D];
__device__ float g_gx[BB * QQ * L4D];
__device__ float g_qh[BB * QQ * DD];
__device__ float g_qnode[BB * DD];
__device__ float g_s0[BB * QQ * NRELROWS];
__device__ float g_Wr[BB * NRELROWS];
__device__ float g_maxb[BB];
__device__ float g_Wt[BB * FF];
__device__ float g_e2fs[BB * EE];
__device__ float g_leA[BB * EE * DD];
__device__ float g_leB[BB * EE * DD];
__device__ float g_head[BB * EE * DD];
__device__ float g_eself[BB * EE * DD];
__device__ float g_Asc[BB * EE * DD];
__device__ float g_pr[BB * EE];
__device__ float g_prnew[BB * EE];
__device__ float g_cnt[BB * EE];
__device__ float g_q2ev[BB * DD];
__device__ float g_biasBE[BB * DD];
__device__ float g_sred[2 * BB * DD];
__device__ float g_prsum[BB];
// CSR for f2e scatter->gather
__device__ int g_cnti[BB * EE];
__device__ int g_rowptr[BB * (EE + 1)];
__device__ int g_fill[BB * EE];
__device__ int g_fidx[BB * FF];

// ------- tensor-core GEMM core (bf16x3, m16n8k16, plane-split smem) ---------
#define TBM 128
#define TBN 128
#define TBK 32
#define LDKB 40                      // bf16 units per row; 20*row+tig mod 32 is bijective
#define PLANE (TBM * LDKB)           // 5120 bf16 per plane
#define SMB (4 * PLANE * (int)sizeof(__nv_bfloat16))   // 40960 B

__device__ __forceinline__ void bf16split(float v, __nv_bfloat16& h,
                                          __nv_bfloat16& l) {
  h = __float2bfloat16(v);
  l = __float2bfloat16(v - __bfloat162float(h));
}

__device__ __forceinline__ void store_split4bf(__nv_bfloat16* hp,
                                               __nv_bfloat16* lp, float4 v) {
  __nv_bfloat16 h[4], l[4];
  bf16split(v.x, h[0], l[0]);
  bf16split(v.y, h[1], l[1]);
  bf16split(v.z, h[2], l[2]);
  bf16split(v.w, h[3], l[3]);
  *(uint2*)hp = *(uint2*)h;
  *(uint2*)lp = *(uint2*)l;
}

#define MMA_BF16(c, a, b)                                                  \
  asm volatile(                                                            \
      "mma.sync.aligned.m16n8k16.row.col.f32.bf16.bf16.f32 "               \
      "{%0,%1,%2,%3},{%4,%5,%6,%7},{%8,%9},{%0,%1,%2,%3};"                 \
      : "+f"((c)[0]), "+f"((c)[1]), "+f"((c)[2]), "+f"((c)[3])             \
      : "r"((a)[0]), "r"((a)[1]), "r"((a)[2]), "r"((a)[3]),                \
        "r"((b)[0]), "r"((b)[1]));

__device__ __forceinline__ void mma_tile_bf(
    float acc[4][4][4], const __nv_bfloat16* __restrict__ Ah,
    const __nv_bfloat16* __restrict__ Al, const __nv_bfloat16* __restrict__ Bh,
    const __nv_bfloat16* __restrict__ Bl, int wm, int wn, int g, int tig) {
#pragma unroll
  for (int ks = 0; ks < TBK; ks += 16) {
    uint32_t bh[4][2], bl[4][2];
#pragma unroll
    for (int nt = 0; nt < 4; nt++) {
      int n0 = wn + nt * 8 + g;
      bh[nt][0] = *(const uint32_t*)&Bh[n0 * LDKB + ks + tig * 2];
      bh[nt][1] = *(const uint32_t*)&Bh[n0 * LDKB + ks + 8 + tig * 2];
      bl[nt][0] = *(const uint32_t*)&Bl[n0 * LDKB + ks + tig * 2];
      bl[nt][1] = *(const uint32_t*)&Bl[n0 * LDKB + ks + 8 + tig * 2];
    }
#pragma unroll
    for (int mt = 0; mt < 4; mt++) {
      int m0 = wm + mt * 16;
      uint32_t ah[4], al[4];
      ah[0] = *(const uint32_t*)&Ah[(m0 + g) * LDKB + ks + tig * 2];
      ah[1] = *(const uint32_t*)&Ah[(m0 + g + 8) * LDKB + ks + tig * 2];
      ah[2] = *(const uint32_t*)&Ah[(m0 + g) * LDKB + ks + 8 + tig * 2];
      ah[3] = *(const uint32_t*)&Ah[(m0 + g + 8) * LDKB + ks + 8 + tig * 2];
      al[0] = *(const uint32_t*)&Al[(m0 + g) * LDKB + ks + tig * 2];
      al[1] = *(const uint32_t*)&Al[(m0 + g + 8) * LDKB + ks + tig * 2];
      al[2] = *(const uint32_t*)&Al[(m0 + g) * LDKB + ks + 8 + tig * 2];
      al[3] = *(const uint32_t*)&Al[(m0 + g + 8) * LDKB + ks + 8 + tig * 2];
#pragma unroll
      for (int nt = 0; nt < 4; nt++) {
        MMA_BF16(acc[mt][nt], ah, bl[nt]);
        MMA_BF16(acc[mt][nt], al, bh[nt]);
        MMA_BF16(acc[mt][nt], ah, bh[nt]);
      }
    }
  }
}

// ---------------- generic GEMM: C = act([C +] alpha*A@W^T + bias) ------------
// BIASMODE: 0 none, 1 bias[n], 2 bias[(m>>11)*N+n], 3 rowscale[m]*bias[n]
template <bool GATHER, bool ACCUM, bool RELU, int BIASMODE>
__global__ void __launch_bounds__(256, 2) gemm_k(
    float* __restrict__ C, const float* __restrict__ A, int lda,
    const int* __restrict__ gidx, const float* __restrict__ W, int ldw,
    const float* __restrict__ bias, const float* __restrict__ rowscale,
    int M, int N, int K, float alpha) {
  extern __shared__ __nv_bfloat16 dynb[];
  __nv_bfloat16* Ah = dynb;
  __nv_bfloat16* Al = Ah + PLANE;
  __nv_bfloat16* Bh = Al + PLANE;
  __nv_bfloat16* Bl = Bh + PLANE;
  const int bm = blockIdx.y * TBM, bn = blockIdx.x * TBN;
  const int tid = threadIdx.x;
  const int warp = tid >> 5, lane = tid & 31;
  const int g = lane >> 2, tig = lane & 3;
  const int wm = (warp >> 2) * 64, wn = (warp & 3) * 32;

  float acc[4][4][4];
#pragma unroll
  for (int i = 0; i < 4; i++)
#pragma unroll
    for (int j = 0; j < 4; j++)
#pragma unroll
      for (int c = 0; c < 4; c++) acc[i][j][c] = 0.f;

  for (int kk0 = 0; kk0 < K; kk0 += TBK) {
#pragma unroll
    for (int i = 0; i < 4; i++) {
      int idx = tid + i * 256;
      int row = idx >> 3, kq = idx & 7;
      int k = kk0 + kq * 4;
      float4 va = make_float4(0.f, 0.f, 0.f, 0.f);
      int m = bm + row;
      if (m < M) {
        long r = GATHER ? (long)gidx[m] : (long)m;
        const float* p = A + r * (long)lda + k;
        if (k + 3 < K) va = *(const float4*)p;
        else {
          if (k < K) va.x = p[0];
          if (k + 1 < K) va.y = p[1];
          if (k + 2 < K) va.z = p[2];
        }
      }
      store_split4bf(Ah + row * LDKB + kq * 4, Al + row * LDKB + kq * 4, va);
      float4 vb = make_float4(0.f, 0.f, 0.f, 0.f);
      int n = bn + row;
      if (n < N) {
        const float* p = W + (long)n * ldw + k;
        if (k + 3 < K) vb = *(const float4*)p;
        else {
          if (k < K) vb.x = p[0];
          if (k + 1 < K) vb.y = p[1];
          if (k + 2 < K) vb.z = p[2];
        }
      }
      store_split4bf(Bh + row * LDKB + kq * 4, Bl + row * LDKB + kq * 4, vb);
    }
    __syncthreads();
    mma_tile_bf(acc, Ah, Al, Bh, Bl, wm, wn, g, tig);
    __syncthreads();
  }

#pragma unroll
  for (int mt = 0; mt < 4; mt++) {
#pragma unroll
    for (int nt = 0; nt < 4; nt++) {
#pragma unroll
      for (int half = 0; half < 2; half++) {
        int m = bm + wm + mt * 16 + g + half * 8;
        if (m >= M) continue;
#pragma unroll
        for (int cc = 0; cc < 2; cc++) {
          int n = bn + wn + nt * 8 + tig * 2 + cc;
          if (n >= N) continue;
          float v = alpha * acc[mt][nt][half * 2 + cc];
          if (BIASMODE == 1) v += bias[n];
          if (BIASMODE == 2) v += bias[(m >> 11) * N + n];
          if (BIASMODE == 3) v += rowscale[m] * bias[n];
          long off = (long)m * N + n;
          if (ACCUM) v += C[off];
          if (RELU) v = fmaxf(v, 0.f);
          C[off] = v;
        }
      }
    }
  }
}

// ------------- dual-output GEMM: head = A@W1^T+b1 ; self = A@W2^T+b2 --------
__global__ void __launch_bounds__(256, 2) gemm_dualout_k(
    float* __restrict__ C1, float* __restrict__ C2,
    const float* __restrict__ A, const float* __restrict__ W1,
    const float* __restrict__ W2, const float* __restrict__ b1,
    const float* __restrict__ b2, int M) {
  extern __shared__ __nv_bfloat16 dynb[];
  __nv_bfloat16* Ah = dynb;
  __nv_bfloat16* Al = Ah + PLANE;
  __nv_bfloat16* Bh = Al + PLANE;
  __nv_bfloat16* Bl = Bh + PLANE;
  const int bm = blockIdx.y * TBM, bn = blockIdx.x * TBN;
  const int tid = threadIdx.x;
  const int warp = tid >> 5, lane = tid & 31;
  const int g = lane >> 2, tig = lane & 3;
  const int wm = (warp >> 2) * 64, wn = (warp & 3) * 32;

  float acc[4][4][4];
#pragma unroll
  for (int i = 0; i < 4; i++)
#pragma unroll
    for (int j = 0; j < 4; j++)
#pragma unroll
      for (int c = 0; c < 4; c++) acc[i][j][c] = 0.f;

  for (int kk0 = 0; kk0 < DD; kk0 += TBK) {
#pragma unroll
    for (int i = 0; i < 4; i++) {
      int idx = tid + i * 256;
      int row = idx >> 3, kq = idx & 7;
      int k = kk0 + kq * 4;
      store_split4bf(Ah + row * LDKB + kq * 4, Al + row * LDKB + kq * 4,
                     *(const float4*)(A + (long)(bm + row) * DD + k));
      int n = bn + row;
      const float* Wp = (n < 256) ? (W1 + (long)n * DD) : (W2 + (long)(n - 256) * DD);
      store_split4bf(Bh + row * LDKB + kq * 4, Bl + row * LDKB + kq * 4,
                     *(const float4*)(Wp + k));
    }
    __syncthreads();
    mma_tile_bf(acc, Ah, Al, Bh, Bl, wm, wn, g, tig);
    __syncthreads();
  }

#pragma unroll
  for (int mt = 0; mt < 4; mt++)
#pragma unroll
    for (int nt = 0; nt < 4; nt++)
#pragma unroll
      for (int half = 0; half < 2; half++) {
        int m = bm + wm + mt * 16 + g + half * 8;
#pragma unroll
        for (int cc = 0; cc < 2; cc++) {
          int n = bn + wn + nt * 8 + tig * 2 + cc;
          float v = acc[mt][nt][half * 2 + cc];
          if (n < 256) C1[(long)m * DD + n] = v + b1[n];
          else C2[(long)m * DD + (n - 256)] = v + b2[n - 256];
        }
      }
}

// -------- dual-input GEMM: C = relu(A1@W1^T + sc2*A2@W2^T + biasBE) ---------
__global__ void __launch_bounds__(256, 2) gemm_dualin_k(
    float* __restrict__ C, const float* __restrict__ A1,
    const float* __restrict__ A2, const float* __restrict__ W1,
    const float* __restrict__ W2, const float* __restrict__ biasBE,
    float sc2, int M) {
  extern __shared__ __nv_bfloat16 dynb[];
  __nv_bfloat16* Ah = dynb;
  __nv_bfloat16* Al = Ah + PLANE;
  __nv_bfloat16* Bh = Al + PLANE;
  __nv_bfloat16* Bl = Bh + PLANE;
  const int bm = blockIdx.y * TBM, bn = blockIdx.x * TBN;
  const int tid = threadIdx.x;
  const int warp = tid >> 5, lane = tid & 31;
  const int g = lane >> 2, tig = lane & 3;
  const int wm = (warp >> 2) * 64, wn = (warp & 3) * 32;

  float acc[4][4][4];
#pragma unroll
  for (int i = 0; i < 4; i++)
#pragma unroll
    for (int j = 0; j < 4; j++)
#pragma unroll
      for (int c = 0; c < 4; c++) acc[i][j][c] = 0.f;

  for (int kk0 = 0; kk0 < 2 * DD; kk0 += TBK) {
    const bool second = (kk0 >= DD);
    const float* Asrc = second ? A2 : A1;
    const float* Wsrc = second ? W2 : W1;
    const int kb = second ? (kk0 - DD) : kk0;
    const float sc = second ? sc2 : 1.f;
#pragma unroll
    for (int i = 0; i < 4; i++) {
      int idx = tid + i * 256;
      int row = idx >> 3, kq = idx & 7;
      int k = kb + kq * 4;
      float4 va = *(const float4*)(Asrc + (long)(bm + row) * DD + k);
      va.x *= sc; va.y *= sc; va.z *= sc; va.w *= sc;
      store_split4bf(Ah + row * LDKB + kq * 4, Al + row * LDKB + kq * 4, va);
      store_split4bf(Bh + row * LDKB + kq * 4, Bl + row * LDKB + kq * 4,
                     *(const float4*)(Wsrc + (long)(bn + row) * 768 + k));
    }
    __syncthreads();
    mma_tile_bf(acc, Ah, Al, Bh, Bl, wm, wn, g, tig);
    __syncthreads();
  }

#pragma unroll
  for (int mt = 0; mt < 4; mt++)
#pragma unroll
    for (int nt = 0; nt < 4; nt++)
#pragma unroll
      for (int half = 0; half < 2; half++) {
        int m = bm + wm + mt * 16 + g + half * 8;
#pragma unroll
        for (int cc = 0; cc < 2; cc++) {
          int n = bn + wn + nt * 8 + tig * 2 + cc;
          float v = acc[mt][nt][half * 2 + cc] + biasBE[(m >> 11) * DD + n];
          C[(long)m * DD + n] = fmaxf(v, 0.f);
        }
      }
}

// ---------------- small kernels ----------------
__global__ void zero_k(float* p, int n) {
  int i = blockIdx.x * 256 + threadIdx.x;
  if (i < n) p[i] = 0.f;
}
__global__ void zeroi_k(int* p, int n) {
  int i = blockIdx.x * 256 + threadIdx.x;
  if (i < n) p[i] = 0;
}
__global__ void copy_k(float* d, const float* s, int n) {
  int i = blockIdx.x * 256 + threadIdx.x;
  if (i < n) d[i] = s[i];
}
__global__ void vadd_k(float* o, const float* a, const float* b, int n) {
  int i = blockIdx.x * 256 + threadIdx.x;
  if (i < n) o[i] = a[i] + b[i];
}
__global__ void transp_k(float* o, const float* in) {  // (1024,256)->(256,1024)
  int i = blockIdx.x * 256 + threadIdx.x;
  if (i >= 1024 * 256) return;
  int g = i >> 8, k = i & 255;
  o[k * 1024 + g] = in[i];
}
__global__ void qcopy_k(float* qnode, const float* qh) {
  int b = blockIdx.x, d = threadIdx.x;
  qnode[b * DD + d] = qh[(b * QQ + QQ - 1) * DD + d];
}

__global__ void __launch_bounds__(1024) lstm_k(const float* __restrict__ gx,
                                               const float* __restrict__ whhT,
                                               float* __restrict__ qh) {
  int b = blockIdx.x, g = threadIdx.x;
  __shared__ float hs[DD], cs[DD], zs[L4D];
  if (g < DD) { hs[g] = 0.f; cs[g] = 0.f; }
  __syncthreads();
  for (int t = 0; t < QQ; t++) {
    float acc = gx[(b * QQ + t) * L4D + g];
#pragma unroll 8
    for (int k = 0; k < DD; k++) acc += hs[k] * whhT[k * L4D + g];
    zs[g] = acc;
    __syncthreads();
    if (g < DD) {
      float zi = zs[g], zf = zs[DD + g], zg = zs[2 * DD + g], zo = zs[3 * DD + g];
      float cn = (1.f / (1.f + expf(-zf))) * cs[g] +
                 (1.f / (1.f + expf(-zi))) * tanhf(zg);
      float hn = (1.f / (1.f + expf(-zo))) * tanhf(cn);
      cs[g] = cn;
      hs[g] = hn;
      qh[(b * QQ + t) * DD + g] = hn;
    }
    __syncthreads();
  }
}

__global__ void wr_k(const float* __restrict__ s0, const int* __restrict__ qt,
                     float* __restrict__ Wr) {
  int idx = blockIdx.x * 256 + threadIdx.x;
  if (idx >= BB * NRELROWS) return;
  int b = idx / NRELROWS, r = idx - b * NRELROWS;
  float raw[QQ], lg[QQ];
  float mx = -1e30f;
  for (int q = 0; q < QQ; q++) {
    float v = s0[(b * QQ + q) * NRELROWS + r];
    raw[q] = v;
    lg[q] = v + ((qt[b * QQ + q] == NWORD) ? VERY_NEG : 0.f);
    mx = fmaxf(mx, lg[q]);
  }
  float se = 0.f;
  for (int q = 0; q < QQ; q++) { lg[q] = expf(lg[q] - mx); se += lg[q]; }
  float w = 0.f;
  for (int q = 0; q < QQ; q++) w += (lg[q] / se) * raw[q];
  Wr[idx] = w;
}

__global__ void rowmax_k(const float* Wr, const int* rel, float* maxb) {
  int b = blockIdx.x;
  __shared__ float red[256];
  float mx = -1e30f;
  for (int f = threadIdx.x; f < FF; f += 256)
    mx = fmaxf(mx, Wr[b * NRELROWS + rel[b * FF + f]]);
  red[threadIdx.x] = mx;
  __syncthreads();
  for (int s = 128; s > 0; s >>= 1) {
    if (threadIdx.x < s) red[threadIdx.x] = fmaxf(red[threadIdx.x], red[threadIdx.x + s]);
    __syncthreads();
  }
  if (!threadIdx.x) maxb[b] = red[0];
}

__global__ void wtilde_k(const float* Wr, const int* rel, const int* e2f,
                         const float* maxb, float* Wt, float* e2fs) {
  int i = blockIdx.x * 256 + threadIdx.x;
  if (i >= BB * FF) return;
  int b = i >> 13;
  float wt = expf(Wr[b * NRELROWS + rel[i]] - maxb[b]);
  Wt[i] = wt;
  atomicAdd(&e2fs[b * EE + e2f[i]], wt);
}

__global__ void clamp_k(float* p, int n) {
  int i = blockIdx.x * 256 + threadIdx.x;
  if (i < n) p[i] = fmaxf(p[i], VERY_SMALL);
}

// ---- CSR build (once; f2e_ent is layer-invariant) ----
__global__ void cnti_k(int* cnt, const int* f2e) {
  int i = blockIdx.x * 256 + threadIdx.x;
  if (i >= BB * FF) return;
  atomicAdd(&cnt[(i >> 13) * EE + f2e[i]], 1);
}

__global__ void scan_k(const int* __restrict__ cnt, int* __restrict__ rowptr,
                       float* __restrict__ cntf) {
  int b = blockIdx.x, t = threadIdx.x;
  __shared__ int part[256];
  __shared__ int partx[257];
  int loc[8];
  int s = 0;
  int base = b * EE + t * 8;
  for (int j = 0; j < 8; j++) { loc[j] = cnt[base + j]; s += loc[j]; }
  part[t] = s;
  __syncthreads();
  if (t == 0) {
    int a = 0;
    for (int i = 0; i < 256; i++) { partx[i] = a; a += part[i]; }
    partx[256] = a;
  }
  __syncthreads();
  int off = partx[t];
  for (int j = 0; j < 8; j++) {
    rowptr[b * (EE + 1) + t * 8 + j] = off;
    cntf[base + j] = (float)loc[j];
    off += loc[j];
  }
  if (t == 255) rowptr[b * (EE + 1) + EE] = off;
}

__global__ void fill_k(const int* __restrict__ f2e, const int* __restrict__ rowptr,
                       int* __restrict__ fill, int* __restrict__ fidx) {
  int i = blockIdx.x * 256 + threadIdx.x;
  if (i >= BB * FF) return;
  int b = i >> 13, f = i & (FF - 1);
  int e = f2e[i];
  int pos = rowptr[b * (EE + 1) + e] + atomicAdd(&fill[b * EE + e], 1);
  fidx[b * FF + pos] = f;
}

// ---- per-layer fact gather ----
__global__ void __launch_bounds__(256) gather_k(
    const float* __restrict__ fsl, const float* __restrict__ head,
    const float* __restrict__ Wt, const float* __restrict__ pr,
    const float* __restrict__ e2fs, const int* __restrict__ rel,
    const int* __restrict__ e2f, const int* __restrict__ rowptr,
    const int* __restrict__ fidx, float* __restrict__ Asc,
    float* __restrict__ prnew) {
  int sub = threadIdx.x >> 6;
  int lane = threadIdx.x & 63;
  int be = blockIdx.x * 4 + sub;
  int b = be >> 11, e = be & (EE - 1);
  int beg = rowptr[b * (EE + 1) + e], end = rowptr[b * (EE + 1) + e + 1];
  float4 acc = make_float4(0.f, 0.f, 0.f, 0.f);
  float nsum = 0.f;
  for (int p = beg; p < end; p++) {
    int f = fidx[b * FF + p];
    int bf = (b << 13) + f;
    int esrc = e2f[bf];
    int r = rel[bf];
    float nrm = Wt[bf] * pr[b * EE + esrc] / e2fs[b * EE + esrc];
    nsum += nrm;
    float4 h = ((const float4*)(head + (long)(b * EE + esrc) * DD))[lane];
    float4 fv = ((const float4*)(fsl + (long)r * DD))[lane];
    acc.x += fmaxf(h.x + fv.x, 0.f) * nrm;
    acc.y += fmaxf(h.y + fv.y, 0.f) * nrm;
    acc.z += fmaxf(h.z + fv.z, 0.f) * nrm;
    acc.w += fmaxf(h.w + fv.w, 0.f) * nrm;
  }
  ((float4*)(Asc + (long)be * DD))[lane] = acc;
  if (lane == 0) prnew[be] = nsum;
}

__global__ void prupd_k(float* pr, const float* prnew, int n) {
  int i = blockIdx.x * 256 + threadIdx.x;
  if (i < n) pr[i] = 0.8f * prnew[i] + 0.2f * pr[i];
}

__global__ void prsum_k(const float* pr, float* prsum) {
  int b = blockIdx.x;
  __shared__ float red[256];
  float s = 0.f;
  for (int e = threadIdx.x; e < EE; e += 256) s += pr[b * EE + e];
  red[threadIdx.x] = s;
  __syncthreads();
  for (int st = 128; st > 0; st >>= 1) {
    if (threadIdx.x < st) red[threadIdx.x] += red[threadIdx.x + st];
    __syncthreads();
  }
  if (!threadIdx.x) prsum[b] = red[0];
}

__global__ void wsum_k(const float* __restrict__ pr, const float* __restrict__ le,
                       const float* __restrict__ f2e, float* __restrict__ sle,
                       float* __restrict__ sf2e) {
  int blk = blockIdx.x;
  int b = blk >> 5, ch = blk & 31;
  int d = threadIdx.x;
  float a = 0.f, c = 0.f;
  int e0 = ch * 64;
  for (int e = e0; e < e0 + 64; e++) {
    float w = pr[b * EE + e];
    a += w * le[(long)(b * EE + e) * DD + d];
    c += w * f2e[(long)(b * EE + e) * DD + d];
  }
  atomicAdd(&sle[b * DD + d], a);
  atomicAdd(&sf2e[b * DD + d], c);
}

__global__ void smallmv_k(const float* __restrict__ x, const float* __restrict__ W,
                          int ldw, const float* __restrict__ bias,
                          float* __restrict__ y, int K) {
  int b = blockIdx.x, n = threadIdx.x;
  const float* w = W + (long)n * ldw;
  const float* xb = x + b * K;
  float acc = bias ? bias[n] : 0.f;
  for (int k = 0; k < K; k++) acc += xb[k] * w[k];
  y[b * DD + n] = acc;
}

__global__ void qupd_k(const float* sle, const float* sf2e, const float* q2ev,
                       const float* prsum, const float* __restrict__ W,
                       const float* bias, float* qnode) {
  int b = blockIdx.x, n = threadIdx.x;
  const float* w = W + (long)n * 768;
  float ps = prsum[b];
  float acc = ps * bias[n];
  for (int k = 0; k < DD; k++) acc += sle[b * DD + k] * w[k];
  for (int k = 0; k < DD; k++) acc += ps * q2ev[b * DD + k] * w[DD + k];
  for (int k = 0; k < DD; k++) acc += 3.f * sf2e[b * DD + k] * w[2 * DD + k];
  qnode[b * DD + n] = acc;
}

__global__ void score_k(const float* __restrict__ le, const float* __restrict__ sw,
                        const float* __restrict__ sb, float* __restrict__ out) {
  int row = blockIdx.x * 8 + (threadIdx.x >> 5);
  int lane = threadIdx.x & 31;
  float acc = 0.f;
#pragma unroll
  for (int j = 0; j < 8; j++) {
    int k = lane + j * 32;
    acc += le[(long)row * DD + k] * sw[k];
  }
#pragma unroll
  for (int o = 16; o > 0; o >>= 1) acc += __shfl_down_sync(0xffffffffu, acc, o);
  if (!lane) out[row] = acc + sb[0];
}

// ---------------- host ----------------
extern "C" void kernel_launch(void* const* d_in, const int* in_sizes, int n_in,
                              void* d_out, int out_size) {
  const int* local_entity = (const int*)d_in[0];
  const float* q2e_adj = (const float*)d_in[1];
  const int* kb_fact_rel = (const int*)d_in[2];
  const int* query_text = (const int*)d_in[3];
  const int* e2f_ent = (const int*)d_in[5];
  const int* f2e_ent = (const int*)d_in[6];
  const float* word_emb = (const float*)d_in[7];
  const float* entity_emb = (const float*)d_in[8];
  const float* relation_emb = (const float*)d_in[9];
  const float* ent_w = (const float*)d_in[10];
  const float* ent_b = (const float*)d_in[11];
  const float* rel_w = (const float*)d_in[12];
  const float* rel_b = (const float*)d_in[13];
  const float* w_ih = (const float*)d_in[14];
  const float* w_hh = (const float*)d_in[15];
  const float* b_ih = (const float*)d_in[16];
  const float* b_hh = (const float*)d_in[17];
  const float* q2e_w = (const float*)d_in[18];
  const float* q2e_b = (const float*)d_in[19];
  const float* e2q_w = (const float*)d_in[20];
  const float* e2q_b = (const float*)d_in[21];
  const float* e2e_w = (const float*)d_in[22];
  const float* e2e_b = (const float*)d_in[23];
  const float* kb_head_w = (const float*)d_in[24];
  const float* kb_head_b = (const float*)d_in[25];
  const float* kb_tail_w = (const float*)d_in[26];
  const float* kb_tail_b = (const float*)d_in[27];
  const float* kb_self_w = (const float*)d_in[28];
  const float* kb_self_b = (const float*)d_in[29];
  const float* score_w = (const float*)d_in[30];
  const float* score_b = (const float*)d_in[31];
  float* out = (float*)d_out;
  (void)in_sizes; (void)n_in; (void)out_size;

  float *lr, *fs, *lstmb, *whhT, *gx, *qh, *qnode, *s0, *Wr, *maxb, *Wt, *e2fs;
  float *leA, *leB, *head, *eself, *Asc, *pr, *prnew, *cnt, *q2ev, *biasBE;
  float *sred, *prsum;
  int *cnti, *rowptr, *fill, *fidx;
  cudaGetSymbolAddress((void**)&lr, g_lr);
  cudaGetSymbolAddress((void**)&fs, g_fs);
  cudaGetSymbolAddress((void**)&lstmb, g_lstmb);
  cudaGetSymbolAddress((void**)&whhT, g_whhT);
  cudaGetSymbolAddress((void**)&gx, g_gx);
  cudaGetSymbolAddress((void**)&qh, g_qh);
  cudaGetSymbolAddress((void**)&qnode, g_qnode);
  cudaGetSymbolAddress((void**)&s0, g_s0);
  cudaGetSymbolAddress((void**)&Wr, g_Wr);
  cudaGetSymbolAddress((void**)&maxb, g_maxb);
  cudaGetSymbolAddress((void**)&Wt, g_Wt);
  cudaGetSymbolAddress((void**)&e2fs, g_e2fs);
  cudaGetSymbolAddress((void**)&leA, g_leA);
  cudaGetSymbolAddress((void**)&leB, g_leB);
  cudaGetSymbolAddress((void**)&head, g_head);
  cudaGetSymbolAddress((void**)&eself, g_eself);
  cudaGetSymbolAddress((void**)&Asc, g_Asc);
  cudaGetSymbolAddress((void**)&pr, g_pr);
  cudaGetSymbolAddress((void**)&prnew, g_prnew);
  cudaGetSymbolAddress((void**)&cnt, g_cnt);
  cudaGetSymbolAddress((void**)&q2ev, g_q2ev);
  cudaGetSymbolAddress((void**)&biasBE, g_biasBE);
  cudaGetSymbolAddress((void**)&sred, g_sred);
  cudaGetSymbolAddress((void**)&prsum, g_prsum);
  cudaGetSymbolAddress((void**)&cnti, g_cnti);
  cudaGetSymbolAddress((void**)&rowptr, g_rowptr);
  cudaGetSymbolAddress((void**)&fill, g_fill);
  cudaGetSymbolAddress((void**)&fidx, g_fidx);

  const int ME = BB * EE;            // 32768
  dim3 gBig(2, ME / TBM);
  dim3 gBig512(4, ME / TBM);
  dim3 gRel(2, (NRELROWS + TBM - 1) / TBM);

  // --- prologue; 4th launch (ncu-profiled) = the BIG entity GEMM ---
  vadd_k<<<4, 256>>>(lstmb, b_ih, b_hh, L4D);                       // 1
  transp_k<<<1024, 256>>>(whhT, w_hh);                              // 2
  gemm_k<false, false, false, 1><<<gRel, 256, SMB>>>(               // 3
      lr, relation_emb, 600, nullptr, rel_w, 600, rel_b, nullptr,
      NRELROWS, 256, 600, 1.f);
  gemm_k<true, false, false, 1><<<gBig, 256, SMB>>>(                // 4 <- profiled
      leA, entity_emb, WDD, local_entity, ent_w, WDD, ent_b, nullptr,
      ME, 256, WDD, 1.f);
  for (int l = 0; l < 3; l++)
    gemm_k<false, false, false, 1><<<gRel, 256, SMB>>>(
        fs + l * NRELROWS * DD, lr, 256, nullptr, kb_self_w + l * 65536, 256,
        kb_self_b + l * 256, nullptr, NRELROWS, 256, 256, 1.f);
  gemm_k<true, false, false, 1><<<dim3(8, 3), 256, SMB>>>(
      gx, word_emb, WDD, query_text, w_ih, WDD, lstmb, nullptr,
      BB * QQ, L4D, WDD, 1.f);
  lstm_k<<<BB, 1024>>>(gx, whhT, qh);
  qcopy_k<<<BB, 256>>>(qnode, qh);

  // --- CSR build for f2e gather ---
  zeroi_k<<<(ME + 255) / 256, 256>>>(cnti, ME);
  zeroi_k<<<(ME + 255) / 256, 256>>>(fill, ME);
  cnti_k<<<(BB * FF) / 256, 256>>>(cnti, f2e_ent);
  scan_k<<<BB, 256>>>(cnti, rowptr, cnt);
  fill_k<<<(BB * FF) / 256, 256>>>(f2e_ent, rowptr, fill, fidx);

  // --- attention -> Wr -> W_tilde -> e2f_softmax ---
  gemm_k<false, false, false, 0><<<dim3(5, 3), 256, SMB>>>(
      s0, qh, 256, nullptr, lr, 256, nullptr, nullptr,
      BB * QQ, NRELROWS, 256, 1.f / 16.f);
  wr_k<<<(BB * NRELROWS + 255) / 256, 256>>>(s0, query_text, Wr);
  rowmax_k<<<BB, 256>>>(Wr, kb_fact_rel, maxb);
  zero_k<<<(ME + 255) / 256, 256>>>(e2fs, ME);
  wtilde_k<<<(BB * FF) / 256, 256>>>(Wr, kb_fact_rel, e2f_ent, maxb, Wt, e2fs);
  clamp_k<<<(ME + 255) / 256, 256>>>(e2fs, ME);

  // --- pagerank init ---
  copy_k<<<(ME + 255) / 256, 256>>>(pr, q2e_adj, ME);

  float* leCur = leA;
  float* leNxt = leB;
  for (int l = 0; l < 3; l++) {
    const float* Wh = kb_head_w + l * 65536;
    const float* Ws = kb_self_w + l * 65536;
    const float* Wtl = kb_tail_w + l * 65536;
    const float* We2e = e2e_w + l * 256 * 768;
    const float* We2q = e2q_w + l * 256 * 768;

    smallmv_k<<<BB, 256>>>(qnode, q2e_w + l * 65536, 256, q2e_b + l * 256, q2ev, 256);
    gemm_dualout_k<<<gBig512, 256, SMB>>>(head, eself, leCur, Wh, Ws,
                                          kb_head_b + l * 256,
                                          kb_self_b + l * 256, ME);
    gather_k<<<ME / 4, 256>>>(fs + l * NRELROWS * DD, head, Wt, pr, e2fs,
                              kb_fact_rel, e2f_ent, rowptr, fidx, Asc, prnew);
    // tail GEMM with fused per-entity tail-bias (cnt[m] * kb_tail_b[n])
    gemm_k<false, true, true, 3><<<gBig, 256, SMB>>>(
        eself, Asc, 256, nullptr, Wtl, 256, kb_tail_b + l * 256, cnt,
        ME, 256, 256, 1.f);
    prupd_k<<<(ME + 255) / 256, 256>>>(pr, prnew, ME);
    zero_k<<<(2 * BB * DD + 255) / 256, 256>>>(sred, 2 * BB * DD);
    prsum_k<<<BB, 256>>>(pr, prsum);
    wsum_k<<<BB * 32, 256>>>(pr, leCur, eself, sred, sred + BB * DD);
    qupd_k<<<BB, 256>>>(sred, sred + BB * DD, q2ev, prsum, We2q,
                        e2q_b + l * 256, qnode);
    smallmv_k<<<BB, 256>>>(q2ev, We2e + 256, 768, e2e_b + l * 256, biasBE, 256);
    gemm_dualin_k<<<gBig, 256, SMB>>>(leNxt, leCur, eself, We2e, We2e + 512,
                                      biasBE, 3.f, ME);
    float* t = leCur; leCur = leNxt; leNxt = t;
  }

  score_k<<<ME / 8, 256>>>(leCur, score_w, score_b, out);
}

// round 10
// speedup vs baseline: 2.2186x; 1.1290x over previous
#include <cuda_runtime.h>
#include <cuda_bf16.h>
#include <math.h>
#include <stdint.h>

#define BB 16
#define EE 2048
#define FF 8192
#define QQ 20
#define DD 256
#define WDD 300
#define NRELROWS 601
#define L4D 1024
#define NWORD 50000

#define VERY_NEG -1e11f
#define VERY_SMALL 1e-10f

// ---------------- scratch (device globals; no runtime alloc) ----------------
__device__ float g_lr[NRELROWS * DD];
__device__ float g_fs[3 * NRELROWS * DD];
__device__ float g_lstmb[L4D];
__device__ float g_whhT[DD * L4D];
__device__ float g_gx[BB * QQ * L4D];
__device__ float g_qh[BB * QQ * DD];
__device__ float g_qnode[BB * DD];
__device__ float g_s0[BB * QQ * NRELROWS];
__device__ float g_Wr[BB * NRELROWS];
__device__ float g_maxb[BB];
__device__ float g_Wt[BB * FF];
__device__ float g_e2fs[BB * EE];
__device__ float g_leA[BB * EE * DD];
__device__ float g_leB[BB * EE * DD];
__device__ float g_head[BB * EE * DD];
__device__ float g_eself[BB * EE * DD];
__device__ float g_Asc[BB * EE * DD];
__device__ float g_pr[BB * EE];
__device__ float g_prnew[BB * EE];
__device__ float g_cnt[BB * EE];
__device__ float g_q2ev[BB * DD];
__device__ float g_biasBE[BB * DD];
__device__ float g_sred[2 * BB * DD];
__device__ float g_prsum[BB];
// CSR for f2e scatter->gather
__device__ int g_cnti[BB * EE];
__device__ int g_rowptr[BB * (EE + 1)];
__device__ int g_fill[BB * EE];
__device__ int g_fidx[BB * FF];

// ------- tensor-core GEMM core (bf16x3, m16n8k16, cp.async pipeline) --------
#define TBM 128
#define TBN 128
#define TBK 32
#define LDKB 40                      // bf16 units per plane row (conflict-free)
#define PLANE (TBM * LDKB)           // 5120 bf16 per plane
#define RAWF (TBM * TBK)             // 4096 floats per raw tile
// smem: 4 bf16 planes + 2 stages x (rawA + rawB)
#define SMB_PIPE (4 * PLANE * (int)sizeof(__nv_bfloat16) + 4 * RAWF * (int)sizeof(float))

#define CP_ASYNC16(dst32, src, sz)                                         \
  asm volatile("cp.async.cg.shared.global [%0], [%1], 16, %2;" ::          \
                   "r"(dst32), "l"(src), "r"(sz))
#define CP_COMMIT() asm volatile("cp.async.commit_group;")
#define CP_WAIT1() asm volatile("cp.async.wait_group 1;")

__device__ __forceinline__ void bf16split(float v, __nv_bfloat16& h,
                                          __nv_bfloat16& l) {
  h = __float2bfloat16(v);
  l = __float2bfloat16(v - __bfloat162float(h));
}

__device__ __forceinline__ void store_split4bf(__nv_bfloat16* hp,
                                               __nv_bfloat16* lp, float4 v) {
  __nv_bfloat16 h[4], l[4];
  bf16split(v.x, h[0], l[0]);
  bf16split(v.y, h[1], l[1]);
  bf16split(v.z, h[2], l[2]);
  bf16split(v.w, h[3], l[3]);
  *(uint2*)hp = *(uint2*)h;
  *(uint2*)lp = *(uint2*)l;
}

#define MMA_BF16(c, a, b)                                                  \
  asm volatile(                                                            \
      "mma.sync.aligned.m16n8k16.row.col.f32.bf16.bf16.f32 "               \
      "{%0,%1,%2,%3},{%4,%5,%6,%7},{%8,%9},{%0,%1,%2,%3};"                 \
      : "+f"((c)[0]), "+f"((c)[1]), "+f"((c)[2]), "+f"((c)[3])             \
      : "r"((a)[0]), "r"((a)[1]), "r"((a)[2]), "r"((a)[3]),                \
        "r"((b)[0]), "r"((b)[1]));

__device__ __forceinline__ void mma_tile_bf(
    float acc[4][4][4], const __nv_bfloat16* __restrict__ Ah,
    const __nv_bfloat16* __restrict__ Al, const __nv_bfloat16* __restrict__ Bh,
    const __nv_bfloat16* __restrict__ Bl, int wm, int wn, int g, int tig) {
#pragma unroll
  for (int ks = 0; ks < TBK; ks += 16) {
    uint32_t bh[4][2], bl[4][2];
#pragma unroll
    for (int nt = 0; nt < 4; nt++) {
      int n0 = wn + nt * 8 + g;
      bh[nt][0] = *(const uint32_t*)&Bh[n0 * LDKB + ks + tig * 2];
      bh[nt][1] = *(const uint32_t*)&Bh[n0 * LDKB + ks + 8 + tig * 2];
      bl[nt][0] = *(const uint32_t*)&Bl[n0 * LDKB + ks + tig * 2];
      bl[nt][1] = *(const uint32_t*)&Bl[n0 * LDKB + ks + 8 + tig * 2];
    }
#pragma unroll
    for (int mt = 0; mt < 4; mt++) {
      int m0 = wm + mt * 16;
      uint32_t ah[4], al[4];
      ah[0] = *(const uint32_t*)&Ah[(m0 + g) * LDKB + ks + tig * 2];
      ah[1] = *(const uint32_t*)&Ah[(m0 + g + 8) * LDKB + ks + tig * 2];
      ah[2] = *(const uint32_t*)&Ah[(m0 + g) * LDKB + ks + 8 + tig * 2];
      ah[3] = *(const uint32_t*)&Ah[(m0 + g + 8) * LDKB + ks + 8 + tig * 2];
      al[0] = *(const uint32_t*)&Al[(m0 + g) * LDKB + ks + tig * 2];
      al[1] = *(const uint32_t*)&Al[(m0 + g + 8) * LDKB + ks + tig * 2];
      al[2] = *(const uint32_t*)&Al[(m0 + g) * LDKB + ks + 8 + tig * 2];
      al[3] = *(const uint32_t*)&Al[(m0 + g + 8) * LDKB + ks + 8 + tig * 2];
#pragma unroll
      for (int nt = 0; nt < 4; nt++) {
        MMA_BF16(acc[mt][nt], ah, bl[nt]);
        MMA_BF16(acc[mt][nt], al, bh[nt]);
        MMA_BF16(acc[mt][nt], ah, bh[nt]);
      }
    }
  }
}

// convert one raw stage (fp32) into the bf16 hi/lo planes; A scaled by sc
__device__ __forceinline__ void convert_stage(
    const float* __restrict__ rA, const float* __restrict__ rB,
    __nv_bfloat16* Ah, __nv_bfloat16* Al, __nv_bfloat16* Bh, __nv_bfloat16* Bl,
    int tid, float sc) {
#pragma unroll
  for (int i = 0; i < 4; i++) {
    int idx = tid + i * 256;
    int row = idx >> 3, kq = idx & 7;
    float4 va = *(const float4*)(rA + row * TBK + kq * 4);
    va.x *= sc; va.y *= sc; va.z *= sc; va.w *= sc;
    store_split4bf(Ah + row * LDKB + kq * 4, Al + row * LDKB + kq * 4, va);
    float4 vb = *(const float4*)(rB + row * TBK + kq * 4);
    store_split4bf(Bh + row * LDKB + kq * 4, Bl + row * LDKB + kq * 4, vb);
  }
}

// ---------------- generic GEMM: C = act([C +] alpha*A@W^T + bias) ------------
// BIASMODE: 0 none, 1 bias[n], 2 bias[(m>>11)*N+n], 3 rowscale[m]*bias[n]
template <bool GATHER, bool ACCUM, bool RELU, int BIASMODE>
__global__ void __launch_bounds__(256, 2) gemm_k(
    float* __restrict__ C, const float* __restrict__ A, int lda,
    const int* __restrict__ gidx, const float* __restrict__ W, int ldw,
    const float* __restrict__ bias, const float* __restrict__ rowscale,
    int M, int N, int K, float alpha) {
  extern __shared__ __align__(16) char smem_c[];
  __nv_bfloat16* Ah = (__nv_bfloat16*)smem_c;
  __nv_bfloat16* Al = Ah + PLANE;
  __nv_bfloat16* Bh = Al + PLANE;
  __nv_bfloat16* Bl = Bh + PLANE;
  float* rbase = (float*)(Bl + PLANE);
  const int bm = blockIdx.y * TBM, bn = blockIdx.x * TBN;
  const int tid = threadIdx.x;
  const int warp = tid >> 5, lane = tid & 31;
  const int g = lane >> 2, tig = lane & 3;
  const int wm = (warp >> 2) * 64, wn = (warp & 3) * 32;

  float acc[4][4][4];
#pragma unroll
  for (int i = 0; i < 4; i++)
#pragma unroll
    for (int j = 0; j < 4; j++)
#pragma unroll
      for (int c = 0; c < 4; c++) acc[i][j][c] = 0.f;

  const int nt = (K + TBK - 1) / TBK;

  auto issue = [&](int tile, int stage) {
    int k0 = tile * TBK;
    float* rA = rbase + stage * 2 * RAWF;
    float* rB = rA + RAWF;
#pragma unroll
    for (int i = 0; i < 4; i++) {
      int idx = tid + i * 256;
      int row = idx >> 3, kq = idx & 7;
      int k = k0 + kq * 4;
      int m = bm + row;
      long r = GATHER ? (long)gidx[m < M ? m : 0] : (long)(m < M ? m : 0);
      const float* pa = A + r * (long)lda + (k < K ? k : 0);
      int sa = (m < M && k < K) ? 16 : 0;
      CP_ASYNC16((uint32_t)__cvta_generic_to_shared(rA + row * TBK + kq * 4),
                 pa, sa);
      int n = bn + row;
      const float* pb = W + (long)(n < N ? n : 0) * ldw + (k < K ? k : 0);
      int sb = (n < N && k < K) ? 16 : 0;
      CP_ASYNC16((uint32_t)__cvta_generic_to_shared(rB + row * TBK + kq * 4),
                 pb, sb);
    }
  };

  issue(0, 0);
  CP_COMMIT();
  if (nt > 1) issue(1, 1);
  CP_COMMIT();
  CP_WAIT1();
  __syncthreads();
  for (int kk = 0; kk < nt; kk++) {
    int stage = kk & 1;
    convert_stage(rbase + stage * 2 * RAWF, rbase + stage * 2 * RAWF + RAWF,
                  Ah, Al, Bh, Bl, tid, 1.f);
    __syncthreads();
    if (kk + 2 < nt) issue(kk + 2, stage);
    CP_COMMIT();
    mma_tile_bf(acc, Ah, Al, Bh, Bl, wm, wn, g, tig);
    CP_WAIT1();
    __syncthreads();
  }

#pragma unroll
  for (int mt = 0; mt < 4; mt++) {
#pragma unroll
    for (int nt2 = 0; nt2 < 4; nt2++) {
#pragma unroll
      for (int half = 0; half < 2; half++) {
        int m = bm + wm + mt * 16 + g + half * 8;
        if (m >= M) continue;
#pragma unroll
        for (int cc = 0; cc < 2; cc++) {
          int n = bn + wn + nt2 * 8 + tig * 2 + cc;
          if (n >= N) continue;
          float v = alpha * acc[mt][nt2][half * 2 + cc];
          if (BIASMODE == 1) v += bias[n];
          if (BIASMODE == 2) v += bias[(m >> 11) * N + n];
          if (BIASMODE == 3) v += rowscale[m] * bias[n];
          long off = (long)m * N + n;
          if (ACCUM) v += C[off];
          if (RELU) v = fmaxf(v, 0.f);
          C[off] = v;
        }
      }
    }
  }
}

// ------------- dual-output GEMM: head = A@W1^T+b1 ; self = A@W2^T+b2 --------
__global__ void __launch_bounds__(256, 2) gemm_dualout_k(
    float* __restrict__ C1, float* __restrict__ C2,
    const float* __restrict__ A, const float* __restrict__ W1,
    const float* __restrict__ W2, const float* __restrict__ b1,
    const float* __restrict__ b2, int M) {
  extern __shared__ __align__(16) char smem_c[];
  __nv_bfloat16* Ah = (__nv_bfloat16*)smem_c;
  __nv_bfloat16* Al = Ah + PLANE;
  __nv_bfloat16* Bh = Al + PLANE;
  __nv_bfloat16* Bl = Bh + PLANE;
  float* rbase = (float*)(Bl + PLANE);
  const int bm = blockIdx.y * TBM, bn = blockIdx.x * TBN;
  const int tid = threadIdx.x;
  const int warp = tid >> 5, lane = tid & 31;
  const int g = lane >> 2, tig = lane & 3;
  const int wm = (warp >> 2) * 64, wn = (warp & 3) * 32;

  float acc[4][4][4];
#pragma unroll
  for (int i = 0; i < 4; i++)
#pragma unroll
    for (int j = 0; j < 4; j++)
#pragma unroll
      for (int c = 0; c < 4; c++) acc[i][j][c] = 0.f;

  const int nt = DD / TBK;  // 8

  auto issue = [&](int tile, int stage) {
    int k0 = tile * TBK;
    float* rA = rbase + stage * 2 * RAWF;
    float* rB = rA + RAWF;
#pragma unroll
    for (int i = 0; i < 4; i++) {
      int idx = tid + i * 256;
      int row = idx >> 3, kq = idx & 7;
      int k = k0 + kq * 4;
      CP_ASYNC16((uint32_t)__cvta_generic_to_shared(rA + row * TBK + kq * 4),
                 A + (long)(bm + row) * DD + k, 16);
      int n = bn + row;
      const float* Wp =
          (n < 256) ? (W1 + (long)n * DD) : (W2 + (long)(n - 256) * DD);
      CP_ASYNC16((uint32_t)__cvta_generic_to_shared(rB + row * TBK + kq * 4),
                 Wp + k, 16);
    }
  };

  issue(0, 0);
  CP_COMMIT();
  issue(1, 1);
  CP_COMMIT();
  CP_WAIT1();
  __syncthreads();
  for (int kk = 0; kk < nt; kk++) {
    int stage = kk & 1;
    convert_stage(rbase + stage * 2 * RAWF, rbase + stage * 2 * RAWF + RAWF,
                  Ah, Al, Bh, Bl, tid, 1.f);
    __syncthreads();
    if (kk + 2 < nt) issue(kk + 2, stage);
    CP_COMMIT();
    mma_tile_bf(acc, Ah, Al, Bh, Bl, wm, wn, g, tig);
    CP_WAIT1();
    __syncthreads();
  }

#pragma unroll
  for (int mt = 0; mt < 4; mt++)
#pragma unroll
    for (int nt2 = 0; nt2 < 4; nt2++)
#pragma unroll
      for (int half = 0; half < 2; half++) {
        int m = bm + wm + mt * 16 + g + half * 8;
#pragma unroll
        for (int cc = 0; cc < 2; cc++) {
          int n = bn + wn + nt2 * 8 + tig * 2 + cc;
          float v = acc[mt][nt2][half * 2 + cc];
          if (n < 256) C1[(long)m * DD + n] = v + b1[n];
          else C2[(long)m * DD + (n - 256)] = v + b2[n - 256];
        }
      }
}

// -------- dual-input GEMM: C = relu(A1@W1^T + sc2*A2@W2^T + biasBE) ---------
__global__ void __launch_bounds__(256, 2) gemm_dualin_k(
    float* __restrict__ C, const float* __restrict__ A1,
    const float* __restrict__ A2, const float* __restrict__ W1,
    const float* __restrict__ W2, const float* __restrict__ biasBE,
    float sc2, int M) {
  extern __shared__ __align__(16) char smem_c[];
  __nv_bfloat16* Ah = (__nv_bfloat16*)smem_c;
  __nv_bfloat16* Al = Ah + PLANE;
  __nv_bfloat16* Bh = Al + PLANE;
  __nv_bfloat16* Bl = Bh + PLANE;
  float* rbase = (float*)(Bl + PLANE);
  const int bm = blockIdx.y * TBM, bn = blockIdx.x * TBN;
  const int tid = threadIdx.x;
  const int warp = tid >> 5, lane = tid & 31;
  const int g = lane >> 2, tig = lane & 3;
  const int wm = (warp >> 2) * 64, wn = (warp & 3) * 32;

  float acc[4][4][4];
#pragma unroll
  for (int i = 0; i < 4; i++)
#pragma unroll
    for (int j = 0; j < 4; j++)
#pragma unroll
      for (int c = 0; c < 4; c++) acc[i][j][c] = 0.f;

  const int nt = 2 * DD / TBK;  // 16
  const int half_nt = DD / TBK; // 8

  auto issue = [&](int tile, int stage) {
    const bool second = (tile >= half_nt);
    const float* Asrc = second ? A2 : A1;
    const float* Wsrc = second ? W2 : W1;
    int k0 = (second ? (tile - half_nt) : tile) * TBK;
    float* rA = rbase + stage * 2 * RAWF;
    float* rB = rA + RAWF;
#pragma unroll
    for (int i = 0; i < 4; i++) {
      int idx = tid + i * 256;
      int row = idx >> 3, kq = idx & 7;
      int k = k0 + kq * 4;
      CP_ASYNC16((uint32_t)__cvta_generic_to_shared(rA + row * TBK + kq * 4),
                 Asrc + (long)(bm + row) * DD + k, 16);
      CP_ASYNC16((uint32_t)__cvta_generic_to_shared(rB + row * TBK + kq * 4),
                 Wsrc + (long)(bn + row) * 768 + k, 16);
    }
  };

  issue(0, 0);
  CP_COMMIT();
  issue(1, 1);
  CP_COMMIT();
  CP_WAIT1();
  __syncthreads();
  for (int kk = 0; kk < nt; kk++) {
    int stage = kk & 1;
    float sc = (kk >= half_nt) ? sc2 : 1.f;
    convert_stage(rbase + stage * 2 * RAWF, rbase + stage * 2 * RAWF + RAWF,
                  Ah, Al, Bh, Bl, tid, sc);
    __syncthreads();
    if (kk + 2 < nt) issue(kk + 2, stage);
    CP_COMMIT();
    mma_tile_bf(acc, Ah, Al, Bh, Bl, wm, wn, g, tig);
    CP_WAIT1();
    __syncthreads();
  }

#pragma unroll
  for (int mt = 0; mt < 4; mt++)
#pragma unroll
    for (int nt2 = 0; nt2 < 4; nt2++)
#pragma unroll
      for (int half = 0; half < 2; half++) {
        int m = bm + wm + mt * 16 + g + half * 8;
#pragma unroll
        for (int cc = 0; cc < 2; cc++) {
          int n = bn + wn + nt2 * 8 + tig * 2 + cc;
          float v = acc[mt][nt2][half * 2 + cc] + biasBE[(m >> 11) * DD + n];
          C[(long)m * DD + n] = fmaxf(v, 0.f);
        }
      }
}

// ---------------- small kernels ----------------
__global__ void zero_k(float* p, int n) {
  int i = blockIdx.x * 256 + threadIdx.x;
  if (i < n) p[i] = 0.f;
}
__global__ void zeroi_k(int* p, int n) {
  int i = blockIdx.x * 256 + threadIdx.x;
  if (i < n) p[i] = 0;
}
__global__ void copy_k(float* d, const float* s, int n) {
  int i = blockIdx.x * 256 + threadIdx.x;
  if (i < n) d[i] = s[i];
}
__global__ void vadd_k(float* o, const float* a, const float* b, int n) {
  int i = blockIdx.x * 256 + threadIdx.x;
  if (i < n) o[i] = a[i] + b[i];
}
__global__ void transp_k(float* o, const float* in) {  // (1024,256)->(256,1024)
  int i = blockIdx.x * 256 + threadIdx.x;
  if (i >= 1024 * 256) return;
  int g = i >> 8, k = i & 255;
  o[k * 1024 + g] = in[i];
}
__global__ void qcopy_k(float* qnode, const float* qh) {
  int b = blockIdx.x, d = threadIdx.x;
  qnode[b * DD + d] = qh[(b * QQ + QQ - 1) * DD + d];
}

__global__ void __launch_bounds__(1024) lstm_k(const float* __restrict__ gx,
                                               const float* __restrict__ whhT,
                                               float* __restrict__ qh) {
  int b = blockIdx.x, g = threadIdx.x;
  __shared__ float hs[DD], cs[DD], zs[L4D];
  if (g < DD) { hs[g] = 0.f; cs[g] = 0.f; }
  __syncthreads();
  for (int t = 0; t < QQ; t++) {
    float acc = gx[(b * QQ + t) * L4D + g];
#pragma unroll 8
    for (int k = 0; k < DD; k++) acc += hs[k] * whhT[k * L4D + g];
    zs[g] = acc;
    __syncthreads();
    if (g < DD) {
      float zi = zs[g], zf = zs[DD + g], zg = zs[2 * DD + g], zo = zs[3 * DD + g];
      float cn = (1.f / (1.f + expf(-zf))) * cs[g] +
                 (1.f / (1.f + expf(-zi))) * tanhf(zg);
      float hn = (1.f / (1.f + expf(-zo))) * tanhf(cn);
      cs[g] = cn;
      hs[g] = hn;
      qh[(b * QQ + t) * DD + g] = hn;
    }
    __syncthreads();
  }
}

__global__ void wr_k(const float* __restrict__ s0, const int* __restrict__ qt,
                     float* __restrict__ Wr) {
  int idx = blockIdx.x * 256 + threadIdx.x;
  if (idx >= BB * NRELROWS) return;
  int b = idx / NRELROWS, r = idx - b * NRELROWS;
  float raw[QQ], lg[QQ];
  float mx = -1e30f;
  for (int q = 0; q < QQ; q++) {
    float v = s0[(b * QQ + q) * NRELROWS + r];
    raw[q] = v;
    lg[q] = v + ((qt[b * QQ + q] == NWORD) ? VERY_NEG : 0.f);
    mx = fmaxf(mx, lg[q]);
  }
  float se = 0.f;
  for (int q = 0; q < QQ; q++) { lg[q] = expf(lg[q] - mx); se += lg[q]; }
  float w = 0.f;
  for (int q = 0; q < QQ; q++) w += (lg[q] / se) * raw[q];
  Wr[idx] = w;
}

__global__ void rowmax_k(const float* Wr, const int* rel, float* maxb) {
  int b = blockIdx.x;
  __shared__ float red[256];
  float mx = -1e30f;
  for (int f = threadIdx.x; f < FF; f += 256)
    mx = fmaxf(mx, Wr[b * NRELROWS + rel[b * FF + f]]);
  red[threadIdx.x] = mx;
  __syncthreads();
  for (int s = 128; s > 0; s >>= 1) {
    if (threadIdx.x < s) red[threadIdx.x] = fmaxf(red[threadIdx.x], red[threadIdx.x + s]);
    __syncthreads();
  }
  if (!threadIdx.x) maxb[b] = red[0];
}

__global__ void wtilde_k(const float* Wr, const int* rel, const int* e2f,
                         const float* maxb, float* Wt, float* e2fs) {
  int i = blockIdx.x * 256 + threadIdx.x;
  if (i >= BB * FF) return;
  int b = i >> 13;
  float wt = expf(Wr[b * NRELROWS + rel[i]] - maxb[b]);
  Wt[i] = wt;
  atomicAdd(&e2fs[b * EE + e2f[i]], wt);
}

__global__ void clamp_k(float* p, int n) {
  int i = blockIdx.x * 256 + threadIdx.x;
  if (i < n) p[i] = fmaxf(p[i], VERY_SMALL);
}

// ---- CSR build (once; f2e_ent is layer-invariant) ----
__global__ void cnti_k(int* cnt, const int* f2e) {
  int i = blockIdx.x * 256 + threadIdx.x;
  if (i >= BB * FF) return;
  atomicAdd(&cnt[(i >> 13) * EE + f2e[i]], 1);
}

__global__ void scan_k(const int* __restrict__ cnt, int* __restrict__ rowptr,
                       float* __restrict__ cntf) {
  int b = blockIdx.x, t = threadIdx.x;
  __shared__ int part[256];
  __shared__ int partx[257];
  int loc[8];
  int s = 0;
  int base = b * EE + t * 8;
  for (int j = 0; j < 8; j++) { loc[j] = cnt[base + j]; s += loc[j]; }
  part[t] = s;
  __syncthreads();
  if (t == 0) {
    int a = 0;
    for (int i = 0; i < 256; i++) { partx[i] = a; a += part[i]; }
    partx[256] = a;
  }
  __syncthreads();
  int off = partx[t];
  for (int j = 0; j < 8; j++) {
    rowptr[b * (EE + 1) + t * 8 + j] = off;
    cntf[base + j] = (float)loc[j];
    off += loc[j];
  }
  if (t == 255) rowptr[b * (EE + 1) + EE] = off;
}

__global__ void fill_k(const int* __restrict__ f2e, const int* __restrict__ rowptr,
                       int* __restrict__ fill, int* __restrict__ fidx) {
  int i = blockIdx.x * 256 + threadIdx.x;
  if (i >= BB * FF) return;
  int b = i >> 13, f = i & (FF - 1);
  int e = f2e[i];
  int pos = rowptr[b * (EE + 1) + e] + atomicAdd(&fill[b * EE + e], 1);
  fidx[b * FF + pos] = f;
}

// ---- per-layer fact gather ----
__global__ void __launch_bounds__(256) gather_k(
    const float* __restrict__ fsl, const float* __restrict__ head,
    const float* __restrict__ Wt, const float* __restrict__ pr,
    const float* __restrict__ e2fs, const int* __restrict__ rel,
    const int* __restrict__ e2f, const int* __restrict__ rowptr,
    const int* __restrict__ fidx, float* __restrict__ Asc,
    float* __restrict__ prnew) {
  int sub = threadIdx.x >> 6;
  int lane = threadIdx.x & 63;
  int be = blockIdx.x * 4 + sub;
  int b = be >> 11, e = be & (EE - 1);
  int beg = rowptr[b * (EE + 1) + e], end = rowptr[b * (EE + 1) + e + 1];
  float4 acc = make_float4(0.f, 0.f, 0.f, 0.f);
  float nsum = 0.f;
  for (int p = beg; p < end; p++) {
    int f = fidx[b * FF + p];
    int bf = (b << 13) + f;
    int esrc = e2f[bf];
    int r = rel[bf];
    float nrm = Wt[bf] * pr[b * EE + esrc] / e2fs[b * EE + esrc];
    nsum += nrm;
    float4 h = ((const float4*)(head + (long)(b * EE + esrc) * DD))[lane];
    float4 fv = ((const float4*)(fsl + (long)r * DD))[lane];
    acc.x += fmaxf(h.x + fv.x, 0.f) * nrm;
    acc.y += fmaxf(h.y + fv.y, 0.f) * nrm;
    acc.z += fmaxf(h.z + fv.z, 0.f) * nrm;
    acc.w += fmaxf(h.w + fv.w, 0.f) * nrm;
  }
  ((float4*)(Asc + (long)be * DD))[lane] = acc;
  if (lane == 0) prnew[be] = nsum;
}

__global__ void prupd_k(float* pr, const float* prnew, int n) {
  int i = blockIdx.x * 256 + threadIdx.x;
  if (i < n) pr[i] = 0.8f * prnew[i] + 0.2f * pr[i];
}

__global__ void prsum_k(const float* pr, float* prsum) {
  int b = blockIdx.x;
  __shared__ float red[256];
  float s = 0.f;
  for (int e = threadIdx.x; e < EE; e += 256) s += pr[b * EE + e];
  red[threadIdx.x] = s;
  __syncthreads();
  for (int st = 128; st > 0; st >>= 1) {
    if (threadIdx.x < st) red[threadIdx.x] += red[threadIdx.x + st];
    __syncthreads();
  }
  if (!threadIdx.x) prsum[b] = red[0];
}

__global__ void wsum_k(const float* __restrict__ pr, const float* __restrict__ le,
                       const float* __restrict__ f2e, float* __restrict__ sle,
                       float* __restrict__ sf2e) {
  int blk = blockIdx.x;
  int b = blk >> 5, ch = blk & 31;
  int d = threadIdx.x;
  float a = 0.f, c = 0.f;
  int e0 = ch * 64;
  for (int e = e0; e < e0 + 64; e++) {
    float w = pr[b * EE + e];
    a += w * le[(long)(b * EE + e) * DD + d];
    c += w * f2e[(long)(b * EE + e) * DD + d];
  }
  atomicAdd(&sle[b * DD + d], a);
  atomicAdd(&sf2e[b * DD + d], c);
}

__global__ void smallmv_k(const float* __restrict__ x, const float* __restrict__ W,
                          int ldw, const float* __restrict__ bias,
                          float* __restrict__ y, int K) {
  int b = blockIdx.x, n = threadIdx.x;
  const float* w = W + (long)n * ldw;
  const float* xb = x + b * K;
  float acc = bias ? bias[n] : 0.f;
  for (int k = 0; k < K; k++) acc += xb[k] * w[k];
  y[b * DD + n] = acc;
}

__global__ void qupd_k(const float* sle, const float* sf2e, const float* q2ev,
                       const float* prsum, const float* __restrict__ W,
                       const float* bias, float* qnode) {
  int b = blockIdx.x, n = threadIdx.x;
  const float* w = W + (long)n * 768;
  float ps = prsum[b];
  float acc = ps * bias[n];
  for (int k = 0; k < DD; k++) acc += sle[b * DD + k] * w[k];
  for (int k = 0; k < DD; k++) acc += ps * q2ev[b * DD + k] * w[DD + k];
  for (int k = 0; k < DD; k++) acc += 3.f * sf2e[b * DD + k] * w[2 * DD + k];
  qnode[b * DD + n] = acc;
}

__global__ void score_k(const float* __restrict__ le, const float* __restrict__ sw,
                        const float* __restrict__ sb, float* __restrict__ out) {
  int row = blockIdx.x * 8 + (threadIdx.x >> 5);
  int lane = threadIdx.x & 31;
  float acc = 0.f;
#pragma unroll
  for (int j = 0; j < 8; j++) {
    int k = lane + j * 32;
    acc += le[(long)row * DD + k] * sw[k];
  }
#pragma unroll
  for (int o = 16; o > 0; o >>= 1) acc += __shfl_down_sync(0xffffffffu, acc, o);
  if (!lane) out[row] = acc + sb[0];
}

// ---------------- host ----------------
extern "C" void kernel_launch(void* const* d_in, const int* in_sizes, int n_in,
                              void* d_out, int out_size) {
  const int* local_entity = (const int*)d_in[0];
  const float* q2e_adj = (const float*)d_in[1];
  const int* kb_fact_rel = (const int*)d_in[2];
  const int* query_text = (const int*)d_in[3];
  const int* e2f_ent = (const int*)d_in[5];
  const int* f2e_ent = (const int*)d_in[6];
  const float* word_emb = (const float*)d_in[7];
  const float* entity_emb = (const float*)d_in[8];
  const float* relation_emb = (const float*)d_in[9];
  const float* ent_w = (const float*)d_in[10];
  const float* ent_b = (const float*)d_in[11];
  const float* rel_w = (const float*)d_in[12];
  const float* rel_b = (const float*)d_in[13];
  const float* w_ih = (const float*)d_in[14];
  const float* w_hh = (const float*)d_in[15];
  const float* b_ih = (const float*)d_in[16];
  const float* b_hh = (const float*)d_in[17];
  const float* q2e_w = (const float*)d_in[18];
  const float* q2e_b = (const float*)d_in[19];
  const float* e2q_w = (const float*)d_in[20];
  const float* e2q_b = (const float*)d_in[21];
  const float* e2e_w = (const float*)d_in[22];
  const float* e2e_b = (const float*)d_in[23];
  const float* kb_head_w = (const float*)d_in[24];
  const float* kb_head_b = (const float*)d_in[25];
  const float* kb_tail_w = (const float*)d_in[26];
  const float* kb_tail_b = (const float*)d_in[27];
  const float* kb_self_w = (const float*)d_in[28];
  const float* kb_self_b = (const float*)d_in[29];
  const float* score_w = (const float*)d_in[30];
  const float* score_b = (const float*)d_in[31];
  float* out = (float*)d_out;
  (void)in_sizes; (void)n_in; (void)out_size;

  cudaFuncSetAttribute(gemm_k<false, false, false, 1>,
                       cudaFuncAttributeMaxDynamicSharedMemorySize, SMB_PIPE);
  cudaFuncSetAttribute(gemm_k<true, false, false, 1>,
                       cudaFuncAttributeMaxDynamicSharedMemorySize, SMB_PIPE);
  cudaFuncSetAttribute(gemm_k<false, false, false, 0>,
                       cudaFuncAttributeMaxDynamicSharedMemorySize, SMB_PIPE);
  cudaFuncSetAttribute(gemm_k<false, true, true, 3>,
                       cudaFuncAttributeMaxDynamicSharedMemorySize, SMB_PIPE);
  cudaFuncSetAttribute(gemm_dualout_k,
                       cudaFuncAttributeMaxDynamicSharedMemorySize, SMB_PIPE);
  cudaFuncSetAttribute(gemm_dualin_k,
                       cudaFuncAttributeMaxDynamicSharedMemorySize, SMB_PIPE);

  float *lr, *fs, *lstmb, *whhT, *gx, *qh, *qnode, *s0, *Wr, *maxb, *Wt, *e2fs;
  float *leA, *leB, *head, *eself, *Asc, *pr, *prnew, *cnt, *q2ev, *biasBE;
  float *sred, *prsum;
  int *cnti, *rowptr, *fill, *fidx;
  cudaGetSymbolAddress((void**)&lr, g_lr);
  cudaGetSymbolAddress((void**)&fs, g_fs);
  cudaGetSymbolAddress((void**)&lstmb, g_lstmb);
  cudaGetSymbolAddress((void**)&whhT, g_whhT);
  cudaGetSymbolAddress((void**)&gx, g_gx);
  cudaGetSymbolAddress((void**)&qh, g_qh);
  cudaGetSymbolAddress((void**)&qnode, g_qnode);
  cudaGetSymbolAddress((void**)&s0, g_s0);
  cudaGetSymbolAddress((void**)&Wr, g_Wr);
  cudaGetSymbolAddress((void**)&maxb, g_maxb);
  cudaGetSymbolAddress((void**)&Wt, g_Wt);
  cudaGetSymbolAddress((void**)&e2fs, g_e2fs);
  cudaGetSymbolAddress((void**)&leA, g_leA);
  cudaGetSymbolAddress((void**)&leB, g_leB);
  cudaGetSymbolAddress((void**)&head, g_head);
  cudaGetSymbolAddress((void**)&eself, g_eself);
  cudaGetSymbolAddress((void**)&Asc, g_Asc);
  cudaGetSymbolAddress((void**)&pr, g_pr);
  cudaGetSymbolAddress((void**)&prnew, g_prnew);
  cudaGetSymbolAddress((void**)&cnt, g_cnt);
  cudaGetSymbolAddress((void**)&q2ev, g_q2ev);
  cudaGetSymbolAddress((void**)&biasBE, g_biasBE);
  cudaGetSymbolAddress((void**)&sred, g_sred);
  cudaGetSymbolAddress((void**)&prsum, g_prsum);
  cudaGetSymbolAddress((void**)&cnti, g_cnti);
  cudaGetSymbolAddress((void**)&rowptr, g_rowptr);
  cudaGetSymbolAddress((void**)&fill, g_fill);
  cudaGetSymbolAddress((void**)&fidx, g_fidx);

  const int ME = BB * EE;            // 32768
  dim3 gBig(2, ME / TBM);
  dim3 gBig512(4, ME / TBM);
  dim3 gRel(2, (NRELROWS + TBM - 1) / TBM);

  // --- prologue; 4th launch (ncu-profiled) = the BIG entity GEMM ---
  vadd_k<<<4, 256>>>(lstmb, b_ih, b_hh, L4D);                       // 1
  transp_k<<<1024, 256>>>(whhT, w_hh);                              // 2
  gemm_k<false, false, false, 1><<<gRel, 256, SMB_PIPE>>>(          // 3
      lr, relation_emb, 600, nullptr, rel_w, 600, rel_b, nullptr,
      NRELROWS, 256, 600, 1.f);
  gemm_k<true, false, false, 1><<<gBig, 256, SMB_PIPE>>>(           // 4 <- profiled
      leA, entity_emb, WDD, local_entity, ent_w, WDD, ent_b, nullptr,
      ME, 256, WDD, 1.f);
  for (int l = 0; l < 3; l++)
    gemm_k<false, false, false, 1><<<gRel, 256, SMB_PIPE>>>(
        fs + l * NRELROWS * DD, lr, 256, nullptr, kb_self_w + l * 65536, 256,
        kb_self_b + l * 256, nullptr, NRELROWS, 256, 256, 1.f);
  gemm_k<true, false, false, 1><<<dim3(8, 3), 256, SMB_PIPE>>>(
      gx, word_emb, WDD, query_text, w_ih, WDD, lstmb, nullptr,
      BB * QQ, L4D, WDD, 1.f);
  lstm_k<<<BB, 1024>>>(gx, whhT, qh);
  qcopy_k<<<BB, 256>>>(qnode, qh);

  // --- CSR build for f2e gather ---
  zeroi_k<<<(ME + 255) / 256, 256>>>(cnti, ME);
  zeroi_k<<<(ME + 255) / 256, 256>>>(fill, ME);
  cnti_k<<<(BB * FF) / 256, 256>>>(cnti, f2e_ent);
  scan_k<<<BB, 256>>>(cnti, rowptr, cnt);
  fill_k<<<(BB * FF) / 256, 256>>>(f2e_ent, rowptr, fill, fidx);

  // --- attention -> Wr -> W_tilde -> e2f_softmax ---
  gemm_k<false, false, false, 0><<<dim3(5, 3), 256, SMB_PIPE>>>(
      s0, qh, 256, nullptr, lr, 256, nullptr, nullptr,
      BB * QQ, NRELROWS, 256, 1.f / 16.f);
  wr_k<<<(BB * NRELROWS + 255) / 256, 256>>>(s0, query_text, Wr);
  rowmax_k<<<BB, 256>>>(Wr, kb_fact_rel, maxb);
  zero_k<<<(ME + 255) / 256, 256>>>(e2fs, ME);
  wtilde_k<<<(BB * FF) / 256, 256>>>(Wr, kb_fact_rel, e2f_ent, maxb, Wt, e2fs);
  clamp_k<<<(ME + 255) / 256, 256>>>(e2fs, ME);

  // --- pagerank init ---
  copy_k<<<(ME + 255) / 256, 256>>>(pr, q2e_adj, ME);

  float* leCur = leA;
  float* leNxt = leB;
  for (int l = 0; l < 3; l++) {
    const float* Wh = kb_head_w + l * 65536;
    const float* Ws = kb_self_w + l * 65536;
    const float* Wtl = kb_tail_w + l * 65536;
    const float* We2e = e2e_w + l * 256 * 768;
    const float* We2q = e2q_w + l * 256 * 768;

    smallmv_k<<<BB, 256>>>(qnode, q2e_w + l * 65536, 256, q2e_b + l * 256, q2ev, 256);
    gemm_dualout_k<<<gBig512, 256, SMB_PIPE>>>(head, eself, leCur, Wh, Ws,
                                               kb_head_b + l * 256,
                                               kb_self_b + l * 256, ME);
    gather_k<<<ME / 4, 256>>>(fs + l * NRELROWS * DD, head, Wt, pr, e2fs,
                              kb_fact_rel, e2f_ent, rowptr, fidx, Asc, prnew);
    // tail GEMM with fused per-entity tail-bias (cnt[m] * kb_tail_b[n])
    gemm_k<false, true, true, 3><<<gBig, 256, SMB_PIPE>>>(
        eself, Asc, 256, nullptr, Wtl, 256, kb_tail_b + l * 256, cnt,
        ME, 256, 256, 1.f);
    prupd_k<<<(ME + 255) / 256, 256>>>(pr, prnew, ME);
    zero_k<<<(2 * BB * DD + 255) / 256, 256>>>(sred, 2 * BB * DD);
    prsum_k<<<BB, 256>>>(pr, prsum);
    wsum_k<<<BB * 32, 256>>>(pr, leCur, eself, sred, sred + BB * DD);
    qupd_k<<<BB, 256>>>(sred, sred + BB * DD, q2ev, prsum, We2q,
                        e2q_b + l * 256, qnode);
    smallmv_k<<<BB, 256>>>(q2ev, We2e + 256, 768, e2e_b + l * 256, biasBE, 256);
    gemm_dualin_k<<<gBig, 256, SMB_PIPE>>>(leNxt, leCur, eself, We2e,
                                           We2e + 512, biasBE, 3.f, ME);
    float* t = leCur; leCur = leNxt; leNxt = t;
  }

  score_k<<<ME / 8, 256>>>(leCur, score_w, score_b, out);
}